// round 2
// baseline (speedup 1.0000x reference)
#include <cuda_runtime.h>

typedef unsigned long long ull;

#define Bb    2
#define NSEQ  8192
#define DIMV  512
#define NH    8
#define BHn   16
#define DHd   64
#define MLM   256
#define LGRP  32
#define KSZ   33
#define PADc  16
#define SCALE 0.125f
#define NCHUNK 32

// ---------------- packed f32x2 helpers ----------------
__device__ __forceinline__ ull pack2(float a, float b) {
    ull r;
    asm("mov.b64 %0, {%1, %2};" : "=l"(r) : "f"(a), "f"(b));
    return r;
}
__device__ __forceinline__ void fma2(ull& d, ull a, ull b) {
    asm("fma.rn.f32x2 %0, %1, %2, %0;" : "+l"(d) : "l"(a), "l"(b));
}
__device__ __forceinline__ void mul2(ull& d, ull a, ull b) {
    asm("mul.rn.f32x2 %0, %1, %2;" : "=l"(d) : "l"(a), "l"(b));
}
__device__ __forceinline__ float2 unpack2(ull v) {
    float2 r;
    asm("mov.b64 {%0, %1}, %2;" : "=f"(r.x), "=f"(r.y) : "l"(v));
    return r;
}

// ---------------- static device scratch ----------------
__device__ float g_xn[(size_t)Bb * NSEQ * DIMV];
__device__ float g_q[(size_t)BHn * NSEQ * DHd];
__device__ float g_k[(size_t)BHn * NSEQ * DHd];
__device__ float g_v[(size_t)BHn * NSEQ * DHd];
__device__ float g_ql[BHn * MLM * DHd];
__device__ float g_kl[BHn * MLM * DHd];
__device__ float g_attn2[BHn * MLM * MLM];
__device__ float g_Y[BHn * MLM * MLM];
__device__ float g_P[BHn * MLM * MLM];
__device__ float g_Qm[BHn * MLM * MLM];
__device__ float g_Za[BHn * MLM * MLM];
__device__ float g_Zb[BHn * MLM * MLM];
__device__ float g_W2[BHn * MLM * DHd];
__device__ float g_W3[BHn * MLM * DHd];
__device__ float g_Wpart[(size_t)BHn * NCHUNK * MLM * DHd];
__device__ float g_Spart[BHn * NCHUNK * MLM];
__device__ float g_outpre[(size_t)Bb * NSEQ * DIMV];
__device__ int   g_maxc_bits;

__global__ void reset_kernel() { g_maxc_bits = 0; }

// ---------------- layernorm ----------------
__global__ __launch_bounds__(128) void ln_kernel(const float* __restrict__ x,
                                                 const float* __restrict__ gam,
                                                 const float* __restrict__ bet) {
    int row = blockIdx.x;
    int tid = threadIdx.x;
    float4 v = ((const float4*)x)[(size_t)row * 128 + tid];
    float s1 = v.x + v.y + v.z + v.w;
    float s2 = v.x * v.x + v.y * v.y + v.z * v.z + v.w * v.w;
#pragma unroll
    for (int o = 16; o; o >>= 1) {
        s1 += __shfl_xor_sync(0xffffffffu, s1, o);
        s2 += __shfl_xor_sync(0xffffffffu, s2, o);
    }
    __shared__ float r1[4], r2[4];
    int w = tid >> 5;
    if ((tid & 31) == 0) { r1[w] = s1; r2[w] = s2; }
    __syncthreads();
    s1 = r1[0] + r1[1] + r1[2] + r1[3];
    s2 = r2[0] + r2[1] + r2[2] + r2[3];
    float mean = s1 * (1.f / 512.f);
    float var  = s2 * (1.f / 512.f) - mean * mean;
    float rstd = rsqrtf(var + 1e-5f);
    float4 g4 = ((const float4*)gam)[tid];
    float4 b4 = ((const float4*)bet)[tid];
    float4 o;
    o.x = (v.x - mean) * rstd * g4.x + b4.x;
    o.y = (v.y - mean) * rstd * g4.y + b4.y;
    o.z = (v.z - mean) * rstd * g4.z + b4.z;
    o.w = (v.w - mean) * rstd * g4.w + b4.w;
    ((float4*)g_xn)[(size_t)row * 128 + tid] = o;
}

// ---------------- qkv GEMM (f32x2): xn[16384,512] @ Wqkv[512,1536] ----------------
__global__ __launch_bounds__(256) void sgemm_qkv_kernel(const float* __restrict__ Bm) {
    __shared__ float As[8][128];
    __shared__ float Bs[8][128];
    int tid = threadIdx.x;
    int ty = tid >> 4, tx = tid & 15;
    int rowBase = blockIdx.y * 128;
    int colBase = blockIdx.x * 128;
    int arow = tid >> 1, acol = (tid & 1) * 4;
    int brow = tid >> 5, bcol = (tid & 31) * 4;
    ull acc2[8][4];
#pragma unroll
    for (int i = 0; i < 8; i++)
#pragma unroll
        for (int j = 0; j < 4; j++) acc2[i][j] = 0ull;

    for (int k0 = 0; k0 < 512; k0 += 8) {
        float4 av = *(const float4*)&g_xn[(size_t)(rowBase + arow) * 512 + k0 + acol];
        As[acol + 0][arow] = av.x; As[acol + 1][arow] = av.y;
        As[acol + 2][arow] = av.z; As[acol + 3][arow] = av.w;
        float4 bv = *(const float4*)&Bm[(size_t)(k0 + brow) * 1536 + colBase + bcol];
        *(float4*)&Bs[brow][bcol] = bv;
        __syncthreads();
#pragma unroll
        for (int kk = 0; kk < 8; kk++) {
            float a[8];
            *(float4*)a       = *(const float4*)&As[kk][ty * 8];
            *(float4*)(a + 4) = *(const float4*)&As[kk][ty * 8 + 4];
            const ulonglong2* bp = (const ulonglong2*)&Bs[kk][tx * 8];
            ulonglong2 b01 = bp[0], b23 = bp[1];
#pragma unroll
            for (int i = 0; i < 8; i++) {
                ull ad = pack2(a[i], a[i]);
                fma2(acc2[i][0], ad, b01.x);
                fma2(acc2[i][1], ad, b01.y);
                fma2(acc2[i][2], ad, b23.x);
                fma2(acc2[i][3], ad, b23.y);
            }
        }
        __syncthreads();
    }
#pragma unroll
    for (int i = 0; i < 8; i++) {
        int gr = rowBase + ty * 8 + i;
        int bb = gr >> 13;
        int n  = gr & 8191;
#pragma unroll
        for (int jp = 0; jp < 2; jp++) {
            float2 u0 = unpack2(acc2[i][jp * 2]);
            float2 u1 = unpack2(acc2[i][jp * 2 + 1]);
            int gc = colBase + tx * 8 + jp * 4;
            int sec = gc >> 9;
            int h = (gc >> 6) & 7;
            int d = gc & 63;
            float4 o = make_float4(u0.x, u0.y, u1.x, u1.y);
            float* dst;
            if (sec == 0) {
                o.x *= SCALE; o.y *= SCALE; o.z *= SCALE; o.w *= SCALE;
                dst = g_q;
            } else if (sec == 1) dst = g_k;
            else dst = g_v;
            *(float4*)&dst[((size_t)(bb * 8 + h) * NSEQ + n) * DHd + d] = o;
        }
    }
}

// ---------------- landmarks ----------------
__global__ void landmark_kernel() {
    int idx = blockIdx.x * 256 + threadIdx.x;
    int sel = idx >> 18;
    int r = idx & 262143;
    int bh = r >> 14;
    int m = (r >> 6) & 255;
    int d = r & 63;
    const float* src = sel ? g_k : g_q;
    const float* p = src + ((size_t)bh * NSEQ + m * LGRP) * DHd + d;
    float s = 0.f;
#pragma unroll
    for (int i = 0; i < LGRP; i++) s += p[i * DHd];
    (sel ? g_kl : g_ql)[(bh * MLM + m) * DHd + d] = s * (1.f / LGRP);
}

// ---------------- attn2 = softmax(q_l k_l^T) ----------------
__global__ __launch_bounds__(256) void attn2_kernel() {
    int bh = blockIdx.x;
    int m = threadIdx.x;
    __shared__ float4 kls[1024];
    ull q2[32];
    {
        const ulonglong2* qp = (const ulonglong2*)(g_ql + (size_t)(bh * MLM + m) * 64);
#pragma unroll
        for (int i = 0; i < 16; i++) { ulonglong2 t = qp[i]; q2[2 * i] = t.x; q2[2 * i + 1] = t.y; }
    }
    float sum = 0.f;
    float* arow = g_attn2 + (size_t)bh * 65536 + (size_t)m * 256;
    for (int tile = 0; tile < 4; tile++) {
        __syncthreads();
        const float4* src = (const float4*)g_kl + (size_t)(bh * MLM + tile * 64) * 16;
#pragma unroll
        for (int i = 0; i < 4; i++) kls[threadIdx.x + i * 256] = src[threadIdx.x + i * 256];
        __syncthreads();
        for (int j = 0; j < 64; j++) {
            const ulonglong2* kr = (const ulonglong2*)&kls[j * 16];
            ull s0 = 0, s1 = 0, s2 = 0, s3 = 0;
#pragma unroll
            for (int d = 0; d < 16; d += 2) {
                ulonglong2 ka = kr[d], kb = kr[d + 1];
                fma2(s0, q2[2 * d + 0], ka.x);
                fma2(s1, q2[2 * d + 1], ka.y);
                fma2(s2, q2[2 * d + 2], kb.x);
                fma2(s3, q2[2 * d + 3], kb.y);
            }
            float2 a0 = unpack2(s0), a1 = unpack2(s1), a2 = unpack2(s2), a3 = unpack2(s3);
            float s = (a0.x + a0.y) + (a1.x + a1.y) + (a2.x + a2.y) + (a3.x + a3.y);
            float p = __expf(s);
            sum += p;
            arow[tile * 64 + j] = p;
        }
    }
    float inv = 1.f / sum;
    for (int j = 0; j < 256; j++) arow[j] *= inv;
}

// ---------------- max column-sum of attn2 ----------------
__global__ __launch_bounds__(256) void colmax_kernel() {
    int bh = blockIdx.x;
    int j = threadIdx.x;
    const float* a = g_attn2 + (size_t)bh * 65536;
    float s = 0.f;
    for (int m2 = 0; m2 < 256; m2++) s += a[m2 * 256 + j];
    __shared__ float red[256];
    red[j] = s;
    __syncthreads();
    for (int o = 128; o; o >>= 1) {
        if (j < o) red[j] = fmaxf(red[j], red[j + o]);
        __syncthreads();
    }
    if (j == 0) atomicMax(&g_maxc_bits, __float_as_int(red[0]));
}

__global__ void z0_kernel() {
    int idx = blockIdx.x * 256 + threadIdx.x;
    int bh = idx >> 16;
    int i = (idx >> 8) & 255;
    int j = idx & 255;
    float scale = 1.f / __int_as_float(g_maxc_bits);
    g_Za[idx] = g_attn2[(bh << 16) + (j << 8) + i] * scale;
}

// ---------------- buffer selector ----------------
__device__ __forceinline__ float* pickBuf(int id) {
    switch (id) {
        case 0: return g_attn2;
        case 1: return g_Y;
        case 2: return g_P;
        case 3: return g_Qm;
        case 4: return g_Za;
        case 5: return g_Zb;
        case 6: return g_W2;
        default: return g_W3;
    }
}

// ---------------- pinv batched GEMM (f32x2, 64x128 tiles): C = alpha*A@(beta*I+sgn*B) ----
__global__ __launch_bounds__(256) void gemm_pinv_kernel(int cId, int aId, int bId,
                                                        float beta, float sgn, float alpha) {
    int bh = blockIdx.z, mt = blockIdx.y, nt = blockIdx.x;
    const float* A  = pickBuf(aId) + (size_t)bh * 65536;
    const float* Bp = pickBuf(bId) + (size_t)bh * 65536;
    float*       C  = pickBuf(cId) + (size_t)bh * 65536;
    __shared__ float As[16][64];
    __shared__ float Bs[16][128];
    int tid = threadIdx.x;
    int ar = tid >> 2, ac = (tid & 3) * 4;
    int br = tid >> 5, bc = (tid & 31) * 4;
    int ty = tid >> 4, tx = tid & 15;
    ull acc2[4][4];
#pragma unroll
    for (int i = 0; i < 4; i++)
#pragma unroll
        for (int j = 0; j < 4; j++) acc2[i][j] = 0ull;

    int gc = nt * 128 + bc;
    for (int k0 = 0; k0 < 256; k0 += 16) {
        float4 av = *(const float4*)&A[(size_t)(mt * 64 + ar) * 256 + k0 + ac];
        As[ac + 0][ar] = av.x; As[ac + 1][ar] = av.y;
        As[ac + 2][ar] = av.z; As[ac + 3][ar] = av.w;
#pragma unroll
        for (int half = 0; half < 2; half++) {
            int gk = k0 + br + half * 8;
            float4 bv = *(const float4*)&Bp[(size_t)gk * 256 + gc];
            bv.x = sgn * bv.x + (gk == gc + 0 ? beta : 0.f);
            bv.y = sgn * bv.y + (gk == gc + 1 ? beta : 0.f);
            bv.z = sgn * bv.z + (gk == gc + 2 ? beta : 0.f);
            bv.w = sgn * bv.w + (gk == gc + 3 ? beta : 0.f);
            *(float4*)&Bs[br + half * 8][bc] = bv;
        }
        __syncthreads();
#pragma unroll
        for (int kk = 0; kk < 16; kk++) {
            float4 a4 = *(const float4*)&As[kk][ty * 4];
            const ulonglong2* bp2 = (const ulonglong2*)&Bs[kk][tx * 8];
            ulonglong2 b01 = bp2[0], b23 = bp2[1];
            ull a0 = pack2(a4.x, a4.x), a1 = pack2(a4.y, a4.y);
            ull a2 = pack2(a4.z, a4.z), a3 = pack2(a4.w, a4.w);
            fma2(acc2[0][0], a0, b01.x); fma2(acc2[0][1], a0, b01.y);
            fma2(acc2[0][2], a0, b23.x); fma2(acc2[0][3], a0, b23.y);
            fma2(acc2[1][0], a1, b01.x); fma2(acc2[1][1], a1, b01.y);
            fma2(acc2[1][2], a1, b23.x); fma2(acc2[1][3], a1, b23.y);
            fma2(acc2[2][0], a2, b01.x); fma2(acc2[2][1], a2, b01.y);
            fma2(acc2[2][2], a2, b23.x); fma2(acc2[2][3], a2, b23.y);
            fma2(acc2[3][0], a3, b01.x); fma2(acc2[3][1], a3, b01.y);
            fma2(acc2[3][2], a3, b23.x); fma2(acc2[3][3], a3, b23.y);
        }
        __syncthreads();
    }
#pragma unroll
    for (int i = 0; i < 4; i++) {
        float* crow = &C[(size_t)(mt * 64 + ty * 4 + i) * 256 + nt * 128 + tx * 8];
#pragma unroll
        for (int jp = 0; jp < 2; jp++) {
            float2 u0 = unpack2(acc2[i][jp * 2]);
            float2 u1 = unpack2(acc2[i][jp * 2 + 1]);
            *(float4*)(crow + jp * 4) = make_float4(u0.x * alpha, u0.y * alpha,
                                                    u1.x * alpha, u1.y * alpha);
        }
    }
}

// ---------------- small GEMM for W3 = Z[256,256] @ W2[256,64] ----------------
__global__ __launch_bounds__(256) void gemm_w3_kernel(int aId) {
    int bh = blockIdx.z, mt = blockIdx.y;
    const float* A  = pickBuf(aId) + (size_t)bh * 65536;
    const float* Bp = g_W2 + (size_t)bh * 256 * 64;
    float*       C  = g_W3 + (size_t)bh * 256 * 64;
    __shared__ float As[16][64];
    __shared__ float Bs[16][64];
    int tid = threadIdx.x;
    int ar = tid >> 2, ac = (tid & 3) * 4;
    int br = tid >> 4, bc = (tid & 15) * 4;
    int ty = tid >> 4, tx = tid & 15;
    ull acc2[4][2];
#pragma unroll
    for (int i = 0; i < 4; i++) { acc2[i][0] = 0ull; acc2[i][1] = 0ull; }

    for (int k0 = 0; k0 < 256; k0 += 16) {
        float4 av = *(const float4*)&A[(size_t)(mt * 64 + ar) * 256 + k0 + ac];
        As[ac + 0][ar] = av.x; As[ac + 1][ar] = av.y;
        As[ac + 2][ar] = av.z; As[ac + 3][ar] = av.w;
        float4 bv = *(const float4*)&Bp[(size_t)(k0 + br) * 64 + bc];
        *(float4*)&Bs[br][bc] = bv;
        __syncthreads();
#pragma unroll
        for (int kk = 0; kk < 16; kk++) {
            float4 a4 = *(const float4*)&As[kk][ty * 4];
            ulonglong2 b2 = *(const ulonglong2*)&Bs[kk][tx * 4];
            ull a0 = pack2(a4.x, a4.x), a1 = pack2(a4.y, a4.y);
            ull a2 = pack2(a4.z, a4.z), a3 = pack2(a4.w, a4.w);
            fma2(acc2[0][0], a0, b2.x); fma2(acc2[0][1], a0, b2.y);
            fma2(acc2[1][0], a1, b2.x); fma2(acc2[1][1], a1, b2.y);
            fma2(acc2[2][0], a2, b2.x); fma2(acc2[2][1], a2, b2.y);
            fma2(acc2[3][0], a3, b2.x); fma2(acc2[3][1], a3, b2.y);
        }
        __syncthreads();
    }
#pragma unroll
    for (int i = 0; i < 4; i++) {
        float2 u0 = unpack2(acc2[i][0]);
        float2 u1 = unpack2(acc2[i][1]);
        *(float4*)&C[(size_t)(mt * 64 + ty * 4 + i) * 64 + tx * 4] =
            make_float4(u0.x, u0.y, u1.x, u1.y);
    }
}

// ---------------- W2 = softmax(q_l k^T) @ v  (split-K, f32x2) ----------------
__global__ __launch_bounds__(256) void flash_w2_kernel() {
    int chunk = blockIdx.x, bh = blockIdx.y;
    int tid = threadIdx.x;
    __shared__ float4 ks[512], vs[512];
    ull q2[32];
    {
        const ulonglong2* qp = (const ulonglong2*)(g_ql + (size_t)(bh * MLM + tid) * 64);
#pragma unroll
        for (int i = 0; i < 16; i++) { ulonglong2 t = qp[i]; q2[2 * i] = t.x; q2[2 * i + 1] = t.y; }
    }
    ull acc2[32];
#pragma unroll
    for (int i = 0; i < 32; i++) acc2[i] = 0ull;
    float sum = 0.f;

    for (int t = 0; t < 8; t++) {
        int k0 = chunk * 256 + t * 32;
        __syncthreads();
        const float4* kp = (const float4*)g_k + ((size_t)bh * NSEQ + k0) * 16;
        const float4* vp = (const float4*)g_v + ((size_t)bh * NSEQ + k0) * 16;
        ks[tid] = kp[tid]; ks[tid + 256] = kp[tid + 256];
        vs[tid] = vp[tid]; vs[tid + 256] = vp[tid + 256];
        __syncthreads();
        for (int j = 0; j < 32; j++) {
            const ulonglong2* kr = (const ulonglong2*)&ks[j * 16];
            ull s0 = 0, s1 = 0, s2 = 0, s3 = 0;
#pragma unroll
            for (int d = 0; d < 16; d += 2) {
                ulonglong2 ka = kr[d], kb = kr[d + 1];
                fma2(s0, q2[2 * d + 0], ka.x);
                fma2(s1, q2[2 * d + 1], ka.y);
                fma2(s2, q2[2 * d + 2], kb.x);
                fma2(s3, q2[2 * d + 3], kb.y);
            }
            float2 a0 = unpack2(s0), a1 = unpack2(s1), a2 = unpack2(s2), a3 = unpack2(s3);
            float s = (a0.x + a0.y) + (a1.x + a1.y) + (a2.x + a2.y) + (a3.x + a3.y);
            float p = __expf(s);
            sum += p;
            ull pd = pack2(p, p);
            const ulonglong2* vr = (const ulonglong2*)&vs[j * 16];
#pragma unroll
            for (int d = 0; d < 16; d++) {
                ulonglong2 u = vr[d];
                fma2(acc2[2 * d], pd, u.x);
                fma2(acc2[2 * d + 1], pd, u.y);
            }
        }
    }
    ull* wp = (ull*)(g_Wpart + (size_t)((bh * NCHUNK + chunk) * MLM + tid) * DHd);
#pragma unroll
    for (int d = 0; d < 32; d++) wp[d] = acc2[d];
    g_Spart[(bh * NCHUNK + chunk) * MLM + tid] = sum;
}

__global__ void combine_w2_kernel() {
    int idx = blockIdx.x * 256 + threadIdx.x;
    int bh = idx >> 14;
    int m = (idx >> 6) & 255;
    int d = idx & 63;
    float num = 0.f, den = 0.f;
    for (int c = 0; c < NCHUNK; c++) {
        num += g_Wpart[(size_t)((bh * NCHUNK + c) * MLM + m) * DHd + d];
        den += g_Spart[(bh * NCHUNK + c) * MLM + m];
    }
    g_W2[(bh * MLM + m) * DHd + d] = num / den;
}

// ---------------- fused: softmax(q k_l^T) @ W3 + conv residual (f32x2) ----------------
__global__ __launch_bounds__(256) void attn1_conv_kernel(const float* __restrict__ convw) {
    int rt = blockIdx.x, bh = blockIdx.y;
    int tid = threadIdx.x;
    int n = rt * 256 + tid;
    int h = bh & 7;
    __shared__ float4 kls[1024];
    __shared__ float4 w3s[1024];
    __shared__ float cw[KSZ];
    if (tid < KSZ) cw[tid] = convw[h * KSZ + tid];

    ull q2[32];
    {
        const ulonglong2* qp = (const ulonglong2*)(g_q + ((size_t)bh * NSEQ + n) * 64);
#pragma unroll
        for (int i = 0; i < 16; i++) { ulonglong2 t = qp[i]; q2[2 * i] = t.x; q2[2 * i + 1] = t.y; }
    }
    ull acc2[32];
#pragma unroll
    for (int i = 0; i < 32; i++) acc2[i] = 0ull;
    float sum = 0.f;

    for (int tile = 0; tile < 4; tile++) {
        __syncthreads();
        const float4* kp = (const float4*)g_kl + (size_t)(bh * MLM + tile * 64) * 16;
        const float4* wp = (const float4*)g_W3 + (size_t)(bh * MLM + tile * 64) * 16;
#pragma unroll
        for (int i = 0; i < 4; i++) {
            kls[tid + i * 256] = kp[tid + i * 256];
            w3s[tid + i * 256] = wp[tid + i * 256];
        }
        __syncthreads();
        for (int j = 0; j < 64; j++) {
            const ulonglong2* kr = (const ulonglong2*)&kls[j * 16];
            ull s0 = 0, s1 = 0, s2 = 0, s3 = 0;
#pragma unroll
            for (int d = 0; d < 16; d += 2) {
                ulonglong2 ka = kr[d], kb = kr[d + 1];
                fma2(s0, q2[2 * d + 0], ka.x);
                fma2(s1, q2[2 * d + 1], ka.y);
                fma2(s2, q2[2 * d + 2], kb.x);
                fma2(s3, q2[2 * d + 3], kb.y);
            }
            float2 a0 = unpack2(s0), a1 = unpack2(s1), a2 = unpack2(s2), a3 = unpack2(s3);
            float s = (a0.x + a0.y) + (a1.x + a1.y) + (a2.x + a2.y) + (a3.x + a3.y);
            float p = __expf(s);
            sum += p;
            ull pd = pack2(p, p);
            const ulonglong2* wr = (const ulonglong2*)&w3s[j * 16];
#pragma unroll
            for (int d = 0; d < 16; d++) {
                ulonglong2 u = wr[d];
                fma2(acc2[2 * d], pd, u.x);
                fma2(acc2[2 * d + 1], pd, u.y);
            }
        }
    }
    float inv = 1.f / sum;
    ull invd = pack2(inv, inv);
#pragma unroll
    for (int d = 0; d < 32; d++) {
        ull t;
        mul2(t, acc2[d], invd);
        acc2[d] = t;
    }
    // depthwise conv-33 residual
    const float* vb = g_v + (size_t)bh * NSEQ * 64;
#pragma unroll
    for (int t = 0; t < KSZ; t++) {
        int r = n + t - PADc;
        if ((unsigned)r < (unsigned)NSEQ) {
            ull wd = pack2(cw[t], cw[t]);
            const ulonglong2* vr = (const ulonglong2*)(vb + (size_t)r * 64);
#pragma unroll
            for (int d = 0; d < 16; d++) {
                ulonglong2 u = vr[d];
                fma2(acc2[2 * d], wd, u.x);
                fma2(acc2[2 * d + 1], wd, u.y);
            }
        }
    }
    int bb = bh >> 3;
    ull* op = (ull*)(g_outpre + (size_t)(bb * NSEQ + n) * DIMV + h * DHd);
#pragma unroll
    for (int d = 0; d < 32; d++) op[d] = acc2[d];
}

// ---------------- final GEMM (f32x2): out = xn + out_pre @ W_out + b_out ----------------
__global__ __launch_bounds__(256) void sgemm_out_kernel(const float* __restrict__ Bm,
                                                        const float* __restrict__ bout,
                                                        float* __restrict__ out) {
    __shared__ float As[8][128];
    __shared__ float Bs[8][128];
    int tid = threadIdx.x;
    int ty = tid >> 4, tx = tid & 15;
    int rowBase = blockIdx.y * 128;
    int colBase = blockIdx.x * 128;
    int arow = tid >> 1, acol = (tid & 1) * 4;
    int brow = tid >> 5, bcol = (tid & 31) * 4;
    ull acc2[8][4];
#pragma unroll
    for (int i = 0; i < 8; i++)
#pragma unroll
        for (int j = 0; j < 4; j++) acc2[i][j] = 0ull;

    for (int k0 = 0; k0 < 512; k0 += 8) {
        float4 av = *(const float4*)&g_outpre[(size_t)(rowBase + arow) * 512 + k0 + acol];
        As[acol + 0][arow] = av.x; As[acol + 1][arow] = av.y;
        As[acol + 2][arow] = av.z; As[acol + 3][arow] = av.w;
        float4 bv = *(const float4*)&Bm[(size_t)(k0 + brow) * 512 + colBase + bcol];
        *(float4*)&Bs[brow][bcol] = bv;
        __syncthreads();
#pragma unroll
        for (int kk = 0; kk < 8; kk++) {
            float a[8];
            *(float4*)a       = *(const float4*)&As[kk][ty * 8];
            *(float4*)(a + 4) = *(const float4*)&As[kk][ty * 8 + 4];
            const ulonglong2* bp = (const ulonglong2*)&Bs[kk][tx * 8];
            ulonglong2 b01 = bp[0], b23 = bp[1];
#pragma unroll
            for (int i = 0; i < 8; i++) {
                ull ad = pack2(a[i], a[i]);
                fma2(acc2[i][0], ad, b01.x);
                fma2(acc2[i][1], ad, b01.y);
                fma2(acc2[i][2], ad, b23.x);
                fma2(acc2[i][3], ad, b23.y);
            }
        }
        __syncthreads();
    }
#pragma unroll
    for (int i = 0; i < 8; i++) {
        int gr = rowBase + ty * 8 + i;
#pragma unroll
        for (int jp = 0; jp < 2; jp++) {
            float2 u0 = unpack2(acc2[i][jp * 2]);
            float2 u1 = unpack2(acc2[i][jp * 2 + 1]);
            int gc = colBase + tx * 8 + jp * 4;
            float4 bo = *(const float4*)&bout[gc];
            float4 xv = *(const float4*)&g_xn[(size_t)gr * 512 + gc];
            float4 o = make_float4(u0.x + bo.x + xv.x, u0.y + bo.y + xv.y,
                                   u1.x + bo.z + xv.z, u1.y + bo.w + xv.w);
            *(float4*)&out[(size_t)gr * 512 + gc] = o;
        }
    }
}

// ---------------- host launcher ----------------
extern "C" void kernel_launch(void* const* d_in, const int* in_sizes, int n_in,
                              void* d_out, int out_size) {
    const float* x     = (const float*)d_in[0];
    const float* ln_g  = (const float*)d_in[1];
    const float* ln_b  = (const float*)d_in[2];
    const float* W_qkv = (const float*)d_in[3];
    const float* W_out = (const float*)d_in[4];
    const float* b_out = (const float*)d_in[5];
    const float* convw = (const float*)d_in[6];
    float* out = (float*)d_out;

    reset_kernel<<<1, 1>>>();
    ln_kernel<<<Bb * NSEQ, 128>>>(x, ln_g, ln_b);
    sgemm_qkv_kernel<<<dim3(12, 128), 256>>>(W_qkv);
    landmark_kernel<<<2048, 256>>>();
    attn2_kernel<<<16, 256>>>();
    colmax_kernel<<<16, 256>>>();
    z0_kernel<<<4096, 256>>>();

    int zc = 4, zn = 5;  // Za, Zb
    for (int it = 0; it < 6; it++) {
        gemm_pinv_kernel<<<dim3(2, 4, 16), 256>>>(1, 0, zc, 0.f, 1.f, 1.f);      // Y  = A2 @ Z
        gemm_pinv_kernel<<<dim3(2, 4, 16), 256>>>(2, 1, 1, 7.f, -1.f, 1.f);      // P  = Y @ (7I - Y)
        gemm_pinv_kernel<<<dim3(2, 4, 16), 256>>>(3, 1, 2, 15.f, -1.f, 1.f);     // Qm = Y @ (15I - P)
        gemm_pinv_kernel<<<dim3(2, 4, 16), 256>>>(zn, zc, 3, 13.f, -1.f, 0.25f); // Z' = 0.25 Z @ (13I - Qm)
        int t = zc; zc = zn; zn = t;
    }

    flash_w2_kernel<<<dim3(NCHUNK, 16), 256>>>();
    combine_w2_kernel<<<1024, 256>>>();
    gemm_w3_kernel<<<dim3(1, 4, 16), 256>>>(zc);  // W3 = Z @ W2
    attn1_conv_kernel<<<dim3(32, 16), 256>>>(convw);
    sgemm_out_kernel<<<dim3(4, 128), 256>>>(W_out, b_out, out);
}

// round 4
// speedup vs baseline: 1.2766x; 1.2766x over previous
#include <cuda_runtime.h>
#include <cuda_bf16.h>

#define Bb    2
#define NSEQ  8192
#define DIMV  512
#define NH    8
#define BHn   16
#define DHd   64
#define MLM   256
#define LGRP  32
#define KSZ   33
#define PADc  16
#define SCALE 0.125f
#define NCHUNK 32

// ================= static device scratch =================
__device__ float g_xn[(size_t)Bb * NSEQ * DIMV];
__device__ float g_q[(size_t)BHn * NSEQ * DHd];
__device__ float g_k[(size_t)BHn * NSEQ * DHd];
__device__ float g_v[(size_t)BHn * NSEQ * DHd];
__device__ float g_ql[BHn * MLM * DHd];
__device__ float g_kl[BHn * MLM * DHd];
__device__ float g_attn2[BHn * MLM * MLM];
__device__ float g_Y[BHn * MLM * MLM];
__device__ float g_P[BHn * MLM * MLM];
__device__ float g_Qm[BHn * MLM * MLM];
__device__ float g_Za[BHn * MLM * MLM];
__device__ float g_Zb[BHn * MLM * MLM];
__device__ float g_W2[BHn * MLM * DHd];
__device__ float g_W3[BHn * MLM * DHd];
__device__ float g_Wpart[(size_t)BHn * NCHUNK * MLM * DHd];
__device__ float g_Spart[BHn * NCHUNK * MLM];
__device__ float g_outpre[(size_t)Bb * NSEQ * DIMV];
__device__ int   g_maxc_bits;

// bf16 hi/lo buffers for tensor-core GEMMs
__device__ __nv_bfloat16 g_Ahi[(size_t)Bb * NSEQ * DIMV];
__device__ __nv_bfloat16 g_Alo[(size_t)Bb * NSEQ * DIMV];
__device__ __nv_bfloat16 g_Bqh[1536 * 512];
__device__ __nv_bfloat16 g_Bql[1536 * 512];
__device__ __nv_bfloat16 g_Boh[512 * 512];
__device__ __nv_bfloat16 g_Bol[512 * 512];

__global__ void reset_kernel() { g_maxc_bits = 0; }

// ================= mma.sync helpers =================
__device__ __forceinline__ unsigned smem_u32(const void* p) {
    unsigned a;
    asm("{ .reg .u64 t; cvta.to.shared.u64 t, %1; cvt.u32.u64 %0, t; }" : "=r"(a) : "l"(p));
    return a;
}
__device__ __forceinline__ void ldm4(unsigned* r, unsigned addr) {
    asm volatile("ldmatrix.sync.aligned.m8n8.x4.shared.b16 {%0,%1,%2,%3}, [%4];"
        : "=r"(r[0]), "=r"(r[1]), "=r"(r[2]), "=r"(r[3]) : "r"(addr));
}
__device__ __forceinline__ void mma16816(float* c, const unsigned* a, unsigned b0, unsigned b1) {
    asm volatile("mma.sync.aligned.m16n8k16.row.col.f32.bf16.bf16.f32 "
        "{%0,%1,%2,%3}, {%4,%5,%6,%7}, {%8,%9}, {%0,%1,%2,%3};"
        : "+f"(c[0]), "+f"(c[1]), "+f"(c[2]), "+f"(c[3])
        : "r"(a[0]), "r"(a[1]), "r"(a[2]), "r"(a[3]), "r"(b0), "r"(b1));
}

// ================= layernorm =================
__global__ __launch_bounds__(128) void ln_kernel(const float* __restrict__ x,
                                                 const float* __restrict__ gam,
                                                 const float* __restrict__ bet) {
    int row = blockIdx.x;
    int tid = threadIdx.x;
    float4 v = ((const float4*)x)[(size_t)row * 128 + tid];
    float s1 = v.x + v.y + v.z + v.w;
    float s2 = v.x * v.x + v.y * v.y + v.z * v.z + v.w * v.w;
#pragma unroll
    for (int o = 16; o; o >>= 1) {
        s1 += __shfl_xor_sync(0xffffffffu, s1, o);
        s2 += __shfl_xor_sync(0xffffffffu, s2, o);
    }
    __shared__ float r1[4], r2[4];
    int w = tid >> 5;
    if ((tid & 31) == 0) { r1[w] = s1; r2[w] = s2; }
    __syncthreads();
    s1 = r1[0] + r1[1] + r1[2] + r1[3];
    s2 = r2[0] + r2[1] + r2[2] + r2[3];
    float mean = s1 * (1.f / 512.f);
    float var  = s2 * (1.f / 512.f) - mean * mean;
    float rstd = rsqrtf(var + 1e-5f);
    float4 g4 = ((const float4*)gam)[tid];
    float4 b4 = ((const float4*)bet)[tid];
    float4 o;
    o.x = (v.x - mean) * rstd * g4.x + b4.x;
    o.y = (v.y - mean) * rstd * g4.y + b4.y;
    o.z = (v.z - mean) * rstd * g4.z + b4.z;
    o.w = (v.w - mean) * rstd * g4.w + b4.w;
    ((float4*)g_xn)[(size_t)row * 128 + tid] = o;
}

// ================= fp32 -> bf16 hi/lo converters =================
__global__ __launch_bounds__(256) void convA_kernel(const float* __restrict__ src) {
    size_t i4 = ((size_t)blockIdx.x * 256 + threadIdx.x) * 4;
    float4 v = *(const float4*)(src + i4);
    __nv_bfloat16 h0 = __float2bfloat16(v.x), h1 = __float2bfloat16(v.y);
    __nv_bfloat16 h2 = __float2bfloat16(v.z), h3 = __float2bfloat16(v.w);
    __nv_bfloat16 l0 = __float2bfloat16(v.x - __bfloat162float(h0));
    __nv_bfloat16 l1 = __float2bfloat16(v.y - __bfloat162float(h1));
    __nv_bfloat16 l2 = __float2bfloat16(v.z - __bfloat162float(h2));
    __nv_bfloat16 l3 = __float2bfloat16(v.w - __bfloat162float(h3));
    __nv_bfloat162* ph = (__nv_bfloat162*)(g_Ahi + i4);
    __nv_bfloat162* pl = (__nv_bfloat162*)(g_Alo + i4);
    ph[0] = __nv_bfloat162(h0, h1); ph[1] = __nv_bfloat162(h2, h3);
    pl[0] = __nv_bfloat162(l0, l1); pl[1] = __nv_bfloat162(l2, l3);
}

// transpose W[512, N] -> BT[N, 512] in bf16 hi/lo
__global__ __launch_bounds__(1024) void convW_kernel(const float* __restrict__ W, int N,
                                                     __nv_bfloat16* __restrict__ BThi,
                                                     __nv_bfloat16* __restrict__ BTlo) {
    __shared__ float sh[32][33];
    int n0 = blockIdx.x * 32, k0 = blockIdx.y * 32;
    int tx = threadIdx.x & 31, ty = threadIdx.x >> 5;
    sh[ty][tx] = W[(size_t)(k0 + ty) * N + n0 + tx];
    __syncthreads();
    float x = sh[tx][ty];
    __nv_bfloat16 h = __float2bfloat16(x);
    __nv_bfloat16 l = __float2bfloat16(x - __bfloat162float(h));
    BThi[(size_t)(n0 + ty) * 512 + k0 + tx] = h;
    BTlo[(size_t)(n0 + ty) * 512 + k0 + tx] = l;
}

// ================= mma.sync bf16 split GEMM =================
// C[M,N] = A[M,512] @ BT[N,512]^T where A = g_Ahi/g_Alo (hi+lo).
// grid (N/128, M/128), 256 threads (8 warps: 4 m x 2 n), warp tile 32x64.
// mode 0: scatter into q/k/v (q scaled by SCALE). mode 1: out = C + bout + xn.
__global__ __launch_bounds__(256) void gemm_mma_kernel(
    const __nv_bfloat16* __restrict__ BThi, const __nv_bfloat16* __restrict__ BTlo,
    int mode, const float* __restrict__ bout, float* __restrict__ outp) {
    __shared__ __align__(16) __nv_bfloat16 sAh[128][40];
    __shared__ __align__(16) __nv_bfloat16 sAl[128][40];
    __shared__ __align__(16) __nv_bfloat16 sBh[128][40];
    __shared__ __align__(16) __nv_bfloat16 sBl[128][40];

    int tid = threadIdx.x, lane = tid & 31, wid = tid >> 5;
    int wm = wid & 3, wn = wid >> 2;
    int mBase = blockIdx.y * 128, nBase = blockIdx.x * 128;

    float acc[2][8][4];
#pragma unroll
    for (int i = 0; i < 2; i++)
#pragma unroll
        for (int j = 0; j < 8; j++)
#pragma unroll
            for (int c = 0; c < 4; c++) acc[i][j][c] = 0.f;

    const uint4* gAh = (const uint4*)(g_Ahi + (size_t)mBase * 512);
    const uint4* gAl = (const uint4*)(g_Alo + (size_t)mBase * 512);
    const uint4* gBh = (const uint4*)(BThi + (size_t)nBase * 512);
    const uint4* gBl = (const uint4*)(BTlo + (size_t)nBase * 512);

    int lr = lane & 15, lh = lane >> 4;

    for (int ch = 0; ch < 16; ch++) {
        if (ch) __syncthreads();
#pragma unroll
        for (int i = 0; i < 2; i++) {
            int idx = tid + i * 256;
            int r = idx >> 2, c = idx & 3;
            size_t goff = (size_t)r * 64 + ch * 4 + c;
            *(uint4*)&sAh[r][c * 8] = gAh[goff];
            *(uint4*)&sAl[r][c * 8] = gAl[goff];
            *(uint4*)&sBh[r][c * 8] = gBh[goff];
            *(uint4*)&sBl[r][c * 8] = gBl[goff];
        }
        __syncthreads();
#pragma unroll
        for (int ks = 0; ks < 2; ks++) {
            int kc = ks * 16 + lh * 8;
            unsigned ah[2][4], al[2][4];
#pragma unroll
            for (int mi = 0; mi < 2; mi++) {
                int rowA = wm * 32 + mi * 16 + lr;
                ldm4(ah[mi], smem_u32(&sAh[rowA][kc]));
                ldm4(al[mi], smem_u32(&sAl[rowA][kc]));
            }
#pragma unroll
            for (int nt = 0; nt < 4; nt++) {
                int rowB = wn * 64 + nt * 16 + lr;
                unsigned bh[4], bl[4];
                ldm4(bh, smem_u32(&sBh[rowB][kc]));
                ldm4(bl, smem_u32(&sBl[rowB][kc]));
#pragma unroll
                for (int mi = 0; mi < 2; mi++) {
#pragma unroll
                    for (int ns = 0; ns < 2; ns++) {
                        float* cc = acc[mi][nt * 2 + ns];
                        mma16816(cc, ah[mi], bh[ns], bh[ns + 2]);
                        mma16816(cc, ah[mi], bl[ns], bl[ns + 2]);
                        mma16816(cc, al[mi], bh[ns], bh[ns + 2]);
                    }
                }
            }
        }
    }

    // epilogue
    int r0 = mBase + wm * 32 + (lane >> 2);
    if (mode == 0) {
        int sec = nBase >> 9;
        float sc = (sec == 0) ? SCALE : 1.f;
        float* dst = (sec == 0) ? g_q : ((sec == 1) ? g_k : g_v);
        int h = ((nBase + wn * 64) >> 6) & 7;
#pragma unroll
        for (int mi = 0; mi < 2; mi++) {
#pragma unroll
            for (int jn = 0; jn < 8; jn++) {
                int d = jn * 8 + (lane & 3) * 2;
#pragma unroll
                for (int half = 0; half < 2; half++) {
                    int gr = r0 + mi * 16 + half * 8;
                    int bb = gr >> 13, n = gr & 8191;
                    float2 o = make_float2(acc[mi][jn][half * 2] * sc,
                                           acc[mi][jn][half * 2 + 1] * sc);
                    *(float2*)&dst[((size_t)(bb * 8 + h) * NSEQ + n) * 64 + d] = o;
                }
            }
        }
    } else {
#pragma unroll
        for (int mi = 0; mi < 2; mi++) {
#pragma unroll
            for (int jn = 0; jn < 8; jn++) {
                int gc = nBase + wn * 64 + jn * 8 + (lane & 3) * 2;
#pragma unroll
                for (int half = 0; half < 2; half++) {
                    int gr = r0 + mi * 16 + half * 8;
                    float2 bo = *(const float2*)&bout[gc];
                    float2 xv = *(const float2*)&g_xn[(size_t)gr * 512 + gc];
                    float2 o = make_float2(acc[mi][jn][half * 2] + bo.x + xv.x,
                                           acc[mi][jn][half * 2 + 1] + bo.y + xv.y);
                    *(float2*)&outp[(size_t)gr * 512 + gc] = o;
                }
            }
        }
    }
}

// ================= landmarks =================
__global__ void landmark_kernel() {
    int idx = blockIdx.x * 256 + threadIdx.x;
    int sel = idx >> 18;
    int r = idx & 262143;
    int bh = r >> 14;
    int m = (r >> 6) & 255;
    int d = r & 63;
    const float* src = sel ? g_k : g_q;
    const float* p = src + ((size_t)bh * NSEQ + m * LGRP) * DHd + d;
    float s = 0.f;
#pragma unroll
    for (int i = 0; i < LGRP; i++) s += p[i * DHd];
    (sel ? g_kl : g_ql)[(bh * MLM + m) * DHd + d] = s * (1.f / LGRP);
}

// ================= attn2 = softmax(q_l k_l^T) =================
__global__ __launch_bounds__(256) void attn2_kernel() {
    int bh = blockIdx.x;
    int m = threadIdx.x;
    __shared__ float4 kls[1024];
    float4 q[16];
    const float4* qp = (const float4*)g_ql + (size_t)(bh * MLM + m) * 16;
#pragma unroll
    for (int i = 0; i < 16; i++) q[i] = qp[i];
    float sum = 0.f;
    float* arow = g_attn2 + (size_t)bh * 65536 + (size_t)m * 256;
    for (int tile = 0; tile < 4; tile++) {
        __syncthreads();
        const float4* src = (const float4*)g_kl + (size_t)(bh * MLM + tile * 64) * 16;
#pragma unroll
        for (int i = 0; i < 4; i++) kls[threadIdx.x + i * 256] = src[threadIdx.x + i * 256];
        __syncthreads();
        for (int j = 0; j < 64; j++) {
            const float4* kr = &kls[j * 16];
            float s = 0.f;
#pragma unroll
            for (int d = 0; d < 16; d++) {
                float4 a = q[d], b = kr[d];
                s += a.x * b.x + a.y * b.y + a.z * b.z + a.w * b.w;
            }
            float p = __expf(s);
            sum += p;
            arow[tile * 64 + j] = p;
        }
    }
    float inv = 1.f / sum;
    for (int j = 0; j < 256; j++) arow[j] *= inv;
}

// ================= max column-sum of attn2 =================
__global__ __launch_bounds__(256) void colmax_kernel() {
    int bh = blockIdx.x;
    int j = threadIdx.x;
    const float* a = g_attn2 + (size_t)bh * 65536;
    float s = 0.f;
    for (int m2 = 0; m2 < 256; m2++) s += a[m2 * 256 + j];
    __shared__ float red[256];
    red[j] = s;
    __syncthreads();
    for (int o = 128; o; o >>= 1) {
        if (j < o) red[j] = fmaxf(red[j], red[j + o]);
        __syncthreads();
    }
    if (j == 0) atomicMax(&g_maxc_bits, __float_as_int(red[0]));
}

__global__ void z0_kernel() {
    int idx = blockIdx.x * 256 + threadIdx.x;
    int bh = idx >> 16;
    int i = (idx >> 8) & 255;
    int j = idx & 255;
    float scale = 1.f / __int_as_float(g_maxc_bits);
    g_Za[idx] = g_attn2[(bh << 16) + (j << 8) + i] * scale;
}

// ================= buffer selector =================
__device__ __forceinline__ float* pickBuf(int id) {
    switch (id) {
        case 0: return g_attn2;
        case 1: return g_Y;
        case 2: return g_P;
        case 3: return g_Qm;
        case 4: return g_Za;
        case 5: return g_Zb;
        case 6: return g_W2;
        default: return g_W3;
    }
}

// ================= batched per-bh GEMM: C = alpha * A @ (beta*I + sgn*B) =================
__global__ __launch_bounds__(256) void gemm_bh_kernel(int cId, int aId, int bId, int Nn,
                                                      float beta, float sgn, float alpha) {
    int bh = blockIdx.z, mt = blockIdx.y, nt = blockIdx.x;
    const float* A  = pickBuf(aId) + (size_t)bh * 65536;
    const float* Bp = pickBuf(bId) + (size_t)bh * 256 * Nn;
    float*       C  = pickBuf(cId) + (size_t)bh * 256 * Nn;
    __shared__ float As[16][64];
    __shared__ float Bs[16][64];
    int tid = threadIdx.x;
    int ar = tid >> 2, ac = (tid & 3) * 4;
    int br = tid >> 4, bc = (tid & 15) * 4;
    int ty = tid >> 4, tx = tid & 15;
    float acc[4][4];
#pragma unroll
    for (int i = 0; i < 4; i++)
#pragma unroll
        for (int j = 0; j < 4; j++) acc[i][j] = 0.f;

    for (int k0 = 0; k0 < 256; k0 += 16) {
        float4 av = *(const float4*)&A[(size_t)(mt * 64 + ar) * 256 + k0 + ac];
        As[ac + 0][ar] = av.x; As[ac + 1][ar] = av.y;
        As[ac + 2][ar] = av.z; As[ac + 3][ar] = av.w;
        int gk = k0 + br;
        int gc = nt * 64 + bc;
        float4 bv = *(const float4*)&Bp[(size_t)gk * Nn + gc];
        bv.x = sgn * bv.x + (gk == gc + 0 ? beta : 0.f);
        bv.y = sgn * bv.y + (gk == gc + 1 ? beta : 0.f);
        bv.z = sgn * bv.z + (gk == gc + 2 ? beta : 0.f);
        bv.w = sgn * bv.w + (gk == gc + 3 ? beta : 0.f);
        *(float4*)&Bs[br][bc] = bv;
        __syncthreads();
#pragma unroll
        for (int kk = 0; kk < 16; kk++) {
            float4 a4 = *(const float4*)&As[kk][ty * 4];
            float4 b4 = *(const float4*)&Bs[kk][tx * 4];
            acc[0][0] += a4.x * b4.x; acc[0][1] += a4.x * b4.y; acc[0][2] += a4.x * b4.z; acc[0][3] += a4.x * b4.w;
            acc[1][0] += a4.y * b4.x; acc[1][1] += a4.y * b4.y; acc[1][2] += a4.y * b4.z; acc[1][3] += a4.y * b4.w;
            acc[2][0] += a4.z * b4.x; acc[2][1] += a4.z * b4.y; acc[2][2] += a4.z * b4.z; acc[2][3] += a4.z * b4.w;
            acc[3][0] += a4.w * b4.x; acc[3][1] += a4.w * b4.y; acc[3][2] += a4.w * b4.z; acc[3][3] += a4.w * b4.w;
        }
        __syncthreads();
    }
#pragma unroll
    for (int i = 0; i < 4; i++) {
        float4 o = make_float4(acc[i][0] * alpha, acc[i][1] * alpha,
                               acc[i][2] * alpha, acc[i][3] * alpha);
        *(float4*)&C[(size_t)(mt * 64 + ty * 4 + i) * Nn + nt * 64 + tx * 4] = o;
    }
}

// ================= W2 = softmax(q_l k^T) @ v  (split-K) =================
__global__ __launch_bounds__(256) void flash_w2_kernel() {
    int chunk = blockIdx.x, bh = blockIdx.y;
    int tid = threadIdx.x;
    __shared__ float4 ks[512], vs[512];
    float4 q[16];
    const float4* qp = (const float4*)g_ql + (size_t)(bh * MLM + tid) * 16;
#pragma unroll
    for (int i = 0; i < 16; i++) q[i] = qp[i];
    float4 acc[16];
#pragma unroll
    for (int i = 0; i < 16; i++) acc[i] = make_float4(0.f, 0.f, 0.f, 0.f);
    float sum = 0.f;

    for (int t = 0; t < 8; t++) {
        int k0 = chunk * 256 + t * 32;
        __syncthreads();
        const float4* kp = (const float4*)g_k + ((size_t)bh * NSEQ + k0) * 16;
        const float4* vp = (const float4*)g_v + ((size_t)bh * NSEQ + k0) * 16;
        ks[tid] = kp[tid]; ks[tid + 256] = kp[tid + 256];
        vs[tid] = vp[tid]; vs[tid + 256] = vp[tid + 256];
        __syncthreads();
        for (int j = 0; j < 32; j++) {
            float s = 0.f;
#pragma unroll
            for (int d = 0; d < 16; d++) {
                float4 a = q[d], b = ks[j * 16 + d];
                s += a.x * b.x + a.y * b.y + a.z * b.z + a.w * b.w;
            }
            float p = __expf(s);
            sum += p;
#pragma unroll
            for (int d = 0; d < 16; d++) {
                float4 b = vs[j * 16 + d];
                acc[d].x += p * b.x; acc[d].y += p * b.y;
                acc[d].z += p * b.z; acc[d].w += p * b.w;
            }
        }
    }
    float4* wp = (float4*)(g_Wpart + (size_t)((bh * NCHUNK + chunk) * MLM + tid) * DHd);
#pragma unroll
    for (int d = 0; d < 16; d++) wp[d] = acc[d];
    g_Spart[(bh * NCHUNK + chunk) * MLM + tid] = sum;
}

__global__ void combine_w2_kernel() {
    int idx = blockIdx.x * 256 + threadIdx.x;
    int bh = idx >> 14;
    int m = (idx >> 6) & 255;
    int d = idx & 63;
    float num = 0.f, den = 0.f;
    for (int c = 0; c < NCHUNK; c++) {
        num += g_Wpart[(size_t)((bh * NCHUNK + c) * MLM + m) * DHd + d];
        den += g_Spart[(bh * NCHUNK + c) * MLM + m];
    }
    g_W2[(bh * MLM + m) * DHd + d] = num / den;
}

// ================= fused: softmax(q k_l^T) @ W3 + conv residual =================
__global__ __launch_bounds__(256) void attn1_conv_kernel(const float* __restrict__ convw) {
    int rt = blockIdx.x, bh = blockIdx.y;
    int tid = threadIdx.x;
    int n = rt * 256 + tid;
    int h = bh & 7;
    __shared__ float4 kls[1024];
    __shared__ float4 w3s[1024];
    __shared__ float cw[KSZ];
    if (tid < KSZ) cw[tid] = convw[h * KSZ + tid];

    float4 q[16];
    const float4* qp = (const float4*)g_q + ((size_t)bh * NSEQ + n) * 16;
#pragma unroll
    for (int i = 0; i < 16; i++) q[i] = qp[i];
    float4 acc[16];
#pragma unroll
    for (int i = 0; i < 16; i++) acc[i] = make_float4(0.f, 0.f, 0.f, 0.f);
    float sum = 0.f;

    for (int tile = 0; tile < 4; tile++) {
        __syncthreads();
        const float4* kp = (const float4*)g_kl + (size_t)(bh * MLM + tile * 64) * 16;
        const float4* wp = (const float4*)g_W3 + (size_t)(bh * MLM + tile * 64) * 16;
#pragma unroll
        for (int i = 0; i < 4; i++) {
            kls[tid + i * 256] = kp[tid + i * 256];
            w3s[tid + i * 256] = wp[tid + i * 256];
        }
        __syncthreads();
        for (int j = 0; j < 64; j++) {
            float s = 0.f;
#pragma unroll
            for (int d = 0; d < 16; d++) {
                float4 a = q[d], b = kls[j * 16 + d];
                s += a.x * b.x + a.y * b.y + a.z * b.z + a.w * b.w;
            }
            float p = __expf(s);
            sum += p;
#pragma unroll
            for (int d = 0; d < 16; d++) {
                float4 b = w3s[j * 16 + d];
                acc[d].x += p * b.x; acc[d].y += p * b.y;
                acc[d].z += p * b.z; acc[d].w += p * b.w;
            }
        }
    }
    float inv = 1.f / sum;
#pragma unroll
    for (int d = 0; d < 16; d++) {
        acc[d].x *= inv; acc[d].y *= inv; acc[d].z *= inv; acc[d].w *= inv;
    }
    const float4* vb = (const float4*)g_v + (size_t)bh * NSEQ * 16;
#pragma unroll
    for (int t = 0; t < KSZ; t++) {
        int r = n + t - PADc;
        if ((unsigned)r < (unsigned)NSEQ) {
            float w = cw[t];
            const float4* vr = vb + (size_t)r * 16;
#pragma unroll
            for (int d = 0; d < 16; d++) {
                float4 b = vr[d];
                acc[d].x += w * b.x; acc[d].y += w * b.y;
                acc[d].z += w * b.z; acc[d].w += w * b.w;
            }
        }
    }
    int bb = bh >> 3;
    float4* op = (float4*)(g_outpre + (size_t)(bb * NSEQ + n) * DIMV + h * DHd);
#pragma unroll
    for (int d = 0; d < 16; d++) op[d] = acc[d];
}

// ================= host launcher =================
extern "C" void kernel_launch(void* const* d_in, const int* in_sizes, int n_in,
                              void* d_out, int out_size) {
    const float* x     = (const float*)d_in[0];
    const float* ln_g  = (const float*)d_in[1];
    const float* ln_b  = (const float*)d_in[2];
    const float* W_qkv = (const float*)d_in[3];
    const float* W_out = (const float*)d_in[4];
    const float* b_out = (const float*)d_in[5];
    const float* convw = (const float*)d_in[6];
    float* out = (float*)d_out;

    __nv_bfloat16 *bqh, *bql, *boh, *bol;
    cudaGetSymbolAddress((void**)&bqh, g_Bqh);
    cudaGetSymbolAddress((void**)&bql, g_Bql);
    cudaGetSymbolAddress((void**)&boh, g_Boh);
    cudaGetSymbolAddress((void**)&bol, g_Bol);
    float* xnp;
    cudaGetSymbolAddress((void**)&xnp, g_xn);
    float* opp;
    cudaGetSymbolAddress((void**)&opp, g_outpre);

    reset_kernel<<<1, 1>>>();
    ln_kernel<<<Bb * NSEQ, 128>>>(x, ln_g, ln_b);

    // bf16 conversions
    convA_kernel<<<8192, 256>>>(xnp);
    convW_kernel<<<dim3(48, 16), 1024>>>(W_qkv, 1536, bqh, bql);
    convW_kernel<<<dim3(16, 16), 1024>>>(W_out, 512, boh, bol);

    // qkv GEMM on tensor cores (mma.sync)
    gemm_mma_kernel<<<dim3(12, 128), 256>>>(bqh, bql, 0, nullptr, nullptr);

    landmark_kernel<<<2048, 256>>>();
    attn2_kernel<<<16, 256>>>();
    colmax_kernel<<<16, 256>>>();
    z0_kernel<<<4096, 256>>>();

    int zc = 4, zn = 5;  // Za, Zb
    for (int it = 0; it < 6; it++) {
        gemm_bh_kernel<<<dim3(4, 4, 16), 256>>>(1, 0, zc, 256, 0.f, 1.f, 1.f);
        gemm_bh_kernel<<<dim3(4, 4, 16), 256>>>(2, 1, 1, 256, 7.f, -1.f, 1.f);
        gemm_bh_kernel<<<dim3(4, 4, 16), 256>>>(3, 1, 2, 256, 15.f, -1.f, 1.f);
        gemm_bh_kernel<<<dim3(4, 4, 16), 256>>>(zn, zc, 3, 256, 13.f, -1.f, 0.25f);
        int t = zc; zc = zn; zn = t;
    }

    flash_w2_kernel<<<dim3(NCHUNK, 16), 256>>>();
    combine_w2_kernel<<<1024, 256>>>();
    gemm_bh_kernel<<<dim3(1, 4, 16), 256>>>(7, zc, 6, 64, 0.f, 1.f, 1.f);  // W3 = Z @ W2
    attn1_conv_kernel<<<dim3(32, 16), 256>>>(convw);

    // out GEMM on tensor cores
    convA_kernel<<<8192, 256>>>(opp);
    gemm_mma_kernel<<<dim3(4, 128), 256>>>(boh, bol, 1, b_out, out);
}

// round 5
// speedup vs baseline: 1.4361x; 1.1250x over previous
#include <cuda_runtime.h>
#include <cuda_bf16.h>

#define Bb    2
#define NSEQ  8192
#define DIMV  512
#define NH    8
#define BHn   16
#define DHd   64
#define MLM   256
#define LGRP  32
#define KSZ   33
#define PADc  16
#define SCALE 0.125f
#define NCHUNK 32

// ================= static device scratch =================
__device__ float g_xn[(size_t)Bb * NSEQ * DIMV];
__device__ float g_q[(size_t)BHn * NSEQ * DHd];
__device__ float g_k[(size_t)BHn * NSEQ * DHd];
__device__ float g_v[(size_t)BHn * NSEQ * DHd];
__device__ float g_ql[BHn * MLM * DHd];
__device__ float g_kl[BHn * MLM * DHd];
__device__ float g_attn2[BHn * MLM * MLM];
__device__ float g_Y[BHn * MLM * MLM];
__device__ float g_P[BHn * MLM * MLM];
__device__ float g_Qm[BHn * MLM * MLM];
__device__ float g_Za[BHn * MLM * MLM];
__device__ float g_Zb[BHn * MLM * MLM];
__device__ float g_W2[BHn * MLM * DHd];
__device__ float g_W3[BHn * MLM * DHd];
__device__ float g_Wpart[(size_t)BHn * NCHUNK * MLM * DHd];
__device__ float g_Spart[BHn * NCHUNK * MLM];
__device__ float g_outpre[(size_t)Bb * NSEQ * DIMV];
__device__ int   g_maxc_bits;

// bf16 hi/lo buffers for dense tensor-core GEMMs
__device__ __nv_bfloat16 g_Ahi[(size_t)Bb * NSEQ * DIMV];
__device__ __nv_bfloat16 g_Alo[(size_t)Bb * NSEQ * DIMV];
__device__ __nv_bfloat16 g_Bqh[1536 * 512];
__device__ __nv_bfloat16 g_Bql[1536 * 512];
__device__ __nv_bfloat16 g_Boh[512 * 512];
__device__ __nv_bfloat16 g_Bol[512 * 512];

__global__ void reset_kernel() { g_maxc_bits = 0; }

// ================= mma.sync helpers =================
__device__ __forceinline__ unsigned smem_u32(const void* p) {
    unsigned a;
    asm("{ .reg .u64 t; cvta.to.shared.u64 t, %1; cvt.u32.u64 %0, t; }" : "=r"(a) : "l"(p));
    return a;
}
__device__ __forceinline__ void ldm4(unsigned* r, unsigned addr) {
    asm volatile("ldmatrix.sync.aligned.m8n8.x4.shared.b16 {%0,%1,%2,%3}, [%4];"
        : "=r"(r[0]), "=r"(r[1]), "=r"(r[2]), "=r"(r[3]) : "r"(addr));
}
__device__ __forceinline__ void mma16816(float* c, const unsigned* a, unsigned b0, unsigned b1) {
    asm volatile("mma.sync.aligned.m16n8k16.row.col.f32.bf16.bf16.f32 "
        "{%0,%1,%2,%3}, {%4,%5,%6,%7}, {%8,%9}, {%0,%1,%2,%3};"
        : "+f"(c[0]), "+f"(c[1]), "+f"(c[2]), "+f"(c[3])
        : "r"(a[0]), "r"(a[1]), "r"(a[2]), "r"(a[3]), "r"(b0), "r"(b1));
}

// ================= layernorm =================
__global__ __launch_bounds__(128) void ln_kernel(const float* __restrict__ x,
                                                 const float* __restrict__ gam,
                                                 const float* __restrict__ bet) {
    int row = blockIdx.x;
    int tid = threadIdx.x;
    float4 v = ((const float4*)x)[(size_t)row * 128 + tid];
    float s1 = v.x + v.y + v.z + v.w;
    float s2 = v.x * v.x + v.y * v.y + v.z * v.z + v.w * v.w;
#pragma unroll
    for (int o = 16; o; o >>= 1) {
        s1 += __shfl_xor_sync(0xffffffffu, s1, o);
        s2 += __shfl_xor_sync(0xffffffffu, s2, o);
    }
    __shared__ float r1[4], r2[4];
    int w = tid >> 5;
    if ((tid & 31) == 0) { r1[w] = s1; r2[w] = s2; }
    __syncthreads();
    s1 = r1[0] + r1[1] + r1[2] + r1[3];
    s2 = r2[0] + r2[1] + r2[2] + r2[3];
    float mean = s1 * (1.f / 512.f);
    float var  = s2 * (1.f / 512.f) - mean * mean;
    float rstd = rsqrtf(var + 1e-5f);
    float4 g4 = ((const float4*)gam)[tid];
    float4 b4 = ((const float4*)bet)[tid];
    float4 o;
    o.x = (v.x - mean) * rstd * g4.x + b4.x;
    o.y = (v.y - mean) * rstd * g4.y + b4.y;
    o.z = (v.z - mean) * rstd * g4.z + b4.z;
    o.w = (v.w - mean) * rstd * g4.w + b4.w;
    ((float4*)g_xn)[(size_t)row * 128 + tid] = o;
}

// ================= fp32 -> bf16 hi/lo converters =================
__global__ __launch_bounds__(256) void convA_kernel(const float* __restrict__ src) {
    size_t i4 = ((size_t)blockIdx.x * 256 + threadIdx.x) * 4;
    float4 v = *(const float4*)(src + i4);
    __nv_bfloat16 h0 = __float2bfloat16(v.x), h1 = __float2bfloat16(v.y);
    __nv_bfloat16 h2 = __float2bfloat16(v.z), h3 = __float2bfloat16(v.w);
    __nv_bfloat16 l0 = __float2bfloat16(v.x - __bfloat162float(h0));
    __nv_bfloat16 l1 = __float2bfloat16(v.y - __bfloat162float(h1));
    __nv_bfloat16 l2 = __float2bfloat16(v.z - __bfloat162float(h2));
    __nv_bfloat16 l3 = __float2bfloat16(v.w - __bfloat162float(h3));
    __nv_bfloat162* ph = (__nv_bfloat162*)(g_Ahi + i4);
    __nv_bfloat162* pl = (__nv_bfloat162*)(g_Alo + i4);
    ph[0] = __nv_bfloat162(h0, h1); ph[1] = __nv_bfloat162(h2, h3);
    pl[0] = __nv_bfloat162(l0, l1); pl[1] = __nv_bfloat162(l2, l3);
}

// transpose W[512, N] -> BT[N, 512] in bf16 hi/lo
__global__ __launch_bounds__(1024) void convW_kernel(const float* __restrict__ W, int N,
                                                     __nv_bfloat16* __restrict__ BThi,
                                                     __nv_bfloat16* __restrict__ BTlo) {
    __shared__ float sh[32][33];
    int n0 = blockIdx.x * 32, k0 = blockIdx.y * 32;
    int tx = threadIdx.x & 31, ty = threadIdx.x >> 5;
    sh[ty][tx] = W[(size_t)(k0 + ty) * N + n0 + tx];
    __syncthreads();
    float x = sh[tx][ty];
    __nv_bfloat16 h = __float2bfloat16(x);
    __nv_bfloat16 l = __float2bfloat16(x - __bfloat162float(h));
    BThi[(size_t)(n0 + ty) * 512 + k0 + tx] = h;
    BTlo[(size_t)(n0 + ty) * 512 + k0 + tx] = l;
}

// ================= mma.sync bf16 split GEMM (dense 512-K) =================
__global__ __launch_bounds__(256) void gemm_mma_kernel(
    const __nv_bfloat16* __restrict__ BThi, const __nv_bfloat16* __restrict__ BTlo,
    int mode, const float* __restrict__ bout, float* __restrict__ outp) {
    __shared__ __align__(16) __nv_bfloat16 sAh[128][40];
    __shared__ __align__(16) __nv_bfloat16 sAl[128][40];
    __shared__ __align__(16) __nv_bfloat16 sBh[128][40];
    __shared__ __align__(16) __nv_bfloat16 sBl[128][40];

    int tid = threadIdx.x, lane = tid & 31, wid = tid >> 5;
    int wm = wid & 3, wn = wid >> 2;
    int mBase = blockIdx.y * 128, nBase = blockIdx.x * 128;

    float acc[2][8][4];
#pragma unroll
    for (int i = 0; i < 2; i++)
#pragma unroll
        for (int j = 0; j < 8; j++)
#pragma unroll
            for (int c = 0; c < 4; c++) acc[i][j][c] = 0.f;

    const uint4* gAh = (const uint4*)(g_Ahi + (size_t)mBase * 512);
    const uint4* gAl = (const uint4*)(g_Alo + (size_t)mBase * 512);
    const uint4* gBh = (const uint4*)(BThi + (size_t)nBase * 512);
    const uint4* gBl = (const uint4*)(BTlo + (size_t)nBase * 512);

    int lr = lane & 15, lh = lane >> 4;

    for (int ch = 0; ch < 16; ch++) {
        if (ch) __syncthreads();
#pragma unroll
        for (int i = 0; i < 2; i++) {
            int idx = tid + i * 256;
            int r = idx >> 2, c = idx & 3;
            size_t goff = (size_t)r * 64 + ch * 4 + c;
            *(uint4*)&sAh[r][c * 8] = gAh[goff];
            *(uint4*)&sAl[r][c * 8] = gAl[goff];
            *(uint4*)&sBh[r][c * 8] = gBh[goff];
            *(uint4*)&sBl[r][c * 8] = gBl[goff];
        }
        __syncthreads();
#pragma unroll
        for (int ks = 0; ks < 2; ks++) {
            int kc = ks * 16 + lh * 8;
            unsigned ah[2][4], al[2][4];
#pragma unroll
            for (int mi = 0; mi < 2; mi++) {
                int rowA = wm * 32 + mi * 16 + lr;
                ldm4(ah[mi], smem_u32(&sAh[rowA][kc]));
                ldm4(al[mi], smem_u32(&sAl[rowA][kc]));
            }
#pragma unroll
            for (int nt = 0; nt < 4; nt++) {
                int rowB = wn * 64 + nt * 16 + lr;
                unsigned bh[4], bl[4];
                ldm4(bh, smem_u32(&sBh[rowB][kc]));
                ldm4(bl, smem_u32(&sBl[rowB][kc]));
#pragma unroll
                for (int mi = 0; mi < 2; mi++) {
#pragma unroll
                    for (int ns = 0; ns < 2; ns++) {
                        float* cc = acc[mi][nt * 2 + ns];
                        mma16816(cc, ah[mi], bh[ns], bh[ns + 2]);
                        mma16816(cc, ah[mi], bl[ns], bl[ns + 2]);
                        mma16816(cc, al[mi], bh[ns], bh[ns + 2]);
                    }
                }
            }
        }
    }

    int r0 = mBase + wm * 32 + (lane >> 2);
    if (mode == 0) {
        int sec = nBase >> 9;
        float sc = (sec == 0) ? SCALE : 1.f;
        float* dst = (sec == 0) ? g_q : ((sec == 1) ? g_k : g_v);
        int h = ((nBase + wn * 64) >> 6) & 7;
#pragma unroll
        for (int mi = 0; mi < 2; mi++) {
#pragma unroll
            for (int jn = 0; jn < 8; jn++) {
                int d = jn * 8 + (lane & 3) * 2;
#pragma unroll
                for (int half = 0; half < 2; half++) {
                    int gr = r0 + mi * 16 + half * 8;
                    int bb = gr >> 13, n = gr & 8191;
                    float2 o = make_float2(acc[mi][jn][half * 2] * sc,
                                           acc[mi][jn][half * 2 + 1] * sc);
                    *(float2*)&dst[((size_t)(bb * 8 + h) * NSEQ + n) * 64 + d] = o;
                }
            }
        }
    } else {
#pragma unroll
        for (int mi = 0; mi < 2; mi++) {
#pragma unroll
            for (int jn = 0; jn < 8; jn++) {
                int gc = nBase + wn * 64 + jn * 8 + (lane & 3) * 2;
#pragma unroll
                for (int half = 0; half < 2; half++) {
                    int gr = r0 + mi * 16 + half * 8;
                    float2 bo = *(const float2*)&bout[gc];
                    float2 xv = *(const float2*)&g_xn[(size_t)gr * 512 + gc];
                    float2 o = make_float2(acc[mi][jn][half * 2] + bo.x + xv.x,
                                           acc[mi][jn][half * 2 + 1] + bo.y + xv.y);
                    *(float2*)&outp[(size_t)gr * 512 + gc] = o;
                }
            }
        }
    }
}

// ================= landmarks =================
__global__ void landmark_kernel() {
    int idx = blockIdx.x * 256 + threadIdx.x;
    int sel = idx >> 18;
    int r = idx & 262143;
    int bh = r >> 14;
    int m = (r >> 6) & 255;
    int d = r & 63;
    const float* src = sel ? g_k : g_q;
    const float* p = src + ((size_t)bh * NSEQ + m * LGRP) * DHd + d;
    float s = 0.f;
#pragma unroll
    for (int i = 0; i < LGRP; i++) s += p[i * DHd];
    (sel ? g_kl : g_ql)[(bh * MLM + m) * DHd + d] = s * (1.f / LGRP);
}

// ================= attn2 = softmax(q_l k_l^T) =================
__global__ __launch_bounds__(256) void attn2_kernel() {
    int bh = blockIdx.x;
    int m = threadIdx.x;
    __shared__ float4 kls[1024];
    float4 q[16];
    const float4* qp = (const float4*)g_ql + (size_t)(bh * MLM + m) * 16;
#pragma unroll
    for (int i = 0; i < 16; i++) q[i] = qp[i];
    float sum = 0.f;
    float* arow = g_attn2 + (size_t)bh * 65536 + (size_t)m * 256;
    for (int tile = 0; tile < 4; tile++) {
        __syncthreads();
        const float4* src = (const float4*)g_kl + (size_t)(bh * MLM + tile * 64) * 16;
#pragma unroll
        for (int i = 0; i < 4; i++) kls[threadIdx.x + i * 256] = src[threadIdx.x + i * 256];
        __syncthreads();
        for (int j = 0; j < 64; j++) {
            const float4* kr = &kls[j * 16];
            float s = 0.f;
#pragma unroll
            for (int d = 0; d < 16; d++) {
                float4 a = q[d], b = kr[d];
                s += a.x * b.x + a.y * b.y + a.z * b.z + a.w * b.w;
            }
            float p = __expf(s);
            sum += p;
            arow[tile * 64 + j] = p;
        }
    }
    float inv = 1.f / sum;
    for (int j = 0; j < 256; j++) arow[j] *= inv;
}

// ================= max column-sum of attn2 =================
__global__ __launch_bounds__(256) void colmax_kernel() {
    int bh = blockIdx.x;
    int j = threadIdx.x;
    const float* a = g_attn2 + (size_t)bh * 65536;
    float s = 0.f;
    for (int m2 = 0; m2 < 256; m2++) s += a[m2 * 256 + j];
    __shared__ float red[256];
    red[j] = s;
    __syncthreads();
    for (int o = 128; o; o >>= 1) {
        if (j < o) red[j] = fmaxf(red[j], red[j + o]);
        __syncthreads();
    }
    if (j == 0) atomicMax(&g_maxc_bits, __float_as_int(red[0]));
}

__global__ void z0_kernel() {
    int idx = blockIdx.x * 256 + threadIdx.x;
    int bh = idx >> 16;
    int i = (idx >> 8) & 255;
    int j = idx & 255;
    float scale = 1.f / __int_as_float(g_maxc_bits);
    g_Za[idx] = g_attn2[(bh << 16) + (j << 8) + i] * scale;
}

// ================= buffer selector =================
__device__ __forceinline__ float* pickBuf(int id) {
    switch (id) {
        case 0: return g_attn2;
        case 1: return g_Y;
        case 2: return g_P;
        case 3: return g_Qm;
        case 4: return g_Za;
        case 5: return g_Zb;
        case 6: return g_W2;
        default: return g_W3;
    }
}

// ================= pinv batched GEMM on tensor cores =================
// C[256,256] = alpha * A[256,256] @ (beta*I + sgn*B[256,256]) per bh.
// fp32 in/out; in-kernel hi/lo bf16 split (3 MMA passes). Tile 128m x 64n.
__global__ __launch_bounds__(256) void gemm_pinv_mma(int cId, int aId, int bId,
                                                     float beta, float sgn, float alpha) {
    __shared__ __align__(16) __nv_bfloat16 sAh[128][40];
    __shared__ __align__(16) __nv_bfloat16 sAl[128][40];
    __shared__ __align__(16) __nv_bfloat16 sBh[64][40];
    __shared__ __align__(16) __nv_bfloat16 sBl[64][40];

    int bh = blockIdx.z;
    int mBase = blockIdx.y * 128, nBase = blockIdx.x * 64;
    const float* A = pickBuf(aId) + (size_t)bh * 65536;
    const float* B = pickBuf(bId) + (size_t)bh * 65536;
    float*       C = pickBuf(cId) + (size_t)bh * 65536;

    int tid = threadIdx.x, lane = tid & 31, w = tid >> 5;
    int wm = w & 3, wn = w >> 2;  // 4 m-warps x 2 n-warps
    int lr = lane & 15, lh = lane >> 4;

    float acc[2][4][4];
#pragma unroll
    for (int i = 0; i < 2; i++)
#pragma unroll
        for (int j = 0; j < 4; j++)
#pragma unroll
            for (int c = 0; c < 4; c++) acc[i][j][c] = 0.f;

    for (int ch = 0; ch < 8; ch++) {
        if (ch) __syncthreads();
        // ---- load A tile 128x32 fp32, convert hi/lo ----
#pragma unroll
        for (int i = 0; i < 4; i++) {
            int idx = tid + i * 256;
            int r = idx >> 3, c4 = (idx & 7) * 4;
            float4 v = *(const float4*)&A[(size_t)(mBase + r) * 256 + ch * 32 + c4];
            __nv_bfloat16 h0 = __float2bfloat16(v.x), h1 = __float2bfloat16(v.y);
            __nv_bfloat16 h2 = __float2bfloat16(v.z), h3 = __float2bfloat16(v.w);
            sAh[r][c4 + 0] = h0; sAh[r][c4 + 1] = h1;
            sAh[r][c4 + 2] = h2; sAh[r][c4 + 3] = h3;
            sAl[r][c4 + 0] = __float2bfloat16(v.x - __bfloat162float(h0));
            sAl[r][c4 + 1] = __float2bfloat16(v.y - __bfloat162float(h1));
            sAl[r][c4 + 2] = __float2bfloat16(v.z - __bfloat162float(h2));
            sAl[r][c4 + 3] = __float2bfloat16(v.w - __bfloat162float(h3));
        }
        // ---- load B tile 32k x 64n fp32, fold beta*I + sgn*B, store transposed ----
#pragma unroll
        for (int kl = 0; kl < 4; kl++) {
            int gk = ch * 32 + w * 4 + kl;
#pragma unroll
            for (int nh = 0; nh < 2; nh++) {
                int n = nh * 32 + lane;
                float v = B[(size_t)gk * 256 + nBase + n];
                v = sgn * v + ((gk == nBase + n) ? beta : 0.f);
                __nv_bfloat16 h = __float2bfloat16(v);
                sBh[n][w * 4 + kl] = h;
                sBl[n][w * 4 + kl] = __float2bfloat16(v - __bfloat162float(h));
            }
        }
        __syncthreads();
        // ---- MMA phase ----
#pragma unroll
        for (int ks = 0; ks < 2; ks++) {
            int kc = ks * 16 + lh * 8;
            unsigned ah[2][4], al[2][4];
#pragma unroll
            for (int mi = 0; mi < 2; mi++) {
                int rowA = wm * 32 + mi * 16 + lr;
                ldm4(ah[mi], smem_u32(&sAh[rowA][kc]));
                ldm4(al[mi], smem_u32(&sAl[rowA][kc]));
            }
#pragma unroll
            for (int nt = 0; nt < 2; nt++) {
                int rowB = wn * 32 + nt * 16 + lr;
                unsigned bhf[4], blf[4];
                ldm4(bhf, smem_u32(&sBh[rowB][kc]));
                ldm4(blf, smem_u32(&sBl[rowB][kc]));
#pragma unroll
                for (int mi = 0; mi < 2; mi++) {
#pragma unroll
                    for (int ns = 0; ns < 2; ns++) {
                        float* cc = acc[mi][nt * 2 + ns];
                        mma16816(cc, ah[mi], bhf[ns], bhf[ns + 2]);
                        mma16816(cc, ah[mi], blf[ns], blf[ns + 2]);
                        mma16816(cc, al[mi], bhf[ns], bhf[ns + 2]);
                    }
                }
            }
        }
    }
    // ---- epilogue: C = alpha * acc ----
#pragma unroll
    for (int mi = 0; mi < 2; mi++) {
#pragma unroll
        for (int jn = 0; jn < 4; jn++) {
            int gc = nBase + wn * 32 + jn * 8 + (lane & 3) * 2;
#pragma unroll
            for (int half = 0; half < 2; half++) {
                int gr = mBase + wm * 32 + mi * 16 + (lane >> 2) + half * 8;
                float2 o = make_float2(acc[mi][jn][half * 2] * alpha,
                                       acc[mi][jn][half * 2 + 1] * alpha);
                *(float2*)&C[(size_t)gr * 256 + gc] = o;
            }
        }
    }
}

// ================= batched per-bh GEMM (scalar, kept for W3) =================
__global__ __launch_bounds__(256) void gemm_bh_kernel(int cId, int aId, int bId, int Nn,
                                                      float beta, float sgn, float alpha) {
    int bh = blockIdx.z, mt = blockIdx.y, nt = blockIdx.x;
    const float* A  = pickBuf(aId) + (size_t)bh * 65536;
    const float* Bp = pickBuf(bId) + (size_t)bh * 256 * Nn;
    float*       C  = pickBuf(cId) + (size_t)bh * 256 * Nn;
    __shared__ float As[16][64];
    __shared__ float Bs[16][64];
    int tid = threadIdx.x;
    int ar = tid >> 2, ac = (tid & 3) * 4;
    int br = tid >> 4, bc = (tid & 15) * 4;
    int ty = tid >> 4, tx = tid & 15;
    float acc[4][4];
#pragma unroll
    for (int i = 0; i < 4; i++)
#pragma unroll
        for (int j = 0; j < 4; j++) acc[i][j] = 0.f;

    for (int k0 = 0; k0 < 256; k0 += 16) {
        float4 av = *(const float4*)&A[(size_t)(mt * 64 + ar) * 256 + k0 + ac];
        As[ac + 0][ar] = av.x; As[ac + 1][ar] = av.y;
        As[ac + 2][ar] = av.z; As[ac + 3][ar] = av.w;
        int gk = k0 + br;
        int gc = nt * 64 + bc;
        float4 bv = *(const float4*)&Bp[(size_t)gk * Nn + gc];
        bv.x = sgn * bv.x + (gk == gc + 0 ? beta : 0.f);
        bv.y = sgn * bv.y + (gk == gc + 1 ? beta : 0.f);
        bv.z = sgn * bv.z + (gk == gc + 2 ? beta : 0.f);
        bv.w = sgn * bv.w + (gk == gc + 3 ? beta : 0.f);
        *(float4*)&Bs[br][bc] = bv;
        __syncthreads();
#pragma unroll
        for (int kk = 0; kk < 16; kk++) {
            float4 a4 = *(const float4*)&As[kk][ty * 4];
            float4 b4 = *(const float4*)&Bs[kk][tx * 4];
            acc[0][0] += a4.x * b4.x; acc[0][1] += a4.x * b4.y; acc[0][2] += a4.x * b4.z; acc[0][3] += a4.x * b4.w;
            acc[1][0] += a4.y * b4.x; acc[1][1] += a4.y * b4.y; acc[1][2] += a4.y * b4.z; acc[1][3] += a4.y * b4.w;
            acc[2][0] += a4.z * b4.x; acc[2][1] += a4.z * b4.y; acc[2][2] += a4.z * b4.z; acc[2][3] += a4.z * b4.w;
            acc[3][0] += a4.w * b4.x; acc[3][1] += a4.w * b4.y; acc[3][2] += a4.w * b4.z; acc[3][3] += a4.w * b4.w;
        }
        __syncthreads();
    }
#pragma unroll
    for (int i = 0; i < 4; i++) {
        float4 o = make_float4(acc[i][0] * alpha, acc[i][1] * alpha,
                               acc[i][2] * alpha, acc[i][3] * alpha);
        *(float4*)&C[(size_t)(mt * 64 + ty * 4 + i) * Nn + nt * 64 + tx * 4] = o;
    }
}

// ================= W2 = softmax(q_l k^T) @ v  (split-K) =================
__global__ __launch_bounds__(256) void flash_w2_kernel() {
    int chunk = blockIdx.x, bh = blockIdx.y;
    int tid = threadIdx.x;
    __shared__ float4 ks[512], vs[512];
    float4 q[16];
    const float4* qp = (const float4*)g_ql + (size_t)(bh * MLM + tid) * 16;
#pragma unroll
    for (int i = 0; i < 16; i++) q[i] = qp[i];
    float4 acc[16];
#pragma unroll
    for (int i = 0; i < 16; i++) acc[i] = make_float4(0.f, 0.f, 0.f, 0.f);
    float sum = 0.f;

    for (int t = 0; t < 8; t++) {
        int k0 = chunk * 256 + t * 32;
        __syncthreads();
        const float4* kp = (const float4*)g_k + ((size_t)bh * NSEQ + k0) * 16;
        const float4* vp = (const float4*)g_v + ((size_t)bh * NSEQ + k0) * 16;
        ks[tid] = kp[tid]; ks[tid + 256] = kp[tid + 256];
        vs[tid] = vp[tid]; vs[tid + 256] = vp[tid + 256];
        __syncthreads();
        for (int j = 0; j < 32; j++) {
            float s = 0.f;
#pragma unroll
            for (int d = 0; d < 16; d++) {
                float4 a = q[d], b = ks[j * 16 + d];
                s += a.x * b.x + a.y * b.y + a.z * b.z + a.w * b.w;
            }
            float p = __expf(s);
            sum += p;
#pragma unroll
            for (int d = 0; d < 16; d++) {
                float4 b = vs[j * 16 + d];
                acc[d].x += p * b.x; acc[d].y += p * b.y;
                acc[d].z += p * b.z; acc[d].w += p * b.w;
            }
        }
    }
    float4* wp = (float4*)(g_Wpart + (size_t)((bh * NCHUNK + chunk) * MLM + tid) * DHd);
#pragma unroll
    for (int d = 0; d < 16; d++) wp[d] = acc[d];
    g_Spart[(bh * NCHUNK + chunk) * MLM + tid] = sum;
}

__global__ void combine_w2_kernel() {
    int idx = blockIdx.x * 256 + threadIdx.x;
    int bh = idx >> 14;
    int m = (idx >> 6) & 255;
    int d = idx & 63;
    float num = 0.f, den = 0.f;
    for (int c = 0; c < NCHUNK; c++) {
        num += g_Wpart[(size_t)((bh * NCHUNK + c) * MLM + m) * DHd + d];
        den += g_Spart[(bh * NCHUNK + c) * MLM + m];
    }
    g_W2[(bh * MLM + m) * DHd + d] = num / den;
}

// ================= fused: softmax(q k_l^T) @ W3 + conv residual =================
__global__ __launch_bounds__(256) void attn1_conv_kernel(const float* __restrict__ convw) {
    int rt = blockIdx.x, bh = blockIdx.y;
    int tid = threadIdx.x;
    int n = rt * 256 + tid;
    int h = bh & 7;
    __shared__ float4 kls[1024];
    __shared__ float4 w3s[1024];
    __shared__ float cw[KSZ];
    if (tid < KSZ) cw[tid] = convw[h * KSZ + tid];

    float4 q[16];
    const float4* qp = (const float4*)g_q + ((size_t)bh * NSEQ + n) * 16;
#pragma unroll
    for (int i = 0; i < 16; i++) q[i] = qp[i];
    float4 acc[16];
#pragma unroll
    for (int i = 0; i < 16; i++) acc[i] = make_float4(0.f, 0.f, 0.f, 0.f);
    float sum = 0.f;

    for (int tile = 0; tile < 4; tile++) {
        __syncthreads();
        const float4* kp = (const float4*)g_kl + (size_t)(bh * MLM + tile * 64) * 16;
        const float4* wp = (const float4*)g_W3 + (size_t)(bh * MLM + tile * 64) * 16;
#pragma unroll
        for (int i = 0; i < 4; i++) {
            kls[tid + i * 256] = kp[tid + i * 256];
            w3s[tid + i * 256] = wp[tid + i * 256];
        }
        __syncthreads();
        for (int j = 0; j < 64; j++) {
            float s = 0.f;
#pragma unroll
            for (int d = 0; d < 16; d++) {
                float4 a = q[d], b = kls[j * 16 + d];
                s += a.x * b.x + a.y * b.y + a.z * b.z + a.w * b.w;
            }
            float p = __expf(s);
            sum += p;
#pragma unroll
            for (int d = 0; d < 16; d++) {
                float4 b = w3s[j * 16 + d];
                acc[d].x += p * b.x; acc[d].y += p * b.y;
                acc[d].z += p * b.z; acc[d].w += p * b.w;
            }
        }
    }
    float inv = 1.f / sum;
#pragma unroll
    for (int d = 0; d < 16; d++) {
        acc[d].x *= inv; acc[d].y *= inv; acc[d].z *= inv; acc[d].w *= inv;
    }
    const float4* vb = (const float4*)g_v + (size_t)bh * NSEQ * 16;
#pragma unroll
    for (int t = 0; t < KSZ; t++) {
        int r = n + t - PADc;
        if ((unsigned)r < (unsigned)NSEQ) {
            float w = cw[t];
            const float4* vr = vb + (size_t)r * 16;
#pragma unroll
            for (int d = 0; d < 16; d++) {
                float4 b = vr[d];
                acc[d].x += w * b.x; acc[d].y += w * b.y;
                acc[d].z += w * b.z; acc[d].w += w * b.w;
            }
        }
    }
    int bb = bh >> 3;
    float4* op = (float4*)(g_outpre + (size_t)(bb * NSEQ + n) * DIMV + h * DHd);
#pragma unroll
    for (int d = 0; d < 16; d++) op[d] = acc[d];
}

// ================= host launcher =================
extern "C" void kernel_launch(void* const* d_in, const int* in_sizes, int n_in,
                              void* d_out, int out_size) {
    const float* x     = (const float*)d_in[0];
    const float* ln_g  = (const float*)d_in[1];
    const float* ln_b  = (const float*)d_in[2];
    const float* W_qkv = (const float*)d_in[3];
    const float* W_out = (const float*)d_in[4];
    const float* b_out = (const float*)d_in[5];
    const float* convw = (const float*)d_in[6];
    float* out = (float*)d_out;

    __nv_bfloat16 *bqh, *bql, *boh, *bol;
    cudaGetSymbolAddress((void**)&bqh, g_Bqh);
    cudaGetSymbolAddress((void**)&bql, g_Bql);
    cudaGetSymbolAddress((void**)&boh, g_Boh);
    cudaGetSymbolAddress((void**)&bol, g_Bol);
    float* xnp;
    cudaGetSymbolAddress((void**)&xnp, g_xn);
    float* opp;
    cudaGetSymbolAddress((void**)&opp, g_outpre);

    reset_kernel<<<1, 1>>>();
    ln_kernel<<<Bb * NSEQ, 128>>>(x, ln_g, ln_b);

    convA_kernel<<<8192, 256>>>(xnp);
    convW_kernel<<<dim3(48, 16), 1024>>>(W_qkv, 1536, bqh, bql);
    convW_kernel<<<dim3(16, 16), 1024>>>(W_out, 512, boh, bol);

    gemm_mma_kernel<<<dim3(12, 128), 256>>>(bqh, bql, 0, nullptr, nullptr);

    landmark_kernel<<<2048, 256>>>();
    attn2_kernel<<<16, 256>>>();
    colmax_kernel<<<16, 256>>>();
    z0_kernel<<<4096, 256>>>();

    int zc = 4, zn = 5;  // Za, Zb
    for (int it = 0; it < 6; it++) {
        gemm_pinv_mma<<<dim3(4, 2, 16), 256>>>(1, 0, zc, 0.f, 1.f, 1.f);      // Y  = A2 @ Z
        gemm_pinv_mma<<<dim3(4, 2, 16), 256>>>(2, 1, 1, 7.f, -1.f, 1.f);      // P  = Y @ (7I - Y)
        gemm_pinv_mma<<<dim3(4, 2, 16), 256>>>(3, 1, 2, 15.f, -1.f, 1.f);     // Qm = Y @ (15I - P)
        gemm_pinv_mma<<<dim3(4, 2, 16), 256>>>(zn, zc, 3, 13.f, -1.f, 0.25f); // Z' = 0.25 Z @ (13I - Qm)
        int t = zc; zc = zn; zn = t;
    }

    flash_w2_kernel<<<dim3(NCHUNK, 16), 256>>>();
    combine_w2_kernel<<<1024, 256>>>();
    gemm_bh_kernel<<<dim3(1, 4, 16), 256>>>(7, zc, 6, 64, 0.f, 1.f, 1.f);  // W3 = Z @ W2
    attn1_conv_kernel<<<dim3(32, 16), 256>>>(convw);

    convA_kernel<<<8192, 256>>>(opp);
    gemm_mma_kernel<<<dim3(4, 128), 256>>>(boh, bol, 1, b_out, out);
}

// round 6
// speedup vs baseline: 2.3977x; 1.6695x over previous
#include <cuda_runtime.h>
#include <cuda_bf16.h>
#include <cuda_fp16.h>

#define Bb    2
#define NSEQ  8192
#define DIMV  512
#define NH    8
#define BHn   16
#define DHd   64
#define MLM   256
#define LGRP  32
#define KSZ   33
#define PADc  16
#define SCALE 0.125f

// ================= static device scratch =================
__device__ float g_xn[(size_t)Bb * NSEQ * DIMV];
__device__ float g_q[(size_t)BHn * NSEQ * DHd];
__device__ float g_k[(size_t)BHn * NSEQ * DHd];
__device__ float g_v[(size_t)BHn * NSEQ * DHd];
__device__ float g_ql[BHn * MLM * DHd];
__device__ float g_kl[BHn * MLM * DHd];
__device__ float g_attn2[BHn * MLM * MLM];
__device__ float g_Y[BHn * MLM * MLM];
__device__ float g_P[BHn * MLM * MLM];
__device__ float g_Qm[BHn * MLM * MLM];
__device__ float g_Za[BHn * MLM * MLM];
__device__ float g_Zb[BHn * MLM * MLM];
__device__ float g_W2[BHn * MLM * DHd];
__device__ float g_W3[BHn * MLM * DHd];
__device__ float g_Wpart[(size_t)BHn * 4 * MLM * DHd];
__device__ float g_Spart[BHn * 4 * MLM];
__device__ float g_outpre[(size_t)Bb * NSEQ * DIMV];
__device__ int   g_maxc_bits;

// bf16 hi/lo buffers for dense tensor-core GEMMs
__device__ __nv_bfloat16 g_Ahi[(size_t)Bb * NSEQ * DIMV];
__device__ __nv_bfloat16 g_Alo[(size_t)Bb * NSEQ * DIMV];
__device__ __nv_bfloat16 g_Bqh[1536 * 512];
__device__ __nv_bfloat16 g_Bql[1536 * 512];
__device__ __nv_bfloat16 g_Boh[512 * 512];
__device__ __nv_bfloat16 g_Bol[512 * 512];

// fp16 buffers for attention mma kernels
__device__ __half g_qh[(size_t)BHn * NSEQ * DHd];
__device__ __half g_kh[(size_t)BHn * NSEQ * DHd];
__device__ __half g_vh[(size_t)BHn * NSEQ * DHd];
__device__ __half g_qlh[BHn * MLM * DHd];
__device__ __half g_klh[BHn * MLM * DHd];
__device__ __half g_W3T[BHn * DHd * MLM];

__global__ void reset_kernel() { g_maxc_bits = 0; }

// ================= mma.sync helpers =================
__device__ __forceinline__ unsigned smem_u32(const void* p) {
    unsigned a;
    asm("{ .reg .u64 t; cvta.to.shared.u64 t, %1; cvt.u32.u64 %0, t; }" : "=r"(a) : "l"(p));
    return a;
}
__device__ __forceinline__ void ldm4(unsigned* r, unsigned addr) {
    asm volatile("ldmatrix.sync.aligned.m8n8.x4.shared.b16 {%0,%1,%2,%3}, [%4];"
        : "=r"(r[0]), "=r"(r[1]), "=r"(r[2]), "=r"(r[3]) : "r"(addr));
}
__device__ __forceinline__ void mma16816(float* c, const unsigned* a, unsigned b0, unsigned b1) {
    asm volatile("mma.sync.aligned.m16n8k16.row.col.f32.bf16.bf16.f32 "
        "{%0,%1,%2,%3}, {%4,%5,%6,%7}, {%8,%9}, {%0,%1,%2,%3};"
        : "+f"(c[0]), "+f"(c[1]), "+f"(c[2]), "+f"(c[3])
        : "r"(a[0]), "r"(a[1]), "r"(a[2]), "r"(a[3]), "r"(b0), "r"(b1));
}
__device__ __forceinline__ void mmaf16(float* c, const unsigned* a, unsigned b0, unsigned b1) {
    asm volatile("mma.sync.aligned.m16n8k16.row.col.f32.f16.f16.f32 "
        "{%0,%1,%2,%3}, {%4,%5,%6,%7}, {%8,%9}, {%0,%1,%2,%3};"
        : "+f"(c[0]), "+f"(c[1]), "+f"(c[2]), "+f"(c[3])
        : "r"(a[0]), "r"(a[1]), "r"(a[2]), "r"(a[3]), "r"(b0), "r"(b1));
}
__device__ __forceinline__ unsigned packh2(float a, float b) {
    __half2 h = __floats2half2_rn(a, b);
    return *(unsigned*)&h;
}
// fast exp on FMA pipe (|x| small; poly rel err ~2.4e-6)
__device__ __forceinline__ float fexp(float x) {
    float t = x * 1.44269504f;
    float r = rintf(t);
    float f = t - r;
    float p = 1.33336e-3f;
    p = fmaf(p, f, 9.61813e-3f);
    p = fmaf(p, f, 5.55041e-2f);
    p = fmaf(p, f, 2.40226507e-1f);
    p = fmaf(p, f, 6.93147181e-1f);
    p = fmaf(p, f, 1.0f);
    int e = (int)r;
    return p * __int_as_float((e + 127) << 23);
}

// ================= layernorm =================
__global__ __launch_bounds__(128) void ln_kernel(const float* __restrict__ x,
                                                 const float* __restrict__ gam,
                                                 const float* __restrict__ bet) {
    int row = blockIdx.x;
    int tid = threadIdx.x;
    float4 v = ((const float4*)x)[(size_t)row * 128 + tid];
    float s1 = v.x + v.y + v.z + v.w;
    float s2 = v.x * v.x + v.y * v.y + v.z * v.z + v.w * v.w;
#pragma unroll
    for (int o = 16; o; o >>= 1) {
        s1 += __shfl_xor_sync(0xffffffffu, s1, o);
        s2 += __shfl_xor_sync(0xffffffffu, s2, o);
    }
    __shared__ float r1[4], r2[4];
    int w = tid >> 5;
    if ((tid & 31) == 0) { r1[w] = s1; r2[w] = s2; }
    __syncthreads();
    s1 = r1[0] + r1[1] + r1[2] + r1[3];
    s2 = r2[0] + r2[1] + r2[2] + r2[3];
    float mean = s1 * (1.f / 512.f);
    float var  = s2 * (1.f / 512.f) - mean * mean;
    float rstd = rsqrtf(var + 1e-5f);
    float4 g4 = ((const float4*)gam)[tid];
    float4 b4 = ((const float4*)bet)[tid];
    float4 o;
    o.x = (v.x - mean) * rstd * g4.x + b4.x;
    o.y = (v.y - mean) * rstd * g4.y + b4.y;
    o.z = (v.z - mean) * rstd * g4.z + b4.z;
    o.w = (v.w - mean) * rstd * g4.w + b4.w;
    ((float4*)g_xn)[(size_t)row * 128 + tid] = o;
}

// ================= fp32 -> bf16 hi/lo converters =================
__global__ __launch_bounds__(256) void convA_kernel(const float* __restrict__ src) {
    size_t i4 = ((size_t)blockIdx.x * 256 + threadIdx.x) * 4;
    float4 v = *(const float4*)(src + i4);
    __nv_bfloat16 h0 = __float2bfloat16(v.x), h1 = __float2bfloat16(v.y);
    __nv_bfloat16 h2 = __float2bfloat16(v.z), h3 = __float2bfloat16(v.w);
    __nv_bfloat16 l0 = __float2bfloat16(v.x - __bfloat162float(h0));
    __nv_bfloat16 l1 = __float2bfloat16(v.y - __bfloat162float(h1));
    __nv_bfloat16 l2 = __float2bfloat16(v.z - __bfloat162float(h2));
    __nv_bfloat16 l3 = __float2bfloat16(v.w - __bfloat162float(h3));
    __nv_bfloat162* ph = (__nv_bfloat162*)(g_Ahi + i4);
    __nv_bfloat162* pl = (__nv_bfloat162*)(g_Alo + i4);
    ph[0] = __nv_bfloat162(h0, h1); ph[1] = __nv_bfloat162(h2, h3);
    pl[0] = __nv_bfloat162(l0, l1); pl[1] = __nv_bfloat162(l2, l3);
}

__global__ __launch_bounds__(1024) void convW_kernel(const float* __restrict__ W, int N,
                                                     __nv_bfloat16* __restrict__ BThi,
                                                     __nv_bfloat16* __restrict__ BTlo) {
    __shared__ float sh[32][33];
    int n0 = blockIdx.x * 32, k0 = blockIdx.y * 32;
    int tx = threadIdx.x & 31, ty = threadIdx.x >> 5;
    sh[ty][tx] = W[(size_t)(k0 + ty) * N + n0 + tx];
    __syncthreads();
    float x = sh[tx][ty];
    __nv_bfloat16 h = __float2bfloat16(x);
    __nv_bfloat16 l = __float2bfloat16(x - __bfloat162float(h));
    BThi[(size_t)(n0 + ty) * 512 + k0 + tx] = h;
    BTlo[(size_t)(n0 + ty) * 512 + k0 + tx] = l;
}

// W3 -> W3T fp16 [bh][d][m]
__global__ void w3t_kernel() {
    int idx = blockIdx.x * 256 + threadIdx.x;
    int bh = idx >> 14;
    int m = (idx >> 6) & 255;
    int d = idx & 63;
    float v = g_W3[(bh * 256 + m) * 64 + d];
    g_W3T[((size_t)bh * 64 + d) * 256 + m] = __float2half(v);
}

// ================= mma.sync bf16 split GEMM (dense 512-K) =================
__global__ __launch_bounds__(256) void gemm_mma_kernel(
    const __nv_bfloat16* __restrict__ BThi, const __nv_bfloat16* __restrict__ BTlo,
    int mode, const float* __restrict__ bout, float* __restrict__ outp) {
    __shared__ __align__(16) __nv_bfloat16 sAh[128][40];
    __shared__ __align__(16) __nv_bfloat16 sAl[128][40];
    __shared__ __align__(16) __nv_bfloat16 sBh[128][40];
    __shared__ __align__(16) __nv_bfloat16 sBl[128][40];

    int tid = threadIdx.x, lane = tid & 31, wid = tid >> 5;
    int wm = wid & 3, wn = wid >> 2;
    int mBase = blockIdx.y * 128, nBase = blockIdx.x * 128;

    float acc[2][8][4];
#pragma unroll
    for (int i = 0; i < 2; i++)
#pragma unroll
        for (int j = 0; j < 8; j++)
#pragma unroll
            for (int c = 0; c < 4; c++) acc[i][j][c] = 0.f;

    const uint4* gAh = (const uint4*)(g_Ahi + (size_t)mBase * 512);
    const uint4* gAl = (const uint4*)(g_Alo + (size_t)mBase * 512);
    const uint4* gBh = (const uint4*)(BThi + (size_t)nBase * 512);
    const uint4* gBl = (const uint4*)(BTlo + (size_t)nBase * 512);

    int lr = lane & 15, lh = lane >> 4;

    for (int ch = 0; ch < 16; ch++) {
        if (ch) __syncthreads();
#pragma unroll
        for (int i = 0; i < 2; i++) {
            int idx = tid + i * 256;
            int r = idx >> 2, c = idx & 3;
            size_t goff = (size_t)r * 64 + ch * 4 + c;
            *(uint4*)&sAh[r][c * 8] = gAh[goff];
            *(uint4*)&sAl[r][c * 8] = gAl[goff];
            *(uint4*)&sBh[r][c * 8] = gBh[goff];
            *(uint4*)&sBl[r][c * 8] = gBl[goff];
        }
        __syncthreads();
#pragma unroll
        for (int ks = 0; ks < 2; ks++) {
            int kc = ks * 16 + lh * 8;
            unsigned ah[2][4], al[2][4];
#pragma unroll
            for (int mi = 0; mi < 2; mi++) {
                int rowA = wm * 32 + mi * 16 + lr;
                ldm4(ah[mi], smem_u32(&sAh[rowA][kc]));
                ldm4(al[mi], smem_u32(&sAl[rowA][kc]));
            }
#pragma unroll
            for (int nt = 0; nt < 4; nt++) {
                int rowB = wn * 64 + nt * 16 + lr;
                unsigned bh[4], bl[4];
                ldm4(bh, smem_u32(&sBh[rowB][kc]));
                ldm4(bl, smem_u32(&sBl[rowB][kc]));
#pragma unroll
                for (int mi = 0; mi < 2; mi++) {
#pragma unroll
                    for (int ns = 0; ns < 2; ns++) {
                        float* cc = acc[mi][nt * 2 + ns];
                        mma16816(cc, ah[mi], bh[ns], bh[ns + 2]);
                        mma16816(cc, ah[mi], bl[ns], bl[ns + 2]);
                        mma16816(cc, al[mi], bh[ns], bh[ns + 2]);
                    }
                }
            }
        }
    }

    int r0 = mBase + wm * 32 + (lane >> 2);
    if (mode == 0) {
        int sec = nBase >> 9;
        float sc = (sec == 0) ? SCALE : 1.f;
        float* dst = (sec == 0) ? g_q : ((sec == 1) ? g_k : g_v);
        __half* hdst = (sec == 0) ? g_qh : ((sec == 1) ? g_kh : g_vh);
        int h = ((nBase + wn * 64) >> 6) & 7;
#pragma unroll
        for (int mi = 0; mi < 2; mi++) {
#pragma unroll
            for (int jn = 0; jn < 8; jn++) {
                int d = jn * 8 + (lane & 3) * 2;
#pragma unroll
                for (int half = 0; half < 2; half++) {
                    int gr = r0 + mi * 16 + half * 8;
                    int bb = gr >> 13, n = gr & 8191;
                    float2 o = make_float2(acc[mi][jn][half * 2] * sc,
                                           acc[mi][jn][half * 2 + 1] * sc);
                    size_t off = ((size_t)(bb * 8 + h) * NSEQ + n) * 64 + d;
                    *(float2*)&dst[off] = o;
                    *(__half2*)&hdst[off] = __floats2half2_rn(o.x, o.y);
                }
            }
        }
    } else {
#pragma unroll
        for (int mi = 0; mi < 2; mi++) {
#pragma unroll
            for (int jn = 0; jn < 8; jn++) {
                int gc = nBase + wn * 64 + jn * 8 + (lane & 3) * 2;
#pragma unroll
                for (int half = 0; half < 2; half++) {
                    int gr = r0 + mi * 16 + half * 8;
                    float2 bo = *(const float2*)&bout[gc];
                    float2 xv = *(const float2*)&g_xn[(size_t)gr * 512 + gc];
                    float2 o = make_float2(acc[mi][jn][half * 2] + bo.x + xv.x,
                                           acc[mi][jn][half * 2 + 1] + bo.y + xv.y);
                    *(float2*)&outp[(size_t)gr * 512 + gc] = o;
                }
            }
        }
    }
}

// ================= landmarks (fp32 + fp16 out) =================
__global__ void landmark_kernel() {
    int idx = blockIdx.x * 256 + threadIdx.x;
    int sel = idx >> 18;
    int r = idx & 262143;
    int bh = r >> 14;
    int m = (r >> 6) & 255;
    int d = r & 63;
    const float* src = sel ? g_k : g_q;
    const float* p = src + ((size_t)bh * NSEQ + m * LGRP) * DHd + d;
    float s = 0.f;
#pragma unroll
    for (int i = 0; i < LGRP; i++) s += p[i * DHd];
    float val = s * (1.f / LGRP);
    (sel ? g_kl : g_ql)[(bh * MLM + m) * DHd + d] = val;
    (sel ? g_klh : g_qlh)[(bh * MLM + m) * DHd + d] = __float2half(val);
}

// ================= attn2 = softmax(q_l k_l^T) =================
__global__ __launch_bounds__(256) void attn2_kernel() {
    int bh = blockIdx.x;
    int m = threadIdx.x;
    __shared__ float4 kls[1024];
    float4 q[16];
    const float4* qp = (const float4*)g_ql + (size_t)(bh * MLM + m) * 16;
#pragma unroll
    for (int i = 0; i < 16; i++) q[i] = qp[i];
    float sum = 0.f;
    float* arow = g_attn2 + (size_t)bh * 65536 + (size_t)m * 256;
    for (int tile = 0; tile < 4; tile++) {
        __syncthreads();
        const float4* src = (const float4*)g_kl + (size_t)(bh * MLM + tile * 64) * 16;
#pragma unroll
        for (int i = 0; i < 4; i++) kls[threadIdx.x + i * 256] = src[threadIdx.x + i * 256];
        __syncthreads();
        for (int j = 0; j < 64; j++) {
            const float4* kr = &kls[j * 16];
            float s = 0.f;
#pragma unroll
            for (int d = 0; d < 16; d++) {
                float4 a = q[d], b = kr[d];
                s += a.x * b.x + a.y * b.y + a.z * b.z + a.w * b.w;
            }
            float p = __expf(s);
            sum += p;
            arow[tile * 64 + j] = p;
        }
    }
    float inv = 1.f / sum;
    for (int j = 0; j < 256; j++) arow[j] *= inv;
}

// ================= max column-sum of attn2 =================
__global__ __launch_bounds__(256) void colmax_kernel() {
    int bh = blockIdx.x;
    int j = threadIdx.x;
    const float* a = g_attn2 + (size_t)bh * 65536;
    float s = 0.f;
    for (int m2 = 0; m2 < 256; m2++) s += a[m2 * 256 + j];
    __shared__ float red[256];
    red[j] = s;
    __syncthreads();
    for (int o = 128; o; o >>= 1) {
        if (j < o) red[j] = fmaxf(red[j], red[j + o]);
        __syncthreads();
    }
    if (j == 0) atomicMax(&g_maxc_bits, __float_as_int(red[0]));
}

__global__ void z0_kernel() {
    int idx = blockIdx.x * 256 + threadIdx.x;
    int bh = idx >> 16;
    int i = (idx >> 8) & 255;
    int j = idx & 255;
    float scale = 1.f / __int_as_float(g_maxc_bits);
    g_Za[idx] = g_attn2[(bh << 16) + (j << 8) + i] * scale;
}

// ================= buffer selector =================
__device__ __forceinline__ float* pickBuf(int id) {
    switch (id) {
        case 0: return g_attn2;
        case 1: return g_Y;
        case 2: return g_P;
        case 3: return g_Qm;
        case 4: return g_Za;
        case 5: return g_Zb;
        case 6: return g_W2;
        default: return g_W3;
    }
}

// ================= pinv batched GEMM on tensor cores =================
__global__ __launch_bounds__(256) void gemm_pinv_mma(int cId, int aId, int bId,
                                                     float beta, float sgn, float alpha) {
    __shared__ __align__(16) __nv_bfloat16 sAh[128][40];
    __shared__ __align__(16) __nv_bfloat16 sAl[128][40];
    __shared__ __align__(16) __nv_bfloat16 sBh[64][40];
    __shared__ __align__(16) __nv_bfloat16 sBl[64][40];

    int bh = blockIdx.z;
    int mBase = blockIdx.y * 128, nBase = blockIdx.x * 64;
    const float* A = pickBuf(aId) + (size_t)bh * 65536;
    const float* B = pickBuf(bId) + (size_t)bh * 65536;
    float*       C = pickBuf(cId) + (size_t)bh * 65536;

    int tid = threadIdx.x, lane = tid & 31, w = tid >> 5;
    int wm = w & 3, wn = w >> 2;
    int lr = lane & 15, lh = lane >> 4;

    float acc[2][4][4];
#pragma unroll
    for (int i = 0; i < 2; i++)
#pragma unroll
        for (int j = 0; j < 4; j++)
#pragma unroll
            for (int c = 0; c < 4; c++) acc[i][j][c] = 0.f;

    for (int ch = 0; ch < 8; ch++) {
        if (ch) __syncthreads();
#pragma unroll
        for (int i = 0; i < 4; i++) {
            int idx = tid + i * 256;
            int r = idx >> 3, c4 = (idx & 7) * 4;
            float4 v = *(const float4*)&A[(size_t)(mBase + r) * 256 + ch * 32 + c4];
            __nv_bfloat16 h0 = __float2bfloat16(v.x), h1 = __float2bfloat16(v.y);
            __nv_bfloat16 h2 = __float2bfloat16(v.z), h3 = __float2bfloat16(v.w);
            sAh[r][c4 + 0] = h0; sAh[r][c4 + 1] = h1;
            sAh[r][c4 + 2] = h2; sAh[r][c4 + 3] = h3;
            sAl[r][c4 + 0] = __float2bfloat16(v.x - __bfloat162float(h0));
            sAl[r][c4 + 1] = __float2bfloat16(v.y - __bfloat162float(h1));
            sAl[r][c4 + 2] = __float2bfloat16(v.z - __bfloat162float(h2));
            sAl[r][c4 + 3] = __float2bfloat16(v.w - __bfloat162float(h3));
        }
#pragma unroll
        for (int kl = 0; kl < 4; kl++) {
            int gk = ch * 32 + w * 4 + kl;
#pragma unroll
            for (int nh = 0; nh < 2; nh++) {
                int n = nh * 32 + lane;
                float v = B[(size_t)gk * 256 + nBase + n];
                v = sgn * v + ((gk == nBase + n) ? beta : 0.f);
                __nv_bfloat16 h = __float2bfloat16(v);
                sBh[n][w * 4 + kl] = h;
                sBl[n][w * 4 + kl] = __float2bfloat16(v - __bfloat162float(h));
            }
        }
        __syncthreads();
#pragma unroll
        for (int ks = 0; ks < 2; ks++) {
            int kc = ks * 16 + lh * 8;
            unsigned ah[2][4], al[2][4];
#pragma unroll
            for (int mi = 0; mi < 2; mi++) {
                int rowA = wm * 32 + mi * 16 + lr;
                ldm4(ah[mi], smem_u32(&sAh[rowA][kc]));
                ldm4(al[mi], smem_u32(&sAl[rowA][kc]));
            }
#pragma unroll
            for (int nt = 0; nt < 2; nt++) {
                int rowB = wn * 32 + nt * 16 + lr;
                unsigned bhf[4], blf[4];
                ldm4(bhf, smem_u32(&sBh[rowB][kc]));
                ldm4(blf, smem_u32(&sBl[rowB][kc]));
#pragma unroll
                for (int mi = 0; mi < 2; mi++) {
#pragma unroll
                    for (int ns = 0; ns < 2; ns++) {
                        float* cc = acc[mi][nt * 2 + ns];
                        mma16816(cc, ah[mi], bhf[ns], bhf[ns + 2]);
                        mma16816(cc, ah[mi], blf[ns], blf[ns + 2]);
                        mma16816(cc, al[mi], bhf[ns], bhf[ns + 2]);
                    }
                }
            }
        }
    }
#pragma unroll
    for (int mi = 0; mi < 2; mi++) {
#pragma unroll
        for (int jn = 0; jn < 4; jn++) {
            int gc = nBase + wn * 32 + jn * 8 + (lane & 3) * 2;
#pragma unroll
            for (int half = 0; half < 2; half++) {
                int gr = mBase + wm * 32 + mi * 16 + (lane >> 2) + half * 8;
                float2 o = make_float2(acc[mi][jn][half * 2] * alpha,
                                       acc[mi][jn][half * 2 + 1] * alpha);
                *(float2*)&C[(size_t)gr * 256 + gc] = o;
            }
        }
    }
}

// ================= batched per-bh GEMM (scalar, kept for W3) =================
__global__ __launch_bounds__(256) void gemm_bh_kernel(int cId, int aId, int bId, int Nn,
                                                      float beta, float sgn, float alpha) {
    int bh = blockIdx.z, mt = blockIdx.y, nt = blockIdx.x;
    const float* A  = pickBuf(aId) + (size_t)bh * 65536;
    const float* Bp = pickBuf(bId) + (size_t)bh * 256 * Nn;
    float*       C  = pickBuf(cId) + (size_t)bh * 256 * Nn;
    __shared__ float As[16][64];
    __shared__ float Bs[16][64];
    int tid = threadIdx.x;
    int ar = tid >> 2, ac = (tid & 3) * 4;
    int br = tid >> 4, bc = (tid & 15) * 4;
    int ty = tid >> 4, tx = tid & 15;
    float acc[4][4];
#pragma unroll
    for (int i = 0; i < 4; i++)
#pragma unroll
        for (int j = 0; j < 4; j++) acc[i][j] = 0.f;

    for (int k0 = 0; k0 < 256; k0 += 16) {
        float4 av = *(const float4*)&A[(size_t)(mt * 64 + ar) * 256 + k0 + ac];
        As[ac + 0][ar] = av.x; As[ac + 1][ar] = av.y;
        As[ac + 2][ar] = av.z; As[ac + 3][ar] = av.w;
        int gk = k0 + br;
        int gc = nt * 64 + bc;
        float4 bv = *(const float4*)&Bp[(size_t)gk * Nn + gc];
        bv.x = sgn * bv.x + (gk == gc + 0 ? beta : 0.f);
        bv.y = sgn * bv.y + (gk == gc + 1 ? beta : 0.f);
        bv.z = sgn * bv.z + (gk == gc + 2 ? beta : 0.f);
        bv.w = sgn * bv.w + (gk == gc + 3 ? beta : 0.f);
        *(float4*)&Bs[br][bc] = bv;
        __syncthreads();
#pragma unroll
        for (int kk = 0; kk < 16; kk++) {
            float4 a4 = *(const float4*)&As[kk][ty * 4];
            float4 b4 = *(const float4*)&Bs[kk][tx * 4];
            acc[0][0] += a4.x * b4.x; acc[0][1] += a4.x * b4.y; acc[0][2] += a4.x * b4.z; acc[0][3] += a4.x * b4.w;
            acc[1][0] += a4.y * b4.x; acc[1][1] += a4.y * b4.y; acc[1][2] += a4.y * b4.z; acc[1][3] += a4.y * b4.w;
            acc[2][0] += a4.z * b4.x; acc[2][1] += a4.z * b4.y; acc[2][2] += a4.z * b4.z; acc[2][3] += a4.z * b4.w;
            acc[3][0] += a4.w * b4.x; acc[3][1] += a4.w * b4.y; acc[3][2] += a4.w * b4.z; acc[3][3] += a4.w * b4.w;
        }
        __syncthreads();
    }
#pragma unroll
    for (int i = 0; i < 4; i++) {
        float4 o = make_float4(acc[i][0] * alpha, acc[i][1] * alpha,
                               acc[i][2] * alpha, acc[i][3] * alpha);
        *(float4*)&C[(size_t)(mt * 64 + ty * 4 + i) * Nn + nt * 64 + tx * 4] = o;
    }
}

// ================= flash W2 on tensor cores =================
// W2 = softmax(q_l k^T) @ v, split-K over 4 sequence chunks of 2048.
// grid (4 chunks, 2 mblk, 16 bh), 256 threads (8 warps x 16 landmark rows).
__global__ __launch_bounds__(256) void flash_w2_mma() {
    __shared__ __align__(16) __half sql[128][72];
    __shared__ __align__(16) __half sk[64][72];
    __shared__ __align__(16) __half svT[64][72];

    int tid = threadIdx.x, lane = tid & 31, w = tid >> 5;
    int chunk = blockIdx.x, mblk = blockIdx.y, bh = blockIdx.z;
    int lr = lane & 15, lh = lane >> 4;

    const __half* qlh = g_qlh + (size_t)(bh * MLM + mblk * 128) * 64;
#pragma unroll
    for (int i = 0; i < 4; i++) {
        int idx = tid + i * 256;
        int r = idx >> 3, c = (idx & 7) * 8;
        *(uint4*)&sql[r][c] = *(const uint4*)&qlh[(size_t)r * 64 + c];
    }
    __syncthreads();
    unsigned qa[4][4];
#pragma unroll
    for (int ks = 0; ks < 4; ks++)
        ldm4(qa[ks], smem_u32(&sql[w * 16 + lr][ks * 16 + lh * 8]));

    float outacc[8][4];
#pragma unroll
    for (int i = 0; i < 8; i++)
#pragma unroll
        for (int c = 0; c < 4; c++) outacc[i][c] = 0.f;
    float rsA = 0.f, rsB = 0.f;

    const __half* kb = g_kh + (size_t)bh * NSEQ * 64;
    const __half* vb = g_vh + (size_t)bh * NSEQ * 64;

    for (int it = 0; it < 32; it++) {
        int s0 = chunk * 2048 + it * 64;
        __syncthreads();
#pragma unroll
        for (int i = 0; i < 2; i++) {
            int idx = tid + i * 256;
            int r = idx >> 3, c = (idx & 7) * 8;
            *(uint4*)&sk[r][c] = *(const uint4*)&kb[(size_t)(s0 + r) * 64 + c];
            uint4 vv = *(const uint4*)&vb[(size_t)(s0 + r) * 64 + c];
            __half vh[8];
            *(uint4*)vh = vv;
#pragma unroll
            for (int j = 0; j < 8; j++) svT[c + j][r] = vh[j];
        }
        __syncthreads();
        float sf[8][4];
#pragma unroll
        for (int i = 0; i < 8; i++)
#pragma unroll
            for (int c = 0; c < 4; c++) sf[i][c] = 0.f;
#pragma unroll
        for (int ks = 0; ks < 4; ks++) {
#pragma unroll
            for (int nf4 = 0; nf4 < 4; nf4++) {
                unsigned bbf[4];
                ldm4(bbf, smem_u32(&sk[nf4 * 16 + lr][ks * 16 + lh * 8]));
                mmaf16(sf[nf4 * 2], qa[ks], bbf[0], bbf[2]);
                mmaf16(sf[nf4 * 2 + 1], qa[ks], bbf[1], bbf[3]);
            }
        }
#pragma unroll
        for (int nf = 0; nf < 8; nf++) {
            sf[nf][0] = fexp(sf[nf][0]); sf[nf][1] = fexp(sf[nf][1]);
            sf[nf][2] = fexp(sf[nf][2]); sf[nf][3] = fexp(sf[nf][3]);
            rsA += sf[nf][0] + sf[nf][1];
            rsB += sf[nf][2] + sf[nf][3];
        }
#pragma unroll
        for (int kk = 0; kk < 4; kk++) {
            unsigned pa[4];
            pa[0] = packh2(sf[2 * kk][0], sf[2 * kk][1]);
            pa[1] = packh2(sf[2 * kk][2], sf[2 * kk][3]);
            pa[2] = packh2(sf[2 * kk + 1][0], sf[2 * kk + 1][1]);
            pa[3] = packh2(sf[2 * kk + 1][2], sf[2 * kk + 1][3]);
#pragma unroll
            for (int nf4 = 0; nf4 < 4; nf4++) {
                unsigned bbf[4];
                ldm4(bbf, smem_u32(&svT[nf4 * 16 + lr][kk * 16 + lh * 8]));
                mmaf16(outacc[nf4 * 2], pa, bbf[0], bbf[2]);
                mmaf16(outacc[nf4 * 2 + 1], pa, bbf[1], bbf[3]);
            }
        }
    }
    rsA += __shfl_xor_sync(0xffffffffu, rsA, 1);
    rsA += __shfl_xor_sync(0xffffffffu, rsA, 2);
    rsB += __shfl_xor_sync(0xffffffffu, rsB, 1);
    rsB += __shfl_xor_sync(0xffffffffu, rsB, 2);

    int rA = mblk * 128 + w * 16 + (lane >> 2);
    int rB = rA + 8;
    float* wpA = g_Wpart + (size_t)((bh * 4 + chunk) * MLM + rA) * 64;
    float* wpB = g_Wpart + (size_t)((bh * 4 + chunk) * MLM + rB) * 64;
#pragma unroll
    for (int nf = 0; nf < 8; nf++) {
        int d = nf * 8 + (lane & 3) * 2;
        *(float2*)&wpA[d] = make_float2(outacc[nf][0], outacc[nf][1]);
        *(float2*)&wpB[d] = make_float2(outacc[nf][2], outacc[nf][3]);
    }
    if ((lane & 3) == 0) {
        g_Spart[(bh * 4 + chunk) * MLM + rA] = rsA;
        g_Spart[(bh * 4 + chunk) * MLM + rB] = rsB;
    }
}

__global__ void combine_w2_kernel() {
    int idx = blockIdx.x * 256 + threadIdx.x;
    int bh = idx >> 14;
    int m = (idx >> 6) & 255;
    int d = idx & 63;
    float num = 0.f, den = 0.f;
#pragma unroll
    for (int c = 0; c < 4; c++) {
        num += g_Wpart[(size_t)((bh * 4 + c) * MLM + m) * 64 + d];
        den += g_Spart[(bh * 4 + c) * MLM + m];
    }
    g_W2[(bh * MLM + m) * 64 + d] = num / den;
}

// ================= attn1 + conv on tensor cores =================
// out_pre = softmax(q kl^T) @ W3 + conv33(v). grid (64 ntiles, 16 bh).
__global__ __launch_bounds__(256) void attn1_mma(const float* __restrict__ convw) {
    extern __shared__ char smx[];
    __half (*sq)[72]  = (__half(*)[72])(smx);
    __half (*skl)[72] = (__half(*)[72])(smx + 18432);
    __half (*swT)[72] = (__half(*)[72])(smx + 27648);
    __half (*sv)[72]  = (__half(*)[72])(smx + 36864);
    float* cw = (float*)(smx + 59904);

    int tid = threadIdx.x, lane = tid & 31, w = tid >> 5;
    int ntile = blockIdx.x, bh = blockIdx.y;
    int h = bh & 7, bb2 = bh >> 3;
    int n0 = ntile * 128;
    int lr = lane & 15, lh = lane >> 4;

    if (tid < KSZ) cw[tid] = convw[h * KSZ + tid];

    const __half* qb = g_qh + ((size_t)bh * NSEQ + n0) * 64;
#pragma unroll
    for (int i = 0; i < 4; i++) {
        int idx = tid + i * 256;
        int r = idx >> 3, c = (idx & 7) * 8;
        *(uint4*)&sq[r][c] = *(const uint4*)&qb[(size_t)r * 64 + c];
    }
    const __half* vb2 = g_vh + (size_t)bh * NSEQ * 64;
#pragma unroll
    for (int i = 0; i < 5; i++) {
        int idx = tid + i * 256;
        int r = idx >> 3, c = (idx & 7) * 8;
        int gr = n0 - 16 + r;
        uint4 z = make_uint4(0u, 0u, 0u, 0u);
        if (gr >= 0 && gr < NSEQ) z = *(const uint4*)&vb2[(size_t)gr * 64 + c];
        *(uint4*)&sv[r][c] = z;
    }
    __syncthreads();

    unsigned qa[4][4];
#pragma unroll
    for (int ks = 0; ks < 4; ks++)
        ldm4(qa[ks], smem_u32(&sq[w * 16 + lr][ks * 16 + lh * 8]));

    float outacc[8][4];
#pragma unroll
    for (int i = 0; i < 8; i++)
#pragma unroll
        for (int c = 0; c < 4; c++) outacc[i][c] = 0.f;
    float rsA = 0.f, rsB = 0.f;

    const __half* klb = g_klh + (size_t)bh * MLM * 64;
    const __half* w3tb = g_W3T + (size_t)bh * 64 * 256;

    for (int lc = 0; lc < 4; lc++) {
        __syncthreads();
#pragma unroll
        for (int i = 0; i < 2; i++) {
            int idx = tid + i * 256;
            int r = idx >> 3, c = (idx & 7) * 8;
            *(uint4*)&skl[r][c] = *(const uint4*)&klb[(size_t)(lc * 64 + r) * 64 + c];
            *(uint4*)&swT[r][c] = *(const uint4*)&w3tb[(size_t)r * 256 + lc * 64 + c];
        }
        __syncthreads();
        float sf[8][4];
#pragma unroll
        for (int i = 0; i < 8; i++)
#pragma unroll
            for (int c = 0; c < 4; c++) sf[i][c] = 0.f;
#pragma unroll
        for (int ks = 0; ks < 4; ks++) {
#pragma unroll
            for (int nf4 = 0; nf4 < 4; nf4++) {
                unsigned bbf[4];
                ldm4(bbf, smem_u32(&skl[nf4 * 16 + lr][ks * 16 + lh * 8]));
                mmaf16(sf[nf4 * 2], qa[ks], bbf[0], bbf[2]);
                mmaf16(sf[nf4 * 2 + 1], qa[ks], bbf[1], bbf[3]);
            }
        }
#pragma unroll
        for (int nf = 0; nf < 8; nf++) {
            sf[nf][0] = fexp(sf[nf][0]); sf[nf][1] = fexp(sf[nf][1]);
            sf[nf][2] = fexp(sf[nf][2]); sf[nf][3] = fexp(sf[nf][3]);
            rsA += sf[nf][0] + sf[nf][1];
            rsB += sf[nf][2] + sf[nf][3];
        }
#pragma unroll
        for (int kk = 0; kk < 4; kk++) {
            unsigned pa[4];
            pa[0] = packh2(sf[2 * kk][0], sf[2 * kk][1]);
            pa[1] = packh2(sf[2 * kk][2], sf[2 * kk][3]);
            pa[2] = packh2(sf[2 * kk + 1][0], sf[2 * kk + 1][1]);
            pa[3] = packh2(sf[2 * kk + 1][2], sf[2 * kk + 1][3]);
#pragma unroll
            for (int nf4 = 0; nf4 < 4; nf4++) {
                unsigned bbf[4];
                ldm4(bbf, smem_u32(&swT[nf4 * 16 + lr][kk * 16 + lh * 8]));
                mmaf16(outacc[nf4 * 2], pa, bbf[0], bbf[2]);
                mmaf16(outacc[nf4 * 2 + 1], pa, bbf[1], bbf[3]);
            }
        }
    }
    rsA += __shfl_xor_sync(0xffffffffu, rsA, 1);
    rsA += __shfl_xor_sync(0xffffffffu, rsA, 2);
    rsB += __shfl_xor_sync(0xffffffffu, rsB, 1);
    rsB += __shfl_xor_sync(0xffffffffu, rsB, 2);
    float invA = 1.f / rsA, invB = 1.f / rsB;

    int lrA = w * 16 + (lane >> 2);
#pragma unroll
    for (int nf = 0; nf < 8; nf++) {
        int d = nf * 8 + (lane & 3) * 2;
        float a0 = 0.f, a1 = 0.f, b0 = 0.f, b1 = 0.f;
#pragma unroll
        for (int t = 0; t < KSZ; t++) {
            float wv = cw[t];
            float2 fA = __half22float2(*(__half2*)&sv[lrA + t][d]);
            float2 fB = __half22float2(*(__half2*)&sv[lrA + 8 + t][d]);
            a0 = fmaf(wv, fA.x, a0); a1 = fmaf(wv, fA.y, a1);
            b0 = fmaf(wv, fB.x, b0); b1 = fmaf(wv, fB.y, b1);
        }
        outacc[nf][0] = outacc[nf][0] * invA + a0;
        outacc[nf][1] = outacc[nf][1] * invA + a1;
        outacc[nf][2] = outacc[nf][2] * invB + b0;
        outacc[nf][3] = outacc[nf][3] * invB + b1;
    }

    int nA = n0 + lrA, nB = nA + 8;
    float* oA = g_outpre + (size_t)(bb2 * NSEQ + nA) * 512 + h * 64;
    float* oB = g_outpre + (size_t)(bb2 * NSEQ + nB) * 512 + h * 64;
#pragma unroll
    for (int nf = 0; nf < 8; nf++) {
        int d = nf * 8 + (lane & 3) * 2;
        *(float2*)&oA[d] = make_float2(outacc[nf][0], outacc[nf][1]);
        *(float2*)&oB[d] = make_float2(outacc[nf][2], outacc[nf][3]);
    }
}

// ================= host launcher =================
extern "C" void kernel_launch(void* const* d_in, const int* in_sizes, int n_in,
                              void* d_out, int out_size) {
    const float* x     = (const float*)d_in[0];
    const float* ln_g  = (const float*)d_in[1];
    const float* ln_b  = (const float*)d_in[2];
    const float* W_qkv = (const float*)d_in[3];
    const float* W_out = (const float*)d_in[4];
    const float* b_out = (const float*)d_in[5];
    const float* convw = (const float*)d_in[6];
    float* out = (float*)d_out;

    cudaFuncSetAttribute(attn1_mma, cudaFuncAttributeMaxDynamicSharedMemorySize, 60416);

    __nv_bfloat16 *bqh, *bql, *boh, *bol;
    cudaGetSymbolAddress((void**)&bqh, g_Bqh);
    cudaGetSymbolAddress((void**)&bql, g_Bql);
    cudaGetSymbolAddress((void**)&boh, g_Boh);
    cudaGetSymbolAddress((void**)&bol, g_Bol);
    float* xnp;
    cudaGetSymbolAddress((void**)&xnp, g_xn);
    float* opp;
    cudaGetSymbolAddress((void**)&opp, g_outpre);

    reset_kernel<<<1, 1>>>();
    ln_kernel<<<Bb * NSEQ, 128>>>(x, ln_g, ln_b);

    convA_kernel<<<8192, 256>>>(xnp);
    convW_kernel<<<dim3(48, 16), 1024>>>(W_qkv, 1536, bqh, bql);
    convW_kernel<<<dim3(16, 16), 1024>>>(W_out, 512, boh, bol);

    gemm_mma_kernel<<<dim3(12, 128), 256>>>(bqh, bql, 0, nullptr, nullptr);

    landmark_kernel<<<2048, 256>>>();
    attn2_kernel<<<16, 256>>>();
    colmax_kernel<<<16, 256>>>();
    z0_kernel<<<4096, 256>>>();

    int zc = 4, zn = 5;  // Za, Zb
    for (int it = 0; it < 6; it++) {
        gemm_pinv_mma<<<dim3(4, 2, 16), 256>>>(1, 0, zc, 0.f, 1.f, 1.f);
        gemm_pinv_mma<<<dim3(4, 2, 16), 256>>>(2, 1, 1, 7.f, -1.f, 1.f);
        gemm_pinv_mma<<<dim3(4, 2, 16), 256>>>(3, 1, 2, 15.f, -1.f, 1.f);
        gemm_pinv_mma<<<dim3(4, 2, 16), 256>>>(zn, zc, 3, 13.f, -1.f, 0.25f);
        int t = zc; zc = zn; zn = t;
    }

    flash_w2_mma<<<dim3(4, 2, 16), 256>>>();
    combine_w2_kernel<<<1024, 256>>>();
    gemm_bh_kernel<<<dim3(1, 4, 16), 256>>>(7, zc, 6, 64, 0.f, 1.f, 1.f);  // W3 = Z @ W2
    w3t_kernel<<<1024, 256>>>();
    attn1_mma<<<dim3(64, 16), 256, 60416>>>(convw);

    convA_kernel<<<8192, 256>>>(opp);
    gemm_mma_kernel<<<dim3(4, 128), 256>>>(boh, bol, 1, b_out, out);
}

// round 7
// speedup vs baseline: 2.4905x; 1.0387x over previous
#include <cuda_runtime.h>
#include <cuda_bf16.h>
#include <cuda_fp16.h>

#define Bb    2
#define NSEQ  8192
#define DIMV  512
#define NH    8
#define BHn   16
#define DHd   64
#define MLM   256
#define LGRP  32
#define KSZ   33
#define PADc  16
#define SCALE 0.125f

// ================= static device scratch =================
__device__ float g_xn[(size_t)Bb * NSEQ * DIMV];
__device__ float g_q[(size_t)BHn * NSEQ * DHd];
__device__ float g_k[(size_t)BHn * NSEQ * DHd];
__device__ float g_ql[BHn * MLM * DHd];
__device__ float g_kl[BHn * MLM * DHd];
__device__ float g_attn2[BHn * MLM * MLM];
__device__ float g_Y[BHn * MLM * MLM];
__device__ float g_P[BHn * MLM * MLM];
__device__ float g_Qm[BHn * MLM * MLM];
__device__ float g_Za[BHn * MLM * MLM];
__device__ float g_Zb[BHn * MLM * MLM];
__device__ float g_W2[BHn * MLM * DHd];
__device__ float g_W3[BHn * MLM * DHd];
__device__ float g_Wpart[(size_t)BHn * 4 * MLM * DHd];
__device__ float g_Spart[BHn * 4 * MLM];
__device__ float g_outpre[(size_t)Bb * NSEQ * DIMV];
__device__ int   g_maxc_bits;

// bf16 hi/lo buffers for dense tensor-core GEMMs
__device__ __nv_bfloat16 g_Ahi[(size_t)Bb * NSEQ * DIMV];
__device__ __nv_bfloat16 g_Alo[(size_t)Bb * NSEQ * DIMV];
__device__ __nv_bfloat16 g_Bqh[1536 * 512];
__device__ __nv_bfloat16 g_Bql[1536 * 512];
__device__ __nv_bfloat16 g_Boh[512 * 512];
__device__ __nv_bfloat16 g_Bol[512 * 512];

// fp16 buffers for attention mma kernels
__device__ __half g_qh[(size_t)BHn * NSEQ * DHd];
__device__ __half g_kh[(size_t)BHn * NSEQ * DHd];
__device__ __half g_vh[(size_t)BHn * NSEQ * DHd];
__device__ __half g_qlh[BHn * MLM * DHd];
__device__ __half g_klh[BHn * MLM * DHd];
__device__ __half g_W3T[BHn * DHd * MLM];

__global__ void reset_kernel() { g_maxc_bits = 0; }

// ================= mma.sync helpers =================
__device__ __forceinline__ unsigned smem_u32(const void* p) {
    unsigned a;
    asm("{ .reg .u64 t; cvta.to.shared.u64 t, %1; cvt.u32.u64 %0, t; }" : "=r"(a) : "l"(p));
    return a;
}
__device__ __forceinline__ void ldm4(unsigned* r, unsigned addr) {
    asm volatile("ldmatrix.sync.aligned.m8n8.x4.shared.b16 {%0,%1,%2,%3}, [%4];"
        : "=r"(r[0]), "=r"(r[1]), "=r"(r[2]), "=r"(r[3]) : "r"(addr));
}
__device__ __forceinline__ void mma16816(float* c, const unsigned* a, unsigned b0, unsigned b1) {
    asm volatile("mma.sync.aligned.m16n8k16.row.col.f32.bf16.bf16.f32 "
        "{%0,%1,%2,%3}, {%4,%5,%6,%7}, {%8,%9}, {%0,%1,%2,%3};"
        : "+f"(c[0]), "+f"(c[1]), "+f"(c[2]), "+f"(c[3])
        : "r"(a[0]), "r"(a[1]), "r"(a[2]), "r"(a[3]), "r"(b0), "r"(b1));
}
__device__ __forceinline__ void mmaf16(float* c, const unsigned* a, unsigned b0, unsigned b1) {
    asm volatile("mma.sync.aligned.m16n8k16.row.col.f32.f16.f16.f32 "
        "{%0,%1,%2,%3}, {%4,%5,%6,%7}, {%8,%9}, {%0,%1,%2,%3};"
        : "+f"(c[0]), "+f"(c[1]), "+f"(c[2]), "+f"(c[3])
        : "r"(a[0]), "r"(a[1]), "r"(a[2]), "r"(a[3]), "r"(b0), "r"(b1));
}
__device__ __forceinline__ void cpasync16(unsigned dst, const void* src) {
    asm volatile("cp.async.cg.shared.global [%0], [%1], 16;" :: "r"(dst), "l"(src));
}
#define CP_COMMIT() asm volatile("cp.async.commit_group;" ::: "memory")
__device__ __forceinline__ unsigned packh2(float a, float b) {
    __half2 h = __floats2half2_rn(a, b);
    return *(unsigned*)&h;
}
// fast exp on FMA pipe (|x| small; poly rel err ~2.4e-6)
__device__ __forceinline__ float fexp(float x) {
    float t = x * 1.44269504f;
    float r = rintf(t);
    float f = t - r;
    float p = 1.33336e-3f;
    p = fmaf(p, f, 9.61813e-3f);
    p = fmaf(p, f, 5.55041e-2f);
    p = fmaf(p, f, 2.40226507e-1f);
    p = fmaf(p, f, 6.93147181e-1f);
    p = fmaf(p, f, 1.0f);
    int e = (int)r;
    return p * __int_as_float((e + 127) << 23);
}

// ================= layernorm =================
__global__ __launch_bounds__(128) void ln_kernel(const float* __restrict__ x,
                                                 const float* __restrict__ gam,
                                                 const float* __restrict__ bet) {
    int row = blockIdx.x;
    int tid = threadIdx.x;
    float4 v = ((const float4*)x)[(size_t)row * 128 + tid];
    float s1 = v.x + v.y + v.z + v.w;
    float s2 = v.x * v.x + v.y * v.y + v.z * v.z + v.w * v.w;
#pragma unroll
    for (int o = 16; o; o >>= 1) {
        s1 += __shfl_xor_sync(0xffffffffu, s1, o);
        s2 += __shfl_xor_sync(0xffffffffu, s2, o);
    }
    __shared__ float r1[4], r2[4];
    int w = tid >> 5;
    if ((tid & 31) == 0) { r1[w] = s1; r2[w] = s2; }
    __syncthreads();
    s1 = r1[0] + r1[1] + r1[2] + r1[3];
    s2 = r2[0] + r2[1] + r2[2] + r2[3];
    float mean = s1 * (1.f / 512.f);
    float var  = s2 * (1.f / 512.f) - mean * mean;
    float rstd = rsqrtf(var + 1e-5f);
    float4 g4 = ((const float4*)gam)[tid];
    float4 b4 = ((const float4*)bet)[tid];
    float4 o;
    o.x = (v.x - mean) * rstd * g4.x + b4.x;
    o.y = (v.y - mean) * rstd * g4.y + b4.y;
    o.z = (v.z - mean) * rstd * g4.z + b4.z;
    o.w = (v.w - mean) * rstd * g4.w + b4.w;
    ((float4*)g_xn)[(size_t)row * 128 + tid] = o;
}

// ================= fp32 -> bf16 hi/lo converters =================
__global__ __launch_bounds__(256) void convA_kernel(const float* __restrict__ src) {
    size_t i4 = ((size_t)blockIdx.x * 256 + threadIdx.x) * 4;
    float4 v = *(const float4*)(src + i4);
    __nv_bfloat16 h0 = __float2bfloat16(v.x), h1 = __float2bfloat16(v.y);
    __nv_bfloat16 h2 = __float2bfloat16(v.z), h3 = __float2bfloat16(v.w);
    __nv_bfloat16 l0 = __float2bfloat16(v.x - __bfloat162float(h0));
    __nv_bfloat16 l1 = __float2bfloat16(v.y - __bfloat162float(h1));
    __nv_bfloat16 l2 = __float2bfloat16(v.z - __bfloat162float(h2));
    __nv_bfloat16 l3 = __float2bfloat16(v.w - __bfloat162float(h3));
    __nv_bfloat162* ph = (__nv_bfloat162*)(g_Ahi + i4);
    __nv_bfloat162* pl = (__nv_bfloat162*)(g_Alo + i4);
    ph[0] = __nv_bfloat162(h0, h1); ph[1] = __nv_bfloat162(h2, h3);
    pl[0] = __nv_bfloat162(l0, l1); pl[1] = __nv_bfloat162(l2, l3);
}

__global__ __launch_bounds__(1024) void convW_kernel(const float* __restrict__ W, int N,
                                                     __nv_bfloat16* __restrict__ BThi,
                                                     __nv_bfloat16* __restrict__ BTlo) {
    __shared__ float sh[32][33];
    int n0 = blockIdx.x * 32, k0 = blockIdx.y * 32;
    int tx = threadIdx.x & 31, ty = threadIdx.x >> 5;
    sh[ty][tx] = W[(size_t)(k0 + ty) * N + n0 + tx];
    __syncthreads();
    float x = sh[tx][ty];
    __nv_bfloat16 h = __float2bfloat16(x);
    __nv_bfloat16 l = __float2bfloat16(x - __bfloat162float(h));
    BThi[(size_t)(n0 + ty) * 512 + k0 + tx] = h;
    BTlo[(size_t)(n0 + ty) * 512 + k0 + tx] = l;
}

// W3 -> W3T fp16 [bh][d][m]
__global__ void w3t_kernel() {
    int idx = blockIdx.x * 256 + threadIdx.x;
    int bh = idx >> 14;
    int m = (idx >> 6) & 255;
    int d = idx & 63;
    float v = g_W3[(bh * 256 + m) * 64 + d];
    g_W3T[((size_t)bh * 64 + d) * 256 + m] = __float2half(v);
}

// ================= mma.sync bf16 split GEMM (dense 512-K, cp.async double-buffered) =================
// dynamic smem: 2 stages x 40960B; per stage Ah@0, Al@10240, Bh@20480, Bl@30720 (row stride 80B)
__global__ __launch_bounds__(256) void gemm_mma_kernel(
    const __nv_bfloat16* __restrict__ BThi, const __nv_bfloat16* __restrict__ BTlo,
    int mode, const float* __restrict__ bout, float* __restrict__ outp) {
    extern __shared__ char smdyn[];
    unsigned sbase = smem_u32(smdyn);
    int tid = threadIdx.x, lane = tid & 31, wid = tid >> 5;
    int wm = wid & 3, wn = wid >> 2;
    int mBase = blockIdx.y * 128, nBase = blockIdx.x * 128;
    int lr = lane & 15, lh = lane >> 4;

    const __nv_bfloat16* gsrc[4];
    gsrc[0] = g_Ahi + (size_t)mBase * 512;
    gsrc[1] = g_Alo + (size_t)mBase * 512;
    gsrc[2] = BThi + (size_t)nBase * 512;
    gsrc[3] = BTlo + (size_t)nBase * 512;

    float acc[2][8][4];
#pragma unroll
    for (int i = 0; i < 2; i++)
#pragma unroll
        for (int j = 0; j < 8; j++)
#pragma unroll
            for (int c = 0; c < 4; c++) acc[i][j][c] = 0.f;

    int r_ld0 = tid >> 2, q_ld = tid & 3;
    unsigned so0 = (unsigned)r_ld0 * 80u + q_ld * 16u;
    unsigned so1 = (unsigned)(r_ld0 + 64) * 80u + q_ld * 16u;

    // prologue: chunk 0 -> stage 0
    {
        size_t go0 = (size_t)r_ld0 * 512 + q_ld * 8;
        size_t go1 = (size_t)(r_ld0 + 64) * 512 + q_ld * 8;
#pragma unroll
        for (int a = 0; a < 4; a++) {
            cpasync16(sbase + a * 10240u + so0, gsrc[a] + go0);
            cpasync16(sbase + a * 10240u + so1, gsrc[a] + go1);
        }
        CP_COMMIT();
    }

    for (int ch = 0; ch < 16; ch++) {
        unsigned st = (unsigned)(ch & 1) * 40960u;
        if (ch + 1 < 16) {
            unsigned stn = (unsigned)((ch + 1) & 1) * 40960u;
            size_t go0 = (size_t)r_ld0 * 512 + (ch + 1) * 32 + q_ld * 8;
            size_t go1 = (size_t)(r_ld0 + 64) * 512 + (ch + 1) * 32 + q_ld * 8;
#pragma unroll
            for (int a = 0; a < 4; a++) {
                cpasync16(sbase + stn + a * 10240u + so0, gsrc[a] + go0);
                cpasync16(sbase + stn + a * 10240u + so1, gsrc[a] + go1);
            }
            CP_COMMIT();
            asm volatile("cp.async.wait_group 1;" ::: "memory");
        } else {
            asm volatile("cp.async.wait_group 0;" ::: "memory");
        }
        __syncthreads();

        unsigned aAh = sbase + st;
        unsigned aAl = aAh + 10240u;
        unsigned aBh = aAh + 20480u;
        unsigned aBl = aAh + 30720u;
#pragma unroll
        for (int ks = 0; ks < 2; ks++) {
            unsigned kc2 = (unsigned)(ks * 16 + lh * 8) * 2u;
            unsigned ah[2][4], al[2][4];
#pragma unroll
            for (int mi = 0; mi < 2; mi++) {
                unsigned rowA = (unsigned)(wm * 32 + mi * 16 + lr) * 80u;
                ldm4(ah[mi], aAh + rowA + kc2);
                ldm4(al[mi], aAl + rowA + kc2);
            }
#pragma unroll
            for (int nt = 0; nt < 4; nt++) {
                unsigned rowB = (unsigned)(wn * 64 + nt * 16 + lr) * 80u;
                unsigned bh[4], bl[4];
                ldm4(bh, aBh + rowB + kc2);
                ldm4(bl, aBl + rowB + kc2);
#pragma unroll
                for (int mi = 0; mi < 2; mi++) {
#pragma unroll
                    for (int ns = 0; ns < 2; ns++) {
                        float* cc = acc[mi][nt * 2 + ns];
                        mma16816(cc, ah[mi], bh[ns], bh[ns + 2]);
                        mma16816(cc, ah[mi], bl[ns], bl[ns + 2]);
                        mma16816(cc, al[mi], bh[ns], bh[ns + 2]);
                    }
                }
            }
        }
        __syncthreads();
    }

    int r0 = mBase + wm * 32 + (lane >> 2);
    if (mode == 0) {
        int sec = nBase >> 9;
        float sc = (sec == 0) ? SCALE : 1.f;
        float* dst = (sec == 0) ? g_q : g_k;
        __half* hdst = (sec == 0) ? g_qh : ((sec == 1) ? g_kh : g_vh);
        int h = ((nBase + wn * 64) >> 6) & 7;
#pragma unroll
        for (int mi = 0; mi < 2; mi++) {
#pragma unroll
            for (int jn = 0; jn < 8; jn++) {
                int d = jn * 8 + (lane & 3) * 2;
#pragma unroll
                for (int half = 0; half < 2; half++) {
                    int gr = r0 + mi * 16 + half * 8;
                    int bb = gr >> 13, n = gr & 8191;
                    float2 o = make_float2(acc[mi][jn][half * 2] * sc,
                                           acc[mi][jn][half * 2 + 1] * sc);
                    size_t off = ((size_t)(bb * 8 + h) * NSEQ + n) * 64 + d;
                    if (sec < 2) *(float2*)&dst[off] = o;  // fp32 q/k for landmarks
                    *(__half2*)&hdst[off] = __floats2half2_rn(o.x, o.y);
                }
            }
        }
    } else {
#pragma unroll
        for (int mi = 0; mi < 2; mi++) {
#pragma unroll
            for (int jn = 0; jn < 8; jn++) {
                int gc = nBase + wn * 64 + jn * 8 + (lane & 3) * 2;
#pragma unroll
                for (int half = 0; half < 2; half++) {
                    int gr = r0 + mi * 16 + half * 8;
                    float2 bo = *(const float2*)&bout[gc];
                    float2 xv = *(const float2*)&g_xn[(size_t)gr * 512 + gc];
                    float2 o = make_float2(acc[mi][jn][half * 2] + bo.x + xv.x,
                                           acc[mi][jn][half * 2 + 1] + bo.y + xv.y);
                    *(float2*)&outp[(size_t)gr * 512 + gc] = o;
                }
            }
        }
    }
}

// ================= landmarks (fp32 + fp16 out) =================
__global__ void landmark_kernel() {
    int idx = blockIdx.x * 256 + threadIdx.x;
    int sel = idx >> 18;
    int r = idx & 262143;
    int bh = r >> 14;
    int m = (r >> 6) & 255;
    int d = r & 63;
    const float* src = sel ? g_k : g_q;
    const float* p = src + ((size_t)bh * NSEQ + m * LGRP) * DHd + d;
    float s = 0.f;
#pragma unroll
    for (int i = 0; i < LGRP; i++) s += p[i * DHd];
    float val = s * (1.f / LGRP);
    (sel ? g_kl : g_ql)[(bh * MLM + m) * DHd + d] = val;
    (sel ? g_klh : g_qlh)[(bh * MLM + m) * DHd + d] = __float2half(val);
}

// ================= attn2 = softmax(q_l k_l^T) =================
__global__ __launch_bounds__(256) void attn2_kernel() {
    int bh = blockIdx.x;
    int m = threadIdx.x;
    __shared__ float4 kls[1024];
    float4 q[16];
    const float4* qp = (const float4*)g_ql + (size_t)(bh * MLM + m) * 16;
#pragma unroll
    for (int i = 0; i < 16; i++) q[i] = qp[i];
    float sum = 0.f;
    float* arow = g_attn2 + (size_t)bh * 65536 + (size_t)m * 256;
    for (int tile = 0; tile < 4; tile++) {
        __syncthreads();
        const float4* src = (const float4*)g_kl + (size_t)(bh * MLM + tile * 64) * 16;
#pragma unroll
        for (int i = 0; i < 4; i++) kls[threadIdx.x + i * 256] = src[threadIdx.x + i * 256];
        __syncthreads();
        for (int j = 0; j < 64; j++) {
            const float4* kr = &kls[j * 16];
            float s = 0.f;
#pragma unroll
            for (int d = 0; d < 16; d++) {
                float4 a = q[d], b = kr[d];
                s += a.x * b.x + a.y * b.y + a.z * b.z + a.w * b.w;
            }
            float p = __expf(s);
            sum += p;
            arow[tile * 64 + j] = p;
        }
    }
    float inv = 1.f / sum;
    for (int j = 0; j < 256; j++) arow[j] *= inv;
}

// ================= max column-sum of attn2 =================
__global__ __launch_bounds__(256) void colmax_kernel() {
    int bh = blockIdx.x;
    int j = threadIdx.x;
    const float* a = g_attn2 + (size_t)bh * 65536;
    float s = 0.f;
    for (int m2 = 0; m2 < 256; m2++) s += a[m2 * 256 + j];
    __shared__ float red[256];
    red[j] = s;
    __syncthreads();
    for (int o = 128; o; o >>= 1) {
        if (j < o) red[j] = fmaxf(red[j], red[j + o]);
        __syncthreads();
    }
    if (j == 0) atomicMax(&g_maxc_bits, __float_as_int(red[0]));
}

__global__ void z0_kernel() {
    int idx = blockIdx.x * 256 + threadIdx.x;
    int bh = idx >> 16;
    int i = (idx >> 8) & 255;
    int j = idx & 255;
    float scale = 1.f / __int_as_float(g_maxc_bits);
    g_Za[idx] = g_attn2[(bh << 16) + (j << 8) + i] * scale;
}

// ================= buffer selector =================
__device__ __forceinline__ float* pickBuf(int id) {
    switch (id) {
        case 0: return g_attn2;
        case 1: return g_Y;
        case 2: return g_P;
        case 3: return g_Qm;
        case 4: return g_Za;
        case 5: return g_Zb;
        case 6: return g_W2;
        default: return g_W3;
    }
}

// ================= pinv batched GEMM on tensor cores =================
__global__ __launch_bounds__(256) void gemm_pinv_mma(int cId, int aId, int bId,
                                                     float beta, float sgn, float alpha) {
    __shared__ __align__(16) __nv_bfloat16 sAh[128][40];
    __shared__ __align__(16) __nv_bfloat16 sAl[128][40];
    __shared__ __align__(16) __nv_bfloat16 sBh[64][40];
    __shared__ __align__(16) __nv_bfloat16 sBl[64][40];

    int bh = blockIdx.z;
    int mBase = blockIdx.y * 128, nBase = blockIdx.x * 64;
    const float* A = pickBuf(aId) + (size_t)bh * 65536;
    const float* B = pickBuf(bId) + (size_t)bh * 65536;
    float*       C = pickBuf(cId) + (size_t)bh * 65536;

    int tid = threadIdx.x, lane = tid & 31, w = tid >> 5;
    int wm = w & 3, wn = w >> 2;
    int lr = lane & 15, lh = lane >> 4;

    float acc[2][4][4];
#pragma unroll
    for (int i = 0; i < 2; i++)
#pragma unroll
        for (int j = 0; j < 4; j++)
#pragma unroll
            for (int c = 0; c < 4; c++) acc[i][j][c] = 0.f;

    for (int ch = 0; ch < 8; ch++) {
        if (ch) __syncthreads();
#pragma unroll
        for (int i = 0; i < 4; i++) {
            int idx = tid + i * 256;
            int r = idx >> 3, c4 = (idx & 7) * 4;
            float4 v = *(const float4*)&A[(size_t)(mBase + r) * 256 + ch * 32 + c4];
            __nv_bfloat16 h0 = __float2bfloat16(v.x), h1 = __float2bfloat16(v.y);
            __nv_bfloat16 h2 = __float2bfloat16(v.z), h3 = __float2bfloat16(v.w);
            sAh[r][c4 + 0] = h0; sAh[r][c4 + 1] = h1;
            sAh[r][c4 + 2] = h2; sAh[r][c4 + 3] = h3;
            sAl[r][c4 + 0] = __float2bfloat16(v.x - __bfloat162float(h0));
            sAl[r][c4 + 1] = __float2bfloat16(v.y - __bfloat162float(h1));
            sAl[r][c4 + 2] = __float2bfloat16(v.z - __bfloat162float(h2));
            sAl[r][c4 + 3] = __float2bfloat16(v.w - __bfloat162float(h3));
        }
#pragma unroll
        for (int kl = 0; kl < 4; kl++) {
            int gk = ch * 32 + w * 4 + kl;
#pragma unroll
            for (int nh = 0; nh < 2; nh++) {
                int n = nh * 32 + lane;
                float v = B[(size_t)gk * 256 + nBase + n];
                v = sgn * v + ((gk == nBase + n) ? beta : 0.f);
                __nv_bfloat16 h = __float2bfloat16(v);
                sBh[n][w * 4 + kl] = h;
                sBl[n][w * 4 + kl] = __float2bfloat16(v - __bfloat162float(h));
            }
        }
        __syncthreads();
#pragma unroll
        for (int ks = 0; ks < 2; ks++) {
            int kc = ks * 16 + lh * 8;
            unsigned ah[2][4], al[2][4];
#pragma unroll
            for (int mi = 0; mi < 2; mi++) {
                int rowA = wm * 32 + mi * 16 + lr;
                ldm4(ah[mi], smem_u32(&sAh[rowA][kc]));
                ldm4(al[mi], smem_u32(&sAl[rowA][kc]));
            }
#pragma unroll
            for (int nt = 0; nt < 2; nt++) {
                int rowB = wn * 32 + nt * 16 + lr;
                unsigned bhf[4], blf[4];
                ldm4(bhf, smem_u32(&sBh[rowB][kc]));
                ldm4(blf, smem_u32(&sBl[rowB][kc]));
#pragma unroll
                for (int mi = 0; mi < 2; mi++) {
#pragma unroll
                    for (int ns = 0; ns < 2; ns++) {
                        float* cc = acc[mi][nt * 2 + ns];
                        mma16816(cc, ah[mi], bhf[ns], bhf[ns + 2]);
                        mma16816(cc, ah[mi], blf[ns], blf[ns + 2]);
                        mma16816(cc, al[mi], bhf[ns], bhf[ns + 2]);
                    }
                }
            }
        }
    }
#pragma unroll
    for (int mi = 0; mi < 2; mi++) {
#pragma unroll
        for (int jn = 0; jn < 4; jn++) {
            int gc = nBase + wn * 32 + jn * 8 + (lane & 3) * 2;
#pragma unroll
            for (int half = 0; half < 2; half++) {
                int gr = mBase + wm * 32 + mi * 16 + (lane >> 2) + half * 8;
                float2 o = make_float2(acc[mi][jn][half * 2] * alpha,
                                       acc[mi][jn][half * 2 + 1] * alpha);
                *(float2*)&C[(size_t)gr * 256 + gc] = o;
            }
        }
    }
}

// ================= batched per-bh GEMM (scalar, kept for W3) =================
__global__ __launch_bounds__(256) void gemm_bh_kernel(int cId, int aId, int bId, int Nn,
                                                      float beta, float sgn, float alpha) {
    int bh = blockIdx.z, mt = blockIdx.y, nt = blockIdx.x;
    const float* A  = pickBuf(aId) + (size_t)bh * 65536;
    const float* Bp = pickBuf(bId) + (size_t)bh * 256 * Nn;
    float*       C  = pickBuf(cId) + (size_t)bh * 256 * Nn;
    __shared__ float As[16][64];
    __shared__ float Bs[16][64];
    int tid = threadIdx.x;
    int ar = tid >> 2, ac = (tid & 3) * 4;
    int br = tid >> 4, bc = (tid & 15) * 4;
    int ty = tid >> 4, tx = tid & 15;
    float acc[4][4];
#pragma unroll
    for (int i = 0; i < 4; i++)
#pragma unroll
        for (int j = 0; j < 4; j++) acc[i][j] = 0.f;

    for (int k0 = 0; k0 < 256; k0 += 16) {
        float4 av = *(const float4*)&A[(size_t)(mt * 64 + ar) * 256 + k0 + ac];
        As[ac + 0][ar] = av.x; As[ac + 1][ar] = av.y;
        As[ac + 2][ar] = av.z; As[ac + 3][ar] = av.w;
        int gk = k0 + br;
        int gc = nt * 64 + bc;
        float4 bv = *(const float4*)&Bp[(size_t)gk * Nn + gc];
        bv.x = sgn * bv.x + (gk == gc + 0 ? beta : 0.f);
        bv.y = sgn * bv.y + (gk == gc + 1 ? beta : 0.f);
        bv.z = sgn * bv.z + (gk == gc + 2 ? beta : 0.f);
        bv.w = sgn * bv.w + (gk == gc + 3 ? beta : 0.f);
        *(float4*)&Bs[br][bc] = bv;
        __syncthreads();
#pragma unroll
        for (int kk = 0; kk < 16; kk++) {
            float4 a4 = *(const float4*)&As[kk][ty * 4];
            float4 b4 = *(const float4*)&Bs[kk][tx * 4];
            acc[0][0] += a4.x * b4.x; acc[0][1] += a4.x * b4.y; acc[0][2] += a4.x * b4.z; acc[0][3] += a4.x * b4.w;
            acc[1][0] += a4.y * b4.x; acc[1][1] += a4.y * b4.y; acc[1][2] += a4.y * b4.z; acc[1][3] += a4.y * b4.w;
            acc[2][0] += a4.z * b4.x; acc[2][1] += a4.z * b4.y; acc[2][2] += a4.z * b4.z; acc[2][3] += a4.z * b4.w;
            acc[3][0] += a4.w * b4.x; acc[3][1] += a4.w * b4.y; acc[3][2] += a4.w * b4.z; acc[3][3] += a4.w * b4.w;
        }
        __syncthreads();
    }
#pragma unroll
    for (int i = 0; i < 4; i++) {
        float4 o = make_float4(acc[i][0] * alpha, acc[i][1] * alpha,
                               acc[i][2] * alpha, acc[i][3] * alpha);
        *(float4*)&C[(size_t)(mt * 64 + ty * 4 + i) * Nn + nt * 64 + tx * 4] = o;
    }
}

// ================= flash W2 on tensor cores =================
__global__ __launch_bounds__(256) void flash_w2_mma() {
    __shared__ __align__(16) __half sql[128][72];
    __shared__ __align__(16) __half sk[64][72];
    __shared__ __align__(16) __half svT[64][72];

    int tid = threadIdx.x, lane = tid & 31, w = tid >> 5;
    int chunk = blockIdx.x, mblk = blockIdx.y, bh = blockIdx.z;
    int lr = lane & 15, lh = lane >> 4;

    const __half* qlh = g_qlh + (size_t)(bh * MLM + mblk * 128) * 64;
#pragma unroll
    for (int i = 0; i < 4; i++) {
        int idx = tid + i * 256;
        int r = idx >> 3, c = (idx & 7) * 8;
        *(uint4*)&sql[r][c] = *(const uint4*)&qlh[(size_t)r * 64 + c];
    }
    __syncthreads();
    unsigned qa[4][4];
#pragma unroll
    for (int ks = 0; ks < 4; ks++)
        ldm4(qa[ks], smem_u32(&sql[w * 16 + lr][ks * 16 + lh * 8]));

    float outacc[8][4];
#pragma unroll
    for (int i = 0; i < 8; i++)
#pragma unroll
        for (int c = 0; c < 4; c++) outacc[i][c] = 0.f;
    float rsA = 0.f, rsB = 0.f;

    const __half* kb = g_kh + (size_t)bh * NSEQ * 64;
    const __half* vb = g_vh + (size_t)bh * NSEQ * 64;

    for (int it = 0; it < 32; it++) {
        int s0 = chunk * 2048 + it * 64;
        __syncthreads();
#pragma unroll
        for (int i = 0; i < 2; i++) {
            int idx = tid + i * 256;
            int r = idx >> 3, c = (idx & 7) * 8;
            *(uint4*)&sk[r][c] = *(const uint4*)&kb[(size_t)(s0 + r) * 64 + c];
            uint4 vv = *(const uint4*)&vb[(size_t)(s0 + r) * 64 + c];
            __half vh[8];
            *(uint4*)vh = vv;
#pragma unroll
            for (int j = 0; j < 8; j++) svT[c + j][r] = vh[j];
        }
        __syncthreads();
        float sf[8][4];
#pragma unroll
        for (int i = 0; i < 8; i++)
#pragma unroll
            for (int c = 0; c < 4; c++) sf[i][c] = 0.f;
#pragma unroll
        for (int ks = 0; ks < 4; ks++) {
#pragma unroll
            for (int nf4 = 0; nf4 < 4; nf4++) {
                unsigned bbf[4];
                ldm4(bbf, smem_u32(&sk[nf4 * 16 + lr][ks * 16 + lh * 8]));
                mmaf16(sf[nf4 * 2], qa[ks], bbf[0], bbf[2]);
                mmaf16(sf[nf4 * 2 + 1], qa[ks], bbf[1], bbf[3]);
            }
        }
#pragma unroll
        for (int nf = 0; nf < 8; nf++) {
            sf[nf][0] = fexp(sf[nf][0]); sf[nf][1] = fexp(sf[nf][1]);
            sf[nf][2] = fexp(sf[nf][2]); sf[nf][3] = fexp(sf[nf][3]);
            rsA += sf[nf][0] + sf[nf][1];
            rsB += sf[nf][2] + sf[nf][3];
        }
#pragma unroll
        for (int kk = 0; kk < 4; kk++) {
            unsigned pa[4];
            pa[0] = packh2(sf[2 * kk][0], sf[2 * kk][1]);
            pa[1] = packh2(sf[2 * kk][2], sf[2 * kk][3]);
            pa[2] = packh2(sf[2 * kk + 1][0], sf[2 * kk + 1][1]);
            pa[3] = packh2(sf[2 * kk + 1][2], sf[2 * kk + 1][3]);
#pragma unroll
            for (int nf4 = 0; nf4 < 4; nf4++) {
                unsigned bbf[4];
                ldm4(bbf, smem_u32(&svT[nf4 * 16 + lr][kk * 16 + lh * 8]));
                mmaf16(outacc[nf4 * 2], pa, bbf[0], bbf[2]);
                mmaf16(outacc[nf4 * 2 + 1], pa, bbf[1], bbf[3]);
            }
        }
    }
    rsA += __shfl_xor_sync(0xffffffffu, rsA, 1);
    rsA += __shfl_xor_sync(0xffffffffu, rsA, 2);
    rsB += __shfl_xor_sync(0xffffffffu, rsB, 1);
    rsB += __shfl_xor_sync(0xffffffffu, rsB, 2);

    int rA = mblk * 128 + w * 16 + (lane >> 2);
    int rB = rA + 8;
    float* wpA = g_Wpart + (size_t)((bh * 4 + chunk) * MLM + rA) * 64;
    float* wpB = g_Wpart + (size_t)((bh * 4 + chunk) * MLM + rB) * 64;
#pragma unroll
    for (int nf = 0; nf < 8; nf++) {
        int d = nf * 8 + (lane & 3) * 2;
        *(float2*)&wpA[d] = make_float2(outacc[nf][0], outacc[nf][1]);
        *(float2*)&wpB[d] = make_float2(outacc[nf][2], outacc[nf][3]);
    }
    if ((lane & 3) == 0) {
        g_Spart[(bh * 4 + chunk) * MLM + rA] = rsA;
        g_Spart[(bh * 4 + chunk) * MLM + rB] = rsB;
    }
}

__global__ void combine_w2_kernel() {
    int idx = blockIdx.x * 256 + threadIdx.x;
    int bh = idx >> 14;
    int m = (idx >> 6) & 255;
    int d = idx & 63;
    float num = 0.f, den = 0.f;
#pragma unroll
    for (int c = 0; c < 4; c++) {
        num += g_Wpart[(size_t)((bh * 4 + c) * MLM + m) * 64 + d];
        den += g_Spart[(bh * 4 + c) * MLM + m];
    }
    g_W2[(bh * MLM + m) * 64 + d] = num / den;
}

// ================= attn1 + conv on tensor cores =================
__global__ __launch_bounds__(256) void attn1_mma(const float* __restrict__ convw) {
    extern __shared__ char smx[];
    __half (*sq)[72]  = (__half(*)[72])(smx);
    __half (*skl)[72] = (__half(*)[72])(smx + 18432);
    __half (*swT)[72] = (__half(*)[72])(smx + 27648);
    __half (*sv)[72]  = (__half(*)[72])(smx + 36864);
    float* cw = (float*)(smx + 59904);

    int tid = threadIdx.x, lane = tid & 31, w = tid >> 5;
    int ntile = blockIdx.x, bh = blockIdx.y;
    int h = bh & 7, bb2 = bh >> 3;
    int n0 = ntile * 128;
    int lr = lane & 15, lh = lane >> 4;

    if (tid < KSZ) cw[tid] = convw[h * KSZ + tid];

    const __half* qb = g_qh + ((size_t)bh * NSEQ + n0) * 64;
#pragma unroll
    for (int i = 0; i < 4; i++) {
        int idx = tid + i * 256;
        int r = idx >> 3, c = (idx & 7) * 8;
        *(uint4*)&sq[r][c] = *(const uint4*)&qb[(size_t)r * 64 + c];
    }
    const __half* vb2 = g_vh + (size_t)bh * NSEQ * 64;
#pragma unroll
    for (int i = 0; i < 5; i++) {
        int idx = tid + i * 256;
        int r = idx >> 3, c = (idx & 7) * 8;
        int gr = n0 - 16 + r;
        uint4 z = make_uint4(0u, 0u, 0u, 0u);
        if (gr >= 0 && gr < NSEQ) z = *(const uint4*)&vb2[(size_t)gr * 64 + c];
        *(uint4*)&sv[r][c] = z;
    }
    __syncthreads();

    unsigned qa[4][4];
#pragma unroll
    for (int ks = 0; ks < 4; ks++)
        ldm4(qa[ks], smem_u32(&sq[w * 16 + lr][ks * 16 + lh * 8]));

    float outacc[8][4];
#pragma unroll
    for (int i = 0; i < 8; i++)
#pragma unroll
        for (int c = 0; c < 4; c++) outacc[i][c] = 0.f;
    float rsA = 0.f, rsB = 0.f;

    const __half* klb = g_klh + (size_t)bh * MLM * 64;
    const __half* w3tb = g_W3T + (size_t)bh * 64 * 256;

    for (int lc = 0; lc < 4; lc++) {
        __syncthreads();
#pragma unroll
        for (int i = 0; i < 2; i++) {
            int idx = tid + i * 256;
            int r = idx >> 3, c = (idx & 7) * 8;
            *(uint4*)&skl[r][c] = *(const uint4*)&klb[(size_t)(lc * 64 + r) * 64 + c];
            *(uint4*)&swT[r][c] = *(const uint4*)&w3tb[(size_t)r * 256 + lc * 64 + c];
        }
        __syncthreads();
        float sf[8][4];
#pragma unroll
        for (int i = 0; i < 8; i++)
#pragma unroll
            for (int c = 0; c < 4; c++) sf[i][c] = 0.f;
#pragma unroll
        for (int ks = 0; ks < 4; ks++) {
#pragma unroll
            for (int nf4 = 0; nf4 < 4; nf4++) {
                unsigned bbf[4];
                ldm4(bbf, smem_u32(&skl[nf4 * 16 + lr][ks * 16 + lh * 8]));
                mmaf16(sf[nf4 * 2], qa[ks], bbf[0], bbf[2]);
                mmaf16(sf[nf4 * 2 + 1], qa[ks], bbf[1], bbf[3]);
            }
        }
#pragma unroll
        for (int nf = 0; nf < 8; nf++) {
            sf[nf][0] = fexp(sf[nf][0]); sf[nf][1] = fexp(sf[nf][1]);
            sf[nf][2] = fexp(sf[nf][2]); sf[nf][3] = fexp(sf[nf][3]);
            rsA += sf[nf][0] + sf[nf][1];
            rsB += sf[nf][2] + sf[nf][3];
        }
#pragma unroll
        for (int kk = 0; kk < 4; kk++) {
            unsigned pa[4];
            pa[0] = packh2(sf[2 * kk][0], sf[2 * kk][1]);
            pa[1] = packh2(sf[2 * kk][2], sf[2 * kk][3]);
            pa[2] = packh2(sf[2 * kk + 1][0], sf[2 * kk + 1][1]);
            pa[3] = packh2(sf[2 * kk + 1][2], sf[2 * kk + 1][3]);
#pragma unroll
            for (int nf4 = 0; nf4 < 4; nf4++) {
                unsigned bbf[4];
                ldm4(bbf, smem_u32(&swT[nf4 * 16 + lr][kk * 16 + lh * 8]));
                mmaf16(outacc[nf4 * 2], pa, bbf[0], bbf[2]);
                mmaf16(outacc[nf4 * 2 + 1], pa, bbf[1], bbf[3]);
            }
        }
    }
    rsA += __shfl_xor_sync(0xffffffffu, rsA, 1);
    rsA += __shfl_xor_sync(0xffffffffu, rsA, 2);
    rsB += __shfl_xor_sync(0xffffffffu, rsB, 1);
    rsB += __shfl_xor_sync(0xffffffffu, rsB, 2);
    float invA = 1.f / rsA, invB = 1.f / rsB;

    int lrA = w * 16 + (lane >> 2);
#pragma unroll
    for (int nf = 0; nf < 8; nf++) {
        int d = nf * 8 + (lane & 3) * 2;
        float a0 = 0.f, a1 = 0.f, b0 = 0.f, b1 = 0.f;
#pragma unroll
        for (int t = 0; t < KSZ; t++) {
            float wv = cw[t];
            float2 fA = __half22float2(*(__half2*)&sv[lrA + t][d]);
            float2 fB = __half22float2(*(__half2*)&sv[lrA + 8 + t][d]);
            a0 = fmaf(wv, fA.x, a0); a1 = fmaf(wv, fA.y, a1);
            b0 = fmaf(wv, fB.x, b0); b1 = fmaf(wv, fB.y, b1);
        }
        outacc[nf][0] = outacc[nf][0] * invA + a0;
        outacc[nf][1] = outacc[nf][1] * invA + a1;
        outacc[nf][2] = outacc[nf][2] * invB + b0;
        outacc[nf][3] = outacc[nf][3] * invB + b1;
    }

    int nA = n0 + lrA, nB = nA + 8;
    float* oA = g_outpre + (size_t)(bb2 * NSEQ + nA) * 512 + h * 64;
    float* oB = g_outpre + (size_t)(bb2 * NSEQ + nB) * 512 + h * 64;
#pragma unroll
    for (int nf = 0; nf < 8; nf++) {
        int d = nf * 8 + (lane & 3) * 2;
        *(float2*)&oA[d] = make_float2(outacc[nf][0], outacc[nf][1]);
        *(float2*)&oB[d] = make_float2(outacc[nf][2], outacc[nf][3]);
    }
}

// ================= host launcher =================
extern "C" void kernel_launch(void* const* d_in, const int* in_sizes, int n_in,
                              void* d_out, int out_size) {
    const float* x     = (const float*)d_in[0];
    const float* ln_g  = (const float*)d_in[1];
    const float* ln_b  = (const float*)d_in[2];
    const float* W_qkv = (const float*)d_in[3];
    const float* W_out = (const float*)d_in[4];
    const float* b_out = (const float*)d_in[5];
    const float* convw = (const float*)d_in[6];
    float* out = (float*)d_out;

    cudaFuncSetAttribute(attn1_mma, cudaFuncAttributeMaxDynamicSharedMemorySize, 60416);
    cudaFuncSetAttribute(gemm_mma_kernel, cudaFuncAttributeMaxDynamicSharedMemorySize, 81920);

    __nv_bfloat16 *bqh, *bql, *boh, *bol;
    cudaGetSymbolAddress((void**)&bqh, g_Bqh);
    cudaGetSymbolAddress((void**)&bql, g_Bql);
    cudaGetSymbolAddress((void**)&boh, g_Boh);
    cudaGetSymbolAddress((void**)&bol, g_Bol);
    float* xnp;
    cudaGetSymbolAddress((void**)&xnp, g_xn);
    float* opp;
    cudaGetSymbolAddress((void**)&opp, g_outpre);

    reset_kernel<<<1, 1>>>();
    ln_kernel<<<Bb * NSEQ, 128>>>(x, ln_g, ln_b);

    convA_kernel<<<8192, 256>>>(xnp);
    convW_kernel<<<dim3(48, 16), 1024>>>(W_qkv, 1536, bqh, bql);
    convW_kernel<<<dim3(16, 16), 1024>>>(W_out, 512, boh, bol);

    gemm_mma_kernel<<<dim3(12, 128), 256, 81920>>>(bqh, bql, 0, nullptr, nullptr);

    landmark_kernel<<<2048, 256>>>();
    attn2_kernel<<<16, 256>>>();
    colmax_kernel<<<16, 256>>>();
    z0_kernel<<<4096, 256>>>();

    int zc = 4, zn = 5;  // Za, Zb
    for (int it = 0; it < 6; it++) {
        gemm_pinv_mma<<<dim3(4, 2, 16), 256>>>(1, 0, zc, 0.f, 1.f, 1.f);
        gemm_pinv_mma<<<dim3(4, 2, 16), 256>>>(2, 1, 1, 7.f, -1.f, 1.f);
        gemm_pinv_mma<<<dim3(4, 2, 16), 256>>>(3, 1, 2, 15.f, -1.f, 1.f);
        gemm_pinv_mma<<<dim3(4, 2, 16), 256>>>(zn, zc, 3, 13.f, -1.f, 0.25f);
        int t = zc; zc = zn; zn = t;
    }

    flash_w2_mma<<<dim3(4, 2, 16), 256>>>();
    combine_w2_kernel<<<1024, 256>>>();
    gemm_bh_kernel<<<dim3(1, 4, 16), 256>>>(7, zc, 6, 64, 0.f, 1.f, 1.f);  // W3 = Z @ W2
    w3t_kernel<<<1024, 256>>>();
    attn1_mma<<<dim3(64, 16), 256, 60416>>>(convw);

    convA_kernel<<<8192, 256>>>(opp);
    gemm_mma_kernel<<<dim3(4, 128), 256, 81920>>>(boh, bol, 1, b_out, out);
}

// round 8
// speedup vs baseline: 2.7621x; 1.1091x over previous
#include <cuda_runtime.h>
#include <cuda_bf16.h>
#include <cuda_fp16.h>

#define Bb    2
#define NSEQ  8192
#define DIMV  512
#define NH    8
#define BHn   16
#define DHd   64
#define MLM   256
#define LGRP  32
#define KSZ   33
#define PADc  16
#define SCALE 0.125f

// ================= static device scratch =================
__device__ float g_xn[(size_t)Bb * NSEQ * DIMV];
__device__ float g_xnlm[512 * 512];
__device__ float g_ql[BHn * MLM * DHd];
__device__ float g_kl[BHn * MLM * DHd];
__device__ float g_attn2[BHn * MLM * MLM];
__device__ float g_Y[BHn * MLM * MLM];
__device__ float g_P[BHn * MLM * MLM];
__device__ float g_Qm[BHn * MLM * MLM];
__device__ float g_Za[BHn * MLM * MLM];
__device__ float g_Zb[BHn * MLM * MLM];
__device__ float g_W2[BHn * MLM * DHd];
__device__ float g_W3[BHn * MLM * DHd];
__device__ float g_Wpart[(size_t)BHn * 4 * MLM * DHd];
__device__ float g_Spart[BHn * 4 * MLM];
__device__ float g_outpre[(size_t)Bb * NSEQ * DIMV];
__device__ int   g_maxc_bits;

// bf16 hi/lo buffers (landmark GEMM + out GEMM)
__device__ __nv_bfloat16 g_Ahi[(size_t)Bb * NSEQ * DIMV];
__device__ __nv_bfloat16 g_Alo[(size_t)Bb * NSEQ * DIMV];
__device__ __nv_bfloat16 g_Bqh[1536 * 512];
__device__ __nv_bfloat16 g_Bql[1536 * 512];
__device__ __nv_bfloat16 g_Boh[512 * 512];
__device__ __nv_bfloat16 g_Bol[512 * 512];

// fp16 buffers
__device__ __half g_A16[(size_t)Bb * NSEQ * DIMV];
__device__ __half g_B16q[1536 * 512];
__device__ __half g_qh[(size_t)BHn * NSEQ * DHd];
__device__ __half g_kh[(size_t)BHn * NSEQ * DHd];
__device__ __half g_vh[(size_t)BHn * NSEQ * DHd];
__device__ __half g_qlh[BHn * MLM * DHd];
__device__ __half g_klh[BHn * MLM * DHd];
__device__ __half g_W3T[BHn * DHd * MLM];

__global__ void reset_kernel() { g_maxc_bits = 0; }

// ================= mma.sync helpers =================
__device__ __forceinline__ unsigned smem_u32(const void* p) {
    unsigned a;
    asm("{ .reg .u64 t; cvta.to.shared.u64 t, %1; cvt.u32.u64 %0, t; }" : "=r"(a) : "l"(p));
    return a;
}
__device__ __forceinline__ void ldm4(unsigned* r, unsigned addr) {
    asm volatile("ldmatrix.sync.aligned.m8n8.x4.shared.b16 {%0,%1,%2,%3}, [%4];"
        : "=r"(r[0]), "=r"(r[1]), "=r"(r[2]), "=r"(r[3]) : "r"(addr));
}
__device__ __forceinline__ void mma16816(float* c, const unsigned* a, unsigned b0, unsigned b1) {
    asm volatile("mma.sync.aligned.m16n8k16.row.col.f32.bf16.bf16.f32 "
        "{%0,%1,%2,%3}, {%4,%5,%6,%7}, {%8,%9}, {%0,%1,%2,%3};"
        : "+f"(c[0]), "+f"(c[1]), "+f"(c[2]), "+f"(c[3])
        : "r"(a[0]), "r"(a[1]), "r"(a[2]), "r"(a[3]), "r"(b0), "r"(b1));
}
__device__ __forceinline__ void mmaf16(float* c, const unsigned* a, unsigned b0, unsigned b1) {
    asm volatile("mma.sync.aligned.m16n8k16.row.col.f32.f16.f16.f32 "
        "{%0,%1,%2,%3}, {%4,%5,%6,%7}, {%8,%9}, {%0,%1,%2,%3};"
        : "+f"(c[0]), "+f"(c[1]), "+f"(c[2]), "+f"(c[3])
        : "r"(a[0]), "r"(a[1]), "r"(a[2]), "r"(a[3]), "r"(b0), "r"(b1));
}
__device__ __forceinline__ void cpasync16(unsigned dst, const void* src) {
    asm volatile("cp.async.cg.shared.global [%0], [%1], 16;" :: "r"(dst), "l"(src));
}
#define CP_COMMIT() asm volatile("cp.async.commit_group;" ::: "memory")
__device__ __forceinline__ unsigned packh2(float a, float b) {
    __half2 h = __floats2half2_rn(a, b);
    return *(unsigned*)&h;
}
__device__ __forceinline__ float fexp(float x) {
    float t = x * 1.44269504f;
    float r = rintf(t);
    float f = t - r;
    float p = 1.33336e-3f;
    p = fmaf(p, f, 9.61813e-3f);
    p = fmaf(p, f, 5.55041e-2f);
    p = fmaf(p, f, 2.40226507e-1f);
    p = fmaf(p, f, 6.93147181e-1f);
    p = fmaf(p, f, 1.0f);
    int e = (int)r;
    return p * __int_as_float((e + 127) << 23);
}

// ================= layernorm =================
__global__ __launch_bounds__(128) void ln_kernel(const float* __restrict__ x,
                                                 const float* __restrict__ gam,
                                                 const float* __restrict__ bet) {
    int row = blockIdx.x;
    int tid = threadIdx.x;
    float4 v = ((const float4*)x)[(size_t)row * 128 + tid];
    float s1 = v.x + v.y + v.z + v.w;
    float s2 = v.x * v.x + v.y * v.y + v.z * v.z + v.w * v.w;
#pragma unroll
    for (int o = 16; o; o >>= 1) {
        s1 += __shfl_xor_sync(0xffffffffu, s1, o);
        s2 += __shfl_xor_sync(0xffffffffu, s2, o);
    }
    __shared__ float r1[4], r2[4];
    int w = tid >> 5;
    if ((tid & 31) == 0) { r1[w] = s1; r2[w] = s2; }
    __syncthreads();
    s1 = r1[0] + r1[1] + r1[2] + r1[3];
    s2 = r2[0] + r2[1] + r2[2] + r2[3];
    float mean = s1 * (1.f / 512.f);
    float var  = s2 * (1.f / 512.f) - mean * mean;
    float rstd = rsqrtf(var + 1e-5f);
    float4 g4 = ((const float4*)gam)[tid];
    float4 b4 = ((const float4*)bet)[tid];
    float4 o;
    o.x = (v.x - mean) * rstd * g4.x + b4.x;
    o.y = (v.y - mean) * rstd * g4.y + b4.y;
    o.z = (v.z - mean) * rstd * g4.z + b4.z;
    o.w = (v.w - mean) * rstd * g4.w + b4.w;
    ((float4*)g_xn)[(size_t)row * 128 + tid] = o;
}

// ================= group means of xn (landmark pre-image) =================
__global__ void xnlm_kernel() {
    int idx = blockIdx.x * 256 + threadIdx.x;  // 512*512
    int row = idx >> 9;       // b*256 + m
    int d = idx & 511;
    int b = row >> 8, m = row & 255;
    const float* p = g_xn + ((size_t)(b * NSEQ) + m * LGRP) * DIMV + d;
    float s = 0.f;
#pragma unroll
    for (int i = 0; i < LGRP; i++) s += p[(size_t)i * DIMV];
    g_xnlm[idx] = s * (1.f / LGRP);
}

// ================= converters =================
__global__ __launch_bounds__(256) void convA_kernel(const float* __restrict__ src) {
    size_t i4 = ((size_t)blockIdx.x * 256 + threadIdx.x) * 4;
    float4 v = *(const float4*)(src + i4);
    __nv_bfloat16 h0 = __float2bfloat16(v.x), h1 = __float2bfloat16(v.y);
    __nv_bfloat16 h2 = __float2bfloat16(v.z), h3 = __float2bfloat16(v.w);
    __nv_bfloat16 l0 = __float2bfloat16(v.x - __bfloat162float(h0));
    __nv_bfloat16 l1 = __float2bfloat16(v.y - __bfloat162float(h1));
    __nv_bfloat16 l2 = __float2bfloat16(v.z - __bfloat162float(h2));
    __nv_bfloat16 l3 = __float2bfloat16(v.w - __bfloat162float(h3));
    __nv_bfloat162* ph = (__nv_bfloat162*)(g_Ahi + i4);
    __nv_bfloat162* pl = (__nv_bfloat162*)(g_Alo + i4);
    ph[0] = __nv_bfloat162(h0, h1); ph[1] = __nv_bfloat162(h2, h3);
    pl[0] = __nv_bfloat162(l0, l1); pl[1] = __nv_bfloat162(l2, l3);
}

__global__ __launch_bounds__(256) void convA16_kernel(const float* __restrict__ src) {
    size_t i4 = ((size_t)blockIdx.x * 256 + threadIdx.x) * 4;
    float4 v = *(const float4*)(src + i4);
    __half2* ph = (__half2*)(g_A16 + i4);
    ph[0] = __floats2half2_rn(v.x, v.y);
    ph[1] = __floats2half2_rn(v.z, v.w);
}

__global__ __launch_bounds__(1024) void convW_kernel(const float* __restrict__ W, int N,
                                                     __nv_bfloat16* __restrict__ BThi,
                                                     __nv_bfloat16* __restrict__ BTlo) {
    __shared__ float sh[32][33];
    int n0 = blockIdx.x * 32, k0 = blockIdx.y * 32;
    int tx = threadIdx.x & 31, ty = threadIdx.x >> 5;
    sh[ty][tx] = W[(size_t)(k0 + ty) * N + n0 + tx];
    __syncthreads();
    float x = sh[tx][ty];
    __nv_bfloat16 h = __float2bfloat16(x);
    __nv_bfloat16 l = __float2bfloat16(x - __bfloat162float(h));
    BThi[(size_t)(n0 + ty) * 512 + k0 + tx] = h;
    BTlo[(size_t)(n0 + ty) * 512 + k0 + tx] = l;
}

__global__ __launch_bounds__(1024) void convW16_kernel(const float* __restrict__ W, int N,
                                                       __half* __restrict__ BT) {
    __shared__ float sh[32][33];
    int n0 = blockIdx.x * 32, k0 = blockIdx.y * 32;
    int tx = threadIdx.x & 31, ty = threadIdx.x >> 5;
    sh[ty][tx] = W[(size_t)(k0 + ty) * N + n0 + tx];
    __syncthreads();
    BT[(size_t)(n0 + ty) * 512 + k0 + tx] = __float2half(sh[tx][ty]);
}

// W3 -> W3T fp16 [bh][d][m]
__global__ void w3t_kernel() {
    int idx = blockIdx.x * 256 + threadIdx.x;
    int bh = idx >> 14;
    int m = (idx >> 6) & 255;
    int d = idx & 63;
    float v = g_W3[(bh * 256 + m) * 64 + d];
    g_W3T[((size_t)bh * 64 + d) * 256 + m] = __float2half(v);
}

// ================= fp16 single-pass qkv GEMM (cp.async double-buffered) =================
// C[16384,1536] = A16 @ B16q^T, epilogue -> g_qh/g_kh/g_vh (fp16). grid (12, 128).
// dynamic smem: 2 stages x 36864B; per stage A@0 (128x72 half), B@18432.
__global__ __launch_bounds__(256) void gemm_qkv16_kernel() {
    extern __shared__ char smdyn[];
    unsigned sbase = smem_u32(smdyn);
    int tid = threadIdx.x, lane = tid & 31, wid = tid >> 5;
    int wm = wid & 3, wn = wid >> 2;
    int mBase = blockIdx.y * 128, nBase = blockIdx.x * 128;
    int lr = lane & 15, lh = lane >> 4;

    const __half* gA = g_A16 + (size_t)mBase * 512;
    const __half* gB = g_B16q + (size_t)nBase * 512;

    float acc[2][8][4];
#pragma unroll
    for (int i = 0; i < 2; i++)
#pragma unroll
        for (int j = 0; j < 8; j++)
#pragma unroll
            for (int c = 0; c < 4; c++) acc[i][j][c] = 0.f;

    // loader mapping: 1024 16B-transfers per tile; thread does 4 (A) + 4 (B)
    int r_ld = tid >> 1;            // 0..127 (two threads per row)
    int q2 = (tid & 1) * 4;          // 0 or 4 (16B units within row-half)
    // each thread loads 4 consecutive 16B units: covers 64 halves per row with 2 threads? 8 units/row of 64 halves
    // row has 64 halves = 8 x 16B units. thread covers units q2..q2+3.

    auto load_stage = [&](int ch, unsigned st) {
#pragma unroll
        for (int u = 0; u < 4; u++) {
            unsigned soff = (unsigned)r_ld * 144u + (q2 + u) * 16u;
            size_t goff = (size_t)r_ld * 512 + ch * 64 + (q2 + u) * 8;
            cpasync16(sbase + st + soff, gA + goff);
            cpasync16(sbase + st + 18432u + soff, gB + goff);
        }
        CP_COMMIT();
    };

    load_stage(0, 0u);

    for (int ch = 0; ch < 8; ch++) {
        unsigned st = (unsigned)(ch & 1) * 36864u;
        if (ch + 1 < 8) {
            load_stage(ch + 1, (unsigned)((ch + 1) & 1) * 36864u);
            asm volatile("cp.async.wait_group 1;" ::: "memory");
        } else {
            asm volatile("cp.async.wait_group 0;" ::: "memory");
        }
        __syncthreads();

        unsigned aA = sbase + st;
        unsigned aB = aA + 18432u;
#pragma unroll
        for (int ks = 0; ks < 4; ks++) {
            unsigned kc2 = (unsigned)(ks * 16 + lh * 8) * 2u;
            unsigned ah[2][4];
#pragma unroll
            for (int mi = 0; mi < 2; mi++) {
                unsigned rowA = (unsigned)(wm * 32 + mi * 16 + lr) * 144u;
                ldm4(ah[mi], aA + rowA + kc2);
            }
#pragma unroll
            for (int nt = 0; nt < 4; nt++) {
                unsigned rowB = (unsigned)(wn * 64 + nt * 16 + lr) * 144u;
                unsigned bf[4];
                ldm4(bf, aB + rowB + kc2);
#pragma unroll
                for (int mi = 0; mi < 2; mi++) {
#pragma unroll
                    for (int ns = 0; ns < 2; ns++)
                        mmaf16(acc[mi][nt * 2 + ns], ah[mi], bf[ns], bf[ns + 2]);
                }
            }
        }
        __syncthreads();
    }

    int r0 = mBase + wm * 32 + (lane >> 2);
    int sec = nBase >> 9;
    float sc = (sec == 0) ? SCALE : 1.f;
    __half* hdst = (sec == 0) ? g_qh : ((sec == 1) ? g_kh : g_vh);
    int h = ((nBase + wn * 64) >> 6) & 7;
#pragma unroll
    for (int mi = 0; mi < 2; mi++) {
#pragma unroll
        for (int jn = 0; jn < 8; jn++) {
            int d = jn * 8 + (lane & 3) * 2;
#pragma unroll
            for (int half = 0; half < 2; half++) {
                int gr = r0 + mi * 16 + half * 8;
                int bb = gr >> 13, n = gr & 8191;
                size_t off = ((size_t)(bb * 8 + h) * NSEQ + n) * 64 + d;
                *(__half2*)&hdst[off] = __floats2half2_rn(acc[mi][jn][half * 2] * sc,
                                                          acc[mi][jn][half * 2 + 1] * sc);
            }
        }
    }
}

// ================= mma.sync bf16 split GEMM (dense 512-K, cp.async double-buffered) =================
// mode 1: out = C + bout + xn (M=16384,N=512). mode 2: landmark q_l/k_l (M=512,N=1024).
__global__ __launch_bounds__(256) void gemm_mma_kernel(
    const __nv_bfloat16* __restrict__ BThi, const __nv_bfloat16* __restrict__ BTlo,
    int mode, const float* __restrict__ bout, float* __restrict__ outp) {
    extern __shared__ char smdyn[];
    unsigned sbase = smem_u32(smdyn);
    int tid = threadIdx.x, lane = tid & 31, wid = tid >> 5;
    int wm = wid & 3, wn = wid >> 2;
    int mBase = blockIdx.y * 128, nBase = blockIdx.x * 128;
    int lr = lane & 15, lh = lane >> 4;

    const __nv_bfloat16* gsrc[4];
    gsrc[0] = g_Ahi + (size_t)mBase * 512;
    gsrc[1] = g_Alo + (size_t)mBase * 512;
    gsrc[2] = BThi + (size_t)nBase * 512;
    gsrc[3] = BTlo + (size_t)nBase * 512;

    float acc[2][8][4];
#pragma unroll
    for (int i = 0; i < 2; i++)
#pragma unroll
        for (int j = 0; j < 8; j++)
#pragma unroll
            for (int c = 0; c < 4; c++) acc[i][j][c] = 0.f;

    int r_ld0 = tid >> 2, q_ld = tid & 3;
    unsigned so0 = (unsigned)r_ld0 * 80u + q_ld * 16u;
    unsigned so1 = (unsigned)(r_ld0 + 64) * 80u + q_ld * 16u;

    {
        size_t go0 = (size_t)r_ld0 * 512 + q_ld * 8;
        size_t go1 = (size_t)(r_ld0 + 64) * 512 + q_ld * 8;
#pragma unroll
        for (int a = 0; a < 4; a++) {
            cpasync16(sbase + a * 10240u + so0, gsrc[a] + go0);
            cpasync16(sbase + a * 10240u + so1, gsrc[a] + go1);
        }
        CP_COMMIT();
    }

    for (int ch = 0; ch < 16; ch++) {
        unsigned st = (unsigned)(ch & 1) * 40960u;
        if (ch + 1 < 16) {
            unsigned stn = (unsigned)((ch + 1) & 1) * 40960u;
            size_t go0 = (size_t)r_ld0 * 512 + (ch + 1) * 32 + q_ld * 8;
            size_t go1 = (size_t)(r_ld0 + 64) * 512 + (ch + 1) * 32 + q_ld * 8;
#pragma unroll
            for (int a = 0; a < 4; a++) {
                cpasync16(sbase + stn + a * 10240u + so0, gsrc[a] + go0);
                cpasync16(sbase + stn + a * 10240u + so1, gsrc[a] + go1);
            }
            CP_COMMIT();
            asm volatile("cp.async.wait_group 1;" ::: "memory");
        } else {
            asm volatile("cp.async.wait_group 0;" ::: "memory");
        }
        __syncthreads();

        unsigned aAh = sbase + st;
        unsigned aAl = aAh + 10240u;
        unsigned aBh = aAh + 20480u;
        unsigned aBl = aAh + 30720u;
#pragma unroll
        for (int ks = 0; ks < 2; ks++) {
            unsigned kc2 = (unsigned)(ks * 16 + lh * 8) * 2u;
            unsigned ah[2][4], al[2][4];
#pragma unroll
            for (int mi = 0; mi < 2; mi++) {
                unsigned rowA = (unsigned)(wm * 32 + mi * 16 + lr) * 80u;
                ldm4(ah[mi], aAh + rowA + kc2);
                ldm4(al[mi], aAl + rowA + kc2);
            }
#pragma unroll
            for (int nt = 0; nt < 4; nt++) {
                unsigned rowB = (unsigned)(wn * 64 + nt * 16 + lr) * 80u;
                unsigned bh[4], bl[4];
                ldm4(bh, aBh + rowB + kc2);
                ldm4(bl, aBl + rowB + kc2);
#pragma unroll
                for (int mi = 0; mi < 2; mi++) {
#pragma unroll
                    for (int ns = 0; ns < 2; ns++) {
                        float* cc = acc[mi][nt * 2 + ns];
                        mma16816(cc, ah[mi], bh[ns], bh[ns + 2]);
                        mma16816(cc, ah[mi], bl[ns], bl[ns + 2]);
                        mma16816(cc, al[mi], bh[ns], bh[ns + 2]);
                    }
                }
            }
        }
        __syncthreads();
    }

    int r0 = mBase + wm * 32 + (lane >> 2);
    if (mode == 1) {
#pragma unroll
        for (int mi = 0; mi < 2; mi++) {
#pragma unroll
            for (int jn = 0; jn < 8; jn++) {
                int gc = nBase + wn * 64 + jn * 8 + (lane & 3) * 2;
#pragma unroll
                for (int half = 0; half < 2; half++) {
                    int gr = r0 + mi * 16 + half * 8;
                    float2 bo = *(const float2*)&bout[gc];
                    float2 xv = *(const float2*)&g_xn[(size_t)gr * 512 + gc];
                    float2 o = make_float2(acc[mi][jn][half * 2] + bo.x + xv.x,
                                           acc[mi][jn][half * 2 + 1] + bo.y + xv.y);
                    *(float2*)&outp[(size_t)gr * 512 + gc] = o;
                }
            }
        }
    } else {
        // mode 2: landmark GEMM. rows: b*256+m (512), cols: q|k sections (1024)
        int sec = nBase >> 9;
        float sc = (sec == 0) ? SCALE : 1.f;
        float* dst = (sec == 0) ? g_ql : g_kl;
        __half* hdst = (sec == 0) ? g_qlh : g_klh;
        int h = ((nBase + wn * 64) >> 6) & 7;
#pragma unroll
        for (int mi = 0; mi < 2; mi++) {
#pragma unroll
            for (int jn = 0; jn < 8; jn++) {
                int d = jn * 8 + (lane & 3) * 2;
#pragma unroll
                for (int half = 0; half < 2; half++) {
                    int gr = r0 + mi * 16 + half * 8;
                    int bb = gr >> 8, m = gr & 255;
                    float2 o = make_float2(acc[mi][jn][half * 2] * sc,
                                           acc[mi][jn][half * 2 + 1] * sc);
                    size_t off = ((size_t)(bb * 8 + h) * MLM + m) * 64 + d;
                    *(float2*)&dst[off] = o;
                    *(__half2*)&hdst[off] = __floats2half2_rn(o.x, o.y);
                }
            }
        }
    }
}

// ================= attn2 = softmax(q_l k_l^T) =================
__global__ __launch_bounds__(256) void attn2_kernel() {
    int bh = blockIdx.x;
    int m = threadIdx.x;
    __shared__ float4 kls[1024];
    float4 q[16];
    const float4* qp = (const float4*)g_ql + (size_t)(bh * MLM + m) * 16;
#pragma unroll
    for (int i = 0; i < 16; i++) q[i] = qp[i];
    float sum = 0.f;
    float* arow = g_attn2 + (size_t)bh * 65536 + (size_t)m * 256;
    for (int tile = 0; tile < 4; tile++) {
        __syncthreads();
        const float4* src = (const float4*)g_kl + (size_t)(bh * MLM + tile * 64) * 16;
#pragma unroll
        for (int i = 0; i < 4; i++) kls[threadIdx.x + i * 256] = src[threadIdx.x + i * 256];
        __syncthreads();
        for (int j = 0; j < 64; j++) {
            const float4* kr = &kls[j * 16];
            float s = 0.f;
#pragma unroll
            for (int d = 0; d < 16; d++) {
                float4 a = q[d], b = kr[d];
                s += a.x * b.x + a.y * b.y + a.z * b.z + a.w * b.w;
            }
            float p = __expf(s);
            sum += p;
            arow[tile * 64 + j] = p;
        }
    }
    float inv = 1.f / sum;
    for (int j = 0; j < 256; j++) arow[j] *= inv;
}

// ================= max column-sum of attn2 =================
__global__ __launch_bounds__(256) void colmax_kernel() {
    int bh = blockIdx.x;
    int j = threadIdx.x;
    const float* a = g_attn2 + (size_t)bh * 65536;
    float s = 0.f;
    for (int m2 = 0; m2 < 256; m2++) s += a[m2 * 256 + j];
    __shared__ float red[256];
    red[j] = s;
    __syncthreads();
    for (int o = 128; o; o >>= 1) {
        if (j < o) red[j] = fmaxf(red[j], red[j + o]);
        __syncthreads();
    }
    if (j == 0) atomicMax(&g_maxc_bits, __float_as_int(red[0]));
}

__global__ void z0_kernel() {
    int idx = blockIdx.x * 256 + threadIdx.x;
    int bh = idx >> 16;
    int i = (idx >> 8) & 255;
    int j = idx & 255;
    float scale = 1.f / __int_as_float(g_maxc_bits);
    g_Za[idx] = g_attn2[(bh << 16) + (j << 8) + i] * scale;
}

// ================= buffer selector =================
__device__ __forceinline__ float* pickBuf(int id) {
    switch (id) {
        case 0: return g_attn2;
        case 1: return g_Y;
        case 2: return g_P;
        case 3: return g_Qm;
        case 4: return g_Za;
        case 5: return g_Zb;
        case 6: return g_W2;
        default: return g_W3;
    }
}

// ================= pinv batched GEMM on tensor cores =================
__global__ __launch_bounds__(256) void gemm_pinv_mma(int cId, int aId, int bId,
                                                     float beta, float sgn, float alpha) {
    __shared__ __align__(16) __nv_bfloat16 sAh[128][40];
    __shared__ __align__(16) __nv_bfloat16 sAl[128][40];
    __shared__ __align__(16) __nv_bfloat16 sBh[64][40];
    __shared__ __align__(16) __nv_bfloat16 sBl[64][40];

    int bh = blockIdx.z;
    int mBase = blockIdx.y * 128, nBase = blockIdx.x * 64;
    const float* A = pickBuf(aId) + (size_t)bh * 65536;
    const float* B = pickBuf(bId) + (size_t)bh * 65536;
    float*       C = pickBuf(cId) + (size_t)bh * 65536;

    int tid = threadIdx.x, lane = tid & 31, w = tid >> 5;
    int wm = w & 3, wn = w >> 2;
    int lr = lane & 15, lh = lane >> 4;

    float acc[2][4][4];
#pragma unroll
    for (int i = 0; i < 2; i++)
#pragma unroll
        for (int j = 0; j < 4; j++)
#pragma unroll
            for (int c = 0; c < 4; c++) acc[i][j][c] = 0.f;

    for (int ch = 0; ch < 8; ch++) {
        if (ch) __syncthreads();
#pragma unroll
        for (int i = 0; i < 4; i++) {
            int idx = tid + i * 256;
            int r = idx >> 3, c4 = (idx & 7) * 4;
            float4 v = *(const float4*)&A[(size_t)(mBase + r) * 256 + ch * 32 + c4];
            __nv_bfloat16 h0 = __float2bfloat16(v.x), h1 = __float2bfloat16(v.y);
            __nv_bfloat16 h2 = __float2bfloat16(v.z), h3 = __float2bfloat16(v.w);
            sAh[r][c4 + 0] = h0; sAh[r][c4 + 1] = h1;
            sAh[r][c4 + 2] = h2; sAh[r][c4 + 3] = h3;
            sAl[r][c4 + 0] = __float2bfloat16(v.x - __bfloat162float(h0));
            sAl[r][c4 + 1] = __float2bfloat16(v.y - __bfloat162float(h1));
            sAl[r][c4 + 2] = __float2bfloat16(v.z - __bfloat162float(h2));
            sAl[r][c4 + 3] = __float2bfloat16(v.w - __bfloat162float(h3));
        }
#pragma unroll
        for (int kl = 0; kl < 4; kl++) {
            int gk = ch * 32 + w * 4 + kl;
#pragma unroll
            for (int nh = 0; nh < 2; nh++) {
                int n = nh * 32 + lane;
                float v = B[(size_t)gk * 256 + nBase + n];
                v = sgn * v + ((gk == nBase + n) ? beta : 0.f);
                __nv_bfloat16 h = __float2bfloat16(v);
                sBh[n][w * 4 + kl] = h;
                sBl[n][w * 4 + kl] = __float2bfloat16(v - __bfloat162float(h));
            }
        }
        __syncthreads();
#pragma unroll
        for (int ks = 0; ks < 2; ks++) {
            int kc = ks * 16 + lh * 8;
            unsigned ah[2][4], al[2][4];
#pragma unroll
            for (int mi = 0; mi < 2; mi++) {
                int rowA = wm * 32 + mi * 16 + lr;
                ldm4(ah[mi], smem_u32(&sAh[rowA][kc]));
                ldm4(al[mi], smem_u32(&sAl[rowA][kc]));
            }
#pragma unroll
            for (int nt = 0; nt < 2; nt++) {
                int rowB = wn * 32 + nt * 16 + lr;
                unsigned bhf[4], blf[4];
                ldm4(bhf, smem_u32(&sBh[rowB][kc]));
                ldm4(blf, smem_u32(&sBl[rowB][kc]));
#pragma unroll
                for (int mi = 0; mi < 2; mi++) {
#pragma unroll
                    for (int ns = 0; ns < 2; ns++) {
                        float* cc = acc[mi][nt * 2 + ns];
                        mma16816(cc, ah[mi], bhf[ns], bhf[ns + 2]);
                        mma16816(cc, ah[mi], blf[ns], blf[ns + 2]);
                        mma16816(cc, al[mi], bhf[ns], bhf[ns + 2]);
                    }
                }
            }
        }
    }
#pragma unroll
    for (int mi = 0; mi < 2; mi++) {
#pragma unroll
        for (int jn = 0; jn < 4; jn++) {
            int gc = nBase + wn * 32 + jn * 8 + (lane & 3) * 2;
#pragma unroll
            for (int half = 0; half < 2; half++) {
                int gr = mBase + wm * 32 + mi * 16 + (lane >> 2) + half * 8;
                float2 o = make_float2(acc[mi][jn][half * 2] * alpha,
                                       acc[mi][jn][half * 2 + 1] * alpha);
                *(float2*)&C[(size_t)gr * 256 + gc] = o;
            }
        }
    }
}

// ================= batched per-bh GEMM (scalar, kept for W3) =================
__global__ __launch_bounds__(256) void gemm_bh_kernel(int cId, int aId, int bId, int Nn,
                                                      float beta, float sgn, float alpha) {
    int bh = blockIdx.z, mt = blockIdx.y, nt = blockIdx.x;
    const float* A  = pickBuf(aId) + (size_t)bh * 65536;
    const float* Bp = pickBuf(bId) + (size_t)bh * 256 * Nn;
    float*       C  = pickBuf(cId) + (size_t)bh * 256 * Nn;
    __shared__ float As[16][64];
    __shared__ float Bs[16][64];
    int tid = threadIdx.x;
    int ar = tid >> 2, ac = (tid & 3) * 4;
    int br = tid >> 4, bc = (tid & 15) * 4;
    int ty = tid >> 4, tx = tid & 15;
    float acc[4][4];
#pragma unroll
    for (int i = 0; i < 4; i++)
#pragma unroll
        for (int j = 0; j < 4; j++) acc[i][j] = 0.f;

    for (int k0 = 0; k0 < 256; k0 += 16) {
        float4 av = *(const float4*)&A[(size_t)(mt * 64 + ar) * 256 + k0 + ac];
        As[ac + 0][ar] = av.x; As[ac + 1][ar] = av.y;
        As[ac + 2][ar] = av.z; As[ac + 3][ar] = av.w;
        int gk = k0 + br;
        int gc = nt * 64 + bc;
        float4 bv = *(const float4*)&Bp[(size_t)gk * Nn + gc];
        bv.x = sgn * bv.x + (gk == gc + 0 ? beta : 0.f);
        bv.y = sgn * bv.y + (gk == gc + 1 ? beta : 0.f);
        bv.z = sgn * bv.z + (gk == gc + 2 ? beta : 0.f);
        bv.w = sgn * bv.w + (gk == gc + 3 ? beta : 0.f);
        *(float4*)&Bs[br][bc] = bv;
        __syncthreads();
#pragma unroll
        for (int kk = 0; kk < 16; kk++) {
            float4 a4 = *(const float4*)&As[kk][ty * 4];
            float4 b4 = *(const float4*)&Bs[kk][tx * 4];
            acc[0][0] += a4.x * b4.x; acc[0][1] += a4.x * b4.y; acc[0][2] += a4.x * b4.z; acc[0][3] += a4.x * b4.w;
            acc[1][0] += a4.y * b4.x; acc[1][1] += a4.y * b4.y; acc[1][2] += a4.y * b4.z; acc[1][3] += a4.y * b4.w;
            acc[2][0] += a4.z * b4.x; acc[2][1] += a4.z * b4.y; acc[2][2] += a4.z * b4.z; acc[2][3] += a4.z * b4.w;
            acc[3][0] += a4.w * b4.x; acc[3][1] += a4.w * b4.y; acc[3][2] += a4.w * b4.z; acc[3][3] += a4.w * b4.w;
        }
        __syncthreads();
    }
#pragma unroll
    for (int i = 0; i < 4; i++) {
        float4 o = make_float4(acc[i][0] * alpha, acc[i][1] * alpha,
                               acc[i][2] * alpha, acc[i][3] * alpha);
        *(float4*)&C[(size_t)(mt * 64 + ty * 4 + i) * Nn + nt * 64 + tx * 4] = o;
    }
}

// ================= flash W2 on tensor cores =================
__global__ __launch_bounds__(256) void flash_w2_mma() {
    __shared__ __align__(16) __half sql[128][72];
    __shared__ __align__(16) __half sk[64][72];
    __shared__ __align__(16) __half svT[64][72];

    int tid = threadIdx.x, lane = tid & 31, w = tid >> 5;
    int chunk = blockIdx.x, mblk = blockIdx.y, bh = blockIdx.z;
    int lr = lane & 15, lh = lane >> 4;

    const __half* qlh = g_qlh + (size_t)(bh * MLM + mblk * 128) * 64;
#pragma unroll
    for (int i = 0; i < 4; i++) {
        int idx = tid + i * 256;
        int r = idx >> 3, c = (idx & 7) * 8;
        *(uint4*)&sql[r][c] = *(const uint4*)&qlh[(size_t)r * 64 + c];
    }
    __syncthreads();
    unsigned qa[4][4];
#pragma unroll
    for (int ks = 0; ks < 4; ks++)
        ldm4(qa[ks], smem_u32(&sql[w * 16 + lr][ks * 16 + lh * 8]));

    float outacc[8][4];
#pragma unroll
    for (int i = 0; i < 8; i++)
#pragma unroll
        for (int c = 0; c < 4; c++) outacc[i][c] = 0.f;
    float rsA = 0.f, rsB = 0.f;

    const __half* kb = g_kh + (size_t)bh * NSEQ * 64;
    const __half* vb = g_vh + (size_t)bh * NSEQ * 64;

    for (int it = 0; it < 32; it++) {
        int s0 = chunk * 2048 + it * 64;
        __syncthreads();
#pragma unroll
        for (int i = 0; i < 2; i++) {
            int idx = tid + i * 256;
            int r = idx >> 3, c = (idx & 7) * 8;
            *(uint4*)&sk[r][c] = *(const uint4*)&kb[(size_t)(s0 + r) * 64 + c];
            uint4 vv = *(const uint4*)&vb[(size_t)(s0 + r) * 64 + c];
            __half vh[8];
            *(uint4*)vh = vv;
#pragma unroll
            for (int j = 0; j < 8; j++) svT[c + j][r] = vh[j];
        }
        __syncthreads();
        float sf[8][4];
#pragma unroll
        for (int i = 0; i < 8; i++)
#pragma unroll
            for (int c = 0; c < 4; c++) sf[i][c] = 0.f;
#pragma unroll
        for (int ks = 0; ks < 4; ks++) {
#pragma unroll
            for (int nf4 = 0; nf4 < 4; nf4++) {
                unsigned bbf[4];
                ldm4(bbf, smem_u32(&sk[nf4 * 16 + lr][ks * 16 + lh * 8]));
                mmaf16(sf[nf4 * 2], qa[ks], bbf[0], bbf[2]);
                mmaf16(sf[nf4 * 2 + 1], qa[ks], bbf[1], bbf[3]);
            }
        }
#pragma unroll
        for (int nf = 0; nf < 8; nf++) {
            sf[nf][0] = fexp(sf[nf][0]); sf[nf][1] = fexp(sf[nf][1]);
            sf[nf][2] = fexp(sf[nf][2]); sf[nf][3] = fexp(sf[nf][3]);
            rsA += sf[nf][0] + sf[nf][1];
            rsB += sf[nf][2] + sf[nf][3];
        }
#pragma unroll
        for (int kk = 0; kk < 4; kk++) {
            unsigned pa[4];
            pa[0] = packh2(sf[2 * kk][0], sf[2 * kk][1]);
            pa[1] = packh2(sf[2 * kk][2], sf[2 * kk][3]);
            pa[2] = packh2(sf[2 * kk + 1][0], sf[2 * kk + 1][1]);
            pa[3] = packh2(sf[2 * kk + 1][2], sf[2 * kk + 1][3]);
#pragma unroll
            for (int nf4 = 0; nf4 < 4; nf4++) {
                unsigned bbf[4];
                ldm4(bbf, smem_u32(&svT[nf4 * 16 + lr][kk * 16 + lh * 8]));
                mmaf16(outacc[nf4 * 2], pa, bbf[0], bbf[2]);
                mmaf16(outacc[nf4 * 2 + 1], pa, bbf[1], bbf[3]);
            }
        }
    }
    rsA += __shfl_xor_sync(0xffffffffu, rsA, 1);
    rsA += __shfl_xor_sync(0xffffffffu, rsA, 2);
    rsB += __shfl_xor_sync(0xffffffffu, rsB, 1);
    rsB += __shfl_xor_sync(0xffffffffu, rsB, 2);

    int rA = mblk * 128 + w * 16 + (lane >> 2);
    int rB = rA + 8;
    float* wpA = g_Wpart + (size_t)((bh * 4 + chunk) * MLM + rA) * 64;
    float* wpB = g_Wpart + (size_t)((bh * 4 + chunk) * MLM + rB) * 64;
#pragma unroll
    for (int nf = 0; nf < 8; nf++) {
        int d = nf * 8 + (lane & 3) * 2;
        *(float2*)&wpA[d] = make_float2(outacc[nf][0], outacc[nf][1]);
        *(float2*)&wpB[d] = make_float2(outacc[nf][2], outacc[nf][3]);
    }
    if ((lane & 3) == 0) {
        g_Spart[(bh * 4 + chunk) * MLM + rA] = rsA;
        g_Spart[(bh * 4 + chunk) * MLM + rB] = rsB;
    }
}

__global__ void combine_w2_kernel() {
    int idx = blockIdx.x * 256 + threadIdx.x;
    int bh = idx >> 14;
    int m = (idx >> 6) & 255;
    int d = idx & 63;
    float num = 0.f, den = 0.f;
#pragma unroll
    for (int c = 0; c < 4; c++) {
        num += g_Wpart[(size_t)((bh * 4 + c) * MLM + m) * 64 + d];
        den += g_Spart[(bh * 4 + c) * MLM + m];
    }
    g_W2[(bh * MLM + m) * 64 + d] = num / den;
}

// ================= attn1 + conv on tensor cores =================
__global__ __launch_bounds__(256) void attn1_mma(const float* __restrict__ convw) {
    extern __shared__ char smx[];
    __half (*sq)[72]  = (__half(*)[72])(smx);
    __half (*skl)[72] = (__half(*)[72])(smx + 18432);
    __half (*swT)[72] = (__half(*)[72])(smx + 27648);
    __half (*sv)[72]  = (__half(*)[72])(smx + 36864);
    float* cw = (float*)(smx + 59904);

    int tid = threadIdx.x, lane = tid & 31, w = tid >> 5;
    int ntile = blockIdx.x, bh = blockIdx.y;
    int h = bh & 7, bb2 = bh >> 3;
    int n0 = ntile * 128;
    int lr = lane & 15, lh = lane >> 4;

    if (tid < KSZ) cw[tid] = convw[h * KSZ + tid];

    const __half* qb = g_qh + ((size_t)bh * NSEQ + n0) * 64;
#pragma unroll
    for (int i = 0; i < 4; i++) {
        int idx = tid + i * 256;
        int r = idx >> 3, c = (idx & 7) * 8;
        *(uint4*)&sq[r][c] = *(const uint4*)&qb[(size_t)r * 64 + c];
    }
    const __half* vb2 = g_vh + (size_t)bh * NSEQ * 64;
#pragma unroll
    for (int i = 0; i < 5; i++) {
        int idx = tid + i * 256;
        int r = idx >> 3, c = (idx & 7) * 8;
        int gr = n0 - 16 + r;
        uint4 z = make_uint4(0u, 0u, 0u, 0u);
        if (gr >= 0 && gr < NSEQ) z = *(const uint4*)&vb2[(size_t)gr * 64 + c];
        *(uint4*)&sv[r][c] = z;
    }
    __syncthreads();

    unsigned qa[4][4];
#pragma unroll
    for (int ks = 0; ks < 4; ks++)
        ldm4(qa[ks], smem_u32(&sq[w * 16 + lr][ks * 16 + lh * 8]));

    float outacc[8][4];
#pragma unroll
    for (int i = 0; i < 8; i++)
#pragma unroll
        for (int c = 0; c < 4; c++) outacc[i][c] = 0.f;
    float rsA = 0.f, rsB = 0.f;

    const __half* klb = g_klh + (size_t)bh * MLM * 64;
    const __half* w3tb = g_W3T + (size_t)bh * 64 * 256;

    for (int lc = 0; lc < 4; lc++) {
        __syncthreads();
#pragma unroll
        for (int i = 0; i < 2; i++) {
            int idx = tid + i * 256;
            int r = idx >> 3, c = (idx & 7) * 8;
            *(uint4*)&skl[r][c] = *(const uint4*)&klb[(size_t)(lc * 64 + r) * 64 + c];
            *(uint4*)&swT[r][c] = *(const uint4*)&w3tb[(size_t)r * 256 + lc * 64 + c];
        }
        __syncthreads();
        float sf[8][4];
#pragma unroll
        for (int i = 0; i < 8; i++)
#pragma unroll
            for (int c = 0; c < 4; c++) sf[i][c] = 0.f;
#pragma unroll
        for (int ks = 0; ks < 4; ks++) {
#pragma unroll
            for (int nf4 = 0; nf4 < 4; nf4++) {
                unsigned bbf[4];
                ldm4(bbf, smem_u32(&skl[nf4 * 16 + lr][ks * 16 + lh * 8]));
                mmaf16(sf[nf4 * 2], qa[ks], bbf[0], bbf[2]);
                mmaf16(sf[nf4 * 2 + 1], qa[ks], bbf[1], bbf[3]);
            }
        }
#pragma unroll
        for (int nf = 0; nf < 8; nf++) {
            sf[nf][0] = fexp(sf[nf][0]); sf[nf][1] = fexp(sf[nf][1]);
            sf[nf][2] = fexp(sf[nf][2]); sf[nf][3] = fexp(sf[nf][3]);
            rsA += sf[nf][0] + sf[nf][1];
            rsB += sf[nf][2] + sf[nf][3];
        }
#pragma unroll
        for (int kk = 0; kk < 4; kk++) {
            unsigned pa[4];
            pa[0] = packh2(sf[2 * kk][0], sf[2 * kk][1]);
            pa[1] = packh2(sf[2 * kk][2], sf[2 * kk][3]);
            pa[2] = packh2(sf[2 * kk + 1][0], sf[2 * kk + 1][1]);
            pa[3] = packh2(sf[2 * kk + 1][2], sf[2 * kk + 1][3]);
#pragma unroll
            for (int nf4 = 0; nf4 < 4; nf4++) {
                unsigned bbf[4];
                ldm4(bbf, smem_u32(&swT[nf4 * 16 + lr][kk * 16 + lh * 8]));
                mmaf16(outacc[nf4 * 2], pa, bbf[0], bbf[2]);
                mmaf16(outacc[nf4 * 2 + 1], pa, bbf[1], bbf[3]);
            }
        }
    }
    rsA += __shfl_xor_sync(0xffffffffu, rsA, 1);
    rsA += __shfl_xor_sync(0xffffffffu, rsA, 2);
    rsB += __shfl_xor_sync(0xffffffffu, rsB, 1);
    rsB += __shfl_xor_sync(0xffffffffu, rsB, 2);
    float invA = 1.f / rsA, invB = 1.f / rsB;

    int lrA = w * 16 + (lane >> 2);
#pragma unroll
    for (int nf = 0; nf < 8; nf++) {
        int d = nf * 8 + (lane & 3) * 2;
        float a0 = 0.f, a1 = 0.f, b0 = 0.f, b1 = 0.f;
#pragma unroll
        for (int t = 0; t < KSZ; t++) {
            float wv = cw[t];
            float2 fA = __half22float2(*(__half2*)&sv[lrA + t][d]);
            float2 fB = __half22float2(*(__half2*)&sv[lrA + 8 + t][d]);
            a0 = fmaf(wv, fA.x, a0); a1 = fmaf(wv, fA.y, a1);
            b0 = fmaf(wv, fB.x, b0); b1 = fmaf(wv, fB.y, b1);
        }
        outacc[nf][0] = outacc[nf][0] * invA + a0;
        outacc[nf][1] = outacc[nf][1] * invA + a1;
        outacc[nf][2] = outacc[nf][2] * invB + b0;
        outacc[nf][3] = outacc[nf][3] * invB + b1;
    }

    int nA = n0 + lrA, nB = nA + 8;
    float* oA = g_outpre + (size_t)(bb2 * NSEQ + nA) * 512 + h * 64;
    float* oB = g_outpre + (size_t)(bb2 * NSEQ + nB) * 512 + h * 64;
#pragma unroll
    for (int nf = 0; nf < 8; nf++) {
        int d = nf * 8 + (lane & 3) * 2;
        *(float2*)&oA[d] = make_float2(outacc[nf][0], outacc[nf][1]);
        *(float2*)&oB[d] = make_float2(outacc[nf][2], outacc[nf][3]);
    }
}

// ================= host launcher =================
extern "C" void kernel_launch(void* const* d_in, const int* in_sizes, int n_in,
                              void* d_out, int out_size) {
    const float* x     = (const float*)d_in[0];
    const float* ln_g  = (const float*)d_in[1];
    const float* ln_b  = (const float*)d_in[2];
    const float* W_qkv = (const float*)d_in[3];
    const float* W_out = (const float*)d_in[4];
    const float* b_out = (const float*)d_in[5];
    const float* convw = (const float*)d_in[6];
    float* out = (float*)d_out;

    cudaFuncSetAttribute(attn1_mma, cudaFuncAttributeMaxDynamicSharedMemorySize, 60416);
    cudaFuncSetAttribute(gemm_mma_kernel, cudaFuncAttributeMaxDynamicSharedMemorySize, 81920);
    cudaFuncSetAttribute(gemm_qkv16_kernel, cudaFuncAttributeMaxDynamicSharedMemorySize, 73728);

    __nv_bfloat16 *bqh, *bql, *boh, *bol;
    cudaGetSymbolAddress((void**)&bqh, g_Bqh);
    cudaGetSymbolAddress((void**)&bql, g_Bql);
    cudaGetSymbolAddress((void**)&boh, g_Boh);
    cudaGetSymbolAddress((void**)&bol, g_Bol);
    float *xnp, *xnlmp, *opp;
    cudaGetSymbolAddress((void**)&xnp, g_xn);
    cudaGetSymbolAddress((void**)&xnlmp, g_xnlm);
    cudaGetSymbolAddress((void**)&opp, g_outpre);

    reset_kernel<<<1, 1>>>();
    ln_kernel<<<Bb * NSEQ, 128>>>(x, ln_g, ln_b);

    // fp16 conversions for qkv
    convA16_kernel<<<8192, 256>>>(xnp);
    convW16_kernel<<<dim3(48, 16), 1024>>>(W_qkv, 1536, (__half*)nullptr == nullptr ? (__half*)({__half* p; cudaGetSymbolAddress((void**)&p, g_B16q); p;}) : nullptr);

    // qkv GEMM: single-pass fp16
    gemm_qkv16_kernel<<<dim3(12, 128), 256, 73728>>>();

    // landmark path: xn group means -> bf16 hi/lo -> accurate small GEMM
    xnlm_kernel<<<1024, 256>>>();
    convA_kernel<<<256, 256>>>(xnlmp);
    convW_kernel<<<dim3(48, 16), 1024>>>(W_qkv, 1536, bqh, bql);
    gemm_mma_kernel<<<dim3(8, 4), 256, 81920>>>(bqh, bql, 2, nullptr, nullptr);

    attn2_kernel<<<16, 256>>>();
    colmax_kernel<<<16, 256>>>();
    z0_kernel<<<4096, 256>>>();

    int zc = 4, zn = 5;  // Za, Zb
    for (int it = 0; it < 6; it++) {
        gemm_pinv_mma<<<dim3(4, 2, 16), 256>>>(1, 0, zc, 0.f, 1.f, 1.f);
        gemm_pinv_mma<<<dim3(4, 2, 16), 256>>>(2, 1, 1, 7.f, -1.f, 1.f);
        gemm_pinv_mma<<<dim3(4, 2, 16), 256>>>(3, 1, 2, 15.f, -1.f, 1.f);
        gemm_pinv_mma<<<dim3(4, 2, 16), 256>>>(zn, zc, 3, 13.f, -1.f, 0.25f);
        int t = zc; zc = zn; zn = t;
    }

    flash_w2_mma<<<dim3(4, 2, 16), 256>>>();
    combine_w2_kernel<<<1024, 256>>>();
    gemm_bh_kernel<<<dim3(1, 4, 16), 256>>>(7, zc, 6, 64, 0.f, 1.f, 1.f);  // W3 = Z @ W2
    w3t_kernel<<<1024, 256>>>();
    attn1_mma<<<dim3(64, 16), 256, 60416>>>(convw);

    // out GEMM: 3-pass bf16 (accurate)
    convW_kernel<<<dim3(16, 16), 1024>>>(W_out, 512, boh, bol);
    convA_kernel<<<8192, 256>>>(opp);
    gemm_mma_kernel<<<dim3(4, 128), 256, 81920>>>(boh, bol, 1, b_out, out);
}

// round 9
// speedup vs baseline: 2.8911x; 1.0467x over previous
#include <cuda_runtime.h>
#include <cuda_bf16.h>
#include <cuda_fp16.h>

#define Bb    2
#define NSEQ  8192
#define DIMV  512
#define NH    8
#define BHn   16
#define DHd   64
#define MLM   256
#define LGRP  32
#define KSZ   33
#define PADc  16
#define SCALE 0.125f

// ================= static device scratch =================
__device__ float g_xn[(size_t)Bb * NSEQ * DIMV];
__device__ float g_xnlm[512 * 512];
__device__ float g_ql[BHn * MLM * DHd];
__device__ float g_kl[BHn * MLM * DHd];
__device__ float g_attn2[BHn * MLM * MLM];
__device__ float g_Y[BHn * MLM * MLM];
__device__ float g_P[BHn * MLM * MLM];
__device__ float g_Qm[BHn * MLM * MLM];
__device__ float g_Za[BHn * MLM * MLM];
__device__ float g_Zb[BHn * MLM * MLM];
__device__ float g_W2[BHn * MLM * DHd];
__device__ float g_W3[BHn * MLM * DHd];
__device__ float g_Wpart[(size_t)BHn * 4 * MLM * DHd];
__device__ float g_Spart[BHn * 4 * MLM];
__device__ float g_outpre[(size_t)Bb * NSEQ * DIMV];
__device__ int   g_maxc_bits;

// bf16 hi/lo buffers (landmark GEMM)
__device__ __nv_bfloat16 g_Ahi[512 * 512];
__device__ __nv_bfloat16 g_Alo[512 * 512];
__device__ __nv_bfloat16 g_Bqh[1536 * 512];
__device__ __nv_bfloat16 g_Bql[1536 * 512];

// fp16 buffers
__device__ __half g_A16[(size_t)Bb * NSEQ * DIMV];
__device__ __half g_B16q[1536 * 512];
__device__ __half g_B16o[512 * 512];
__device__ __half g_qh[(size_t)BHn * NSEQ * DHd];
__device__ __half g_kh[(size_t)BHn * NSEQ * DHd];
__device__ __half g_vh[(size_t)BHn * NSEQ * DHd];
__device__ __half g_qlh[BHn * MLM * DHd];
__device__ __half g_klh[BHn * MLM * DHd];
__device__ __half g_W3T[BHn * DHd * MLM];

__global__ void reset_kernel() { g_maxc_bits = 0; }

// ================= mma.sync helpers =================
__device__ __forceinline__ unsigned smem_u32(const void* p) {
    unsigned a;
    asm("{ .reg .u64 t; cvta.to.shared.u64 t, %1; cvt.u32.u64 %0, t; }" : "=r"(a) : "l"(p));
    return a;
}
__device__ __forceinline__ void ldm4(unsigned* r, unsigned addr) {
    asm volatile("ldmatrix.sync.aligned.m8n8.x4.shared.b16 {%0,%1,%2,%3}, [%4];"
        : "=r"(r[0]), "=r"(r[1]), "=r"(r[2]), "=r"(r[3]) : "r"(addr));
}
__device__ __forceinline__ void mma16816(float* c, const unsigned* a, unsigned b0, unsigned b1) {
    asm volatile("mma.sync.aligned.m16n8k16.row.col.f32.bf16.bf16.f32 "
        "{%0,%1,%2,%3}, {%4,%5,%6,%7}, {%8,%9}, {%0,%1,%2,%3};"
        : "+f"(c[0]), "+f"(c[1]), "+f"(c[2]), "+f"(c[3])
        : "r"(a[0]), "r"(a[1]), "r"(a[2]), "r"(a[3]), "r"(b0), "r"(b1));
}
__device__ __forceinline__ void mmaf16(float* c, const unsigned* a, unsigned b0, unsigned b1) {
    asm volatile("mma.sync.aligned.m16n8k16.row.col.f32.f16.f16.f32 "
        "{%0,%1,%2,%3}, {%4,%5,%6,%7}, {%8,%9}, {%0,%1,%2,%3};"
        : "+f"(c[0]), "+f"(c[1]), "+f"(c[2]), "+f"(c[3])
        : "r"(a[0]), "r"(a[1]), "r"(a[2]), "r"(a[3]), "r"(b0), "r"(b1));
}
__device__ __forceinline__ void cpasync16(unsigned dst, const void* src) {
    asm volatile("cp.async.cg.shared.global [%0], [%1], 16;" :: "r"(dst), "l"(src));
}
#define CP_COMMIT() asm volatile("cp.async.commit_group;" ::: "memory")
__device__ __forceinline__ unsigned packh2(float a, float b) {
    __half2 h = __floats2half2_rn(a, b);
    return *(unsigned*)&h;
}
__device__ __forceinline__ float fexp(float x) {
    float t = x * 1.44269504f;
    float r = rintf(t);
    float f = t - r;
    float p = 1.33336e-3f;
    p = fmaf(p, f, 9.61813e-3f);
    p = fmaf(p, f, 5.55041e-2f);
    p = fmaf(p, f, 2.40226507e-1f);
    p = fmaf(p, f, 6.93147181e-1f);
    p = fmaf(p, f, 1.0f);
    int e = (int)r;
    return p * __int_as_float((e + 127) << 23);
}

// ================= layernorm =================
__global__ __launch_bounds__(128) void ln_kernel(const float* __restrict__ x,
                                                 const float* __restrict__ gam,
                                                 const float* __restrict__ bet) {
    int row = blockIdx.x;
    int tid = threadIdx.x;
    float4 v = ((const float4*)x)[(size_t)row * 128 + tid];
    float s1 = v.x + v.y + v.z + v.w;
    float s2 = v.x * v.x + v.y * v.y + v.z * v.z + v.w * v.w;
#pragma unroll
    for (int o = 16; o; o >>= 1) {
        s1 += __shfl_xor_sync(0xffffffffu, s1, o);
        s2 += __shfl_xor_sync(0xffffffffu, s2, o);
    }
    __shared__ float r1[4], r2[4];
    int w = tid >> 5;
    if ((tid & 31) == 0) { r1[w] = s1; r2[w] = s2; }
    __syncthreads();
    s1 = r1[0] + r1[1] + r1[2] + r1[3];
    s2 = r2[0] + r2[1] + r2[2] + r2[3];
    float mean = s1 * (1.f / 512.f);
    float var  = s2 * (1.f / 512.f) - mean * mean;
    float rstd = rsqrtf(var + 1e-5f);
    float4 g4 = ((const float4*)gam)[tid];
    float4 b4 = ((const float4*)bet)[tid];
    float4 o;
    o.x = (v.x - mean) * rstd * g4.x + b4.x;
    o.y = (v.y - mean) * rstd * g4.y + b4.y;
    o.z = (v.z - mean) * rstd * g4.z + b4.z;
    o.w = (v.w - mean) * rstd * g4.w + b4.w;
    ((float4*)g_xn)[(size_t)row * 128 + tid] = o;
}

// ================= group means of xn (landmark pre-image) =================
__global__ void xnlm_kernel() {
    int idx = blockIdx.x * 256 + threadIdx.x;
    int row = idx >> 9;
    int d = idx & 511;
    int b = row >> 8, m = row & 255;
    const float* p = g_xn + ((size_t)(b * NSEQ) + m * LGRP) * DIMV + d;
    float s = 0.f;
#pragma unroll
    for (int i = 0; i < LGRP; i++) s += p[(size_t)i * DIMV];
    g_xnlm[idx] = s * (1.f / LGRP);
}

// ================= converters =================
__global__ __launch_bounds__(256) void convA_kernel(const float* __restrict__ src) {
    size_t i4 = ((size_t)blockIdx.x * 256 + threadIdx.x) * 4;
    float4 v = *(const float4*)(src + i4);
    __nv_bfloat16 h0 = __float2bfloat16(v.x), h1 = __float2bfloat16(v.y);
    __nv_bfloat16 h2 = __float2bfloat16(v.z), h3 = __float2bfloat16(v.w);
    __nv_bfloat16 l0 = __float2bfloat16(v.x - __bfloat162float(h0));
    __nv_bfloat16 l1 = __float2bfloat16(v.y - __bfloat162float(h1));
    __nv_bfloat16 l2 = __float2bfloat16(v.z - __bfloat162float(h2));
    __nv_bfloat16 l3 = __float2bfloat16(v.w - __bfloat162float(h3));
    __nv_bfloat162* ph = (__nv_bfloat162*)(g_Ahi + i4);
    __nv_bfloat162* pl = (__nv_bfloat162*)(g_Alo + i4);
    ph[0] = __nv_bfloat162(h0, h1); ph[1] = __nv_bfloat162(h2, h3);
    pl[0] = __nv_bfloat162(l0, l1); pl[1] = __nv_bfloat162(l2, l3);
}

__global__ __launch_bounds__(256) void convA16_kernel(const float* __restrict__ src) {
    size_t i4 = ((size_t)blockIdx.x * 256 + threadIdx.x) * 4;
    float4 v = *(const float4*)(src + i4);
    __half2* ph = (__half2*)(g_A16 + i4);
    ph[0] = __floats2half2_rn(v.x, v.y);
    ph[1] = __floats2half2_rn(v.z, v.w);
}

__global__ __launch_bounds__(1024) void convW_kernel(const float* __restrict__ W, int N,
                                                     __nv_bfloat16* __restrict__ BThi,
                                                     __nv_bfloat16* __restrict__ BTlo) {
    __shared__ float sh[32][33];
    int n0 = blockIdx.x * 32, k0 = blockIdx.y * 32;
    int tx = threadIdx.x & 31, ty = threadIdx.x >> 5;
    sh[ty][tx] = W[(size_t)(k0 + ty) * N + n0 + tx];
    __syncthreads();
    float x = sh[tx][ty];
    __nv_bfloat16 h = __float2bfloat16(x);
    __nv_bfloat16 l = __float2bfloat16(x - __bfloat162float(h));
    BThi[(size_t)(n0 + ty) * 512 + k0 + tx] = h;
    BTlo[(size_t)(n0 + ty) * 512 + k0 + tx] = l;
}

__global__ __launch_bounds__(1024) void convW16_kernel(const float* __restrict__ W, int N,
                                                       __half* __restrict__ BT) {
    __shared__ float sh[32][33];
    int n0 = blockIdx.x * 32, k0 = blockIdx.y * 32;
    int tx = threadIdx.x & 31, ty = threadIdx.x >> 5;
    sh[ty][tx] = W[(size_t)(k0 + ty) * N + n0 + tx];
    __syncthreads();
    BT[(size_t)(n0 + ty) * 512 + k0 + tx] = __float2half(sh[tx][ty]);
}

// W3 -> W3T fp16 [bh][d][m]
__global__ void w3t_kernel() {
    int idx = blockIdx.x * 256 + threadIdx.x;
    int bh = idx >> 14;
    int m = (idx >> 6) & 255;
    int d = idx & 63;
    float v = g_W3[(bh * 256 + m) * 64 + d];
    g_W3T[((size_t)bh * 64 + d) * 256 + m] = __float2half(v);
}

// ================= fp16 single-pass dense GEMM (cp.async double-buffered) =================
// C[M,128-tile] = A16 @ BT^T. mode 0: qkv scatter (fp16 out). mode 1: out = C + bout + xn.
// dynamic smem: 2 stages x 36864B; per stage A@0 (128x72 half), B@18432.
__global__ __launch_bounds__(256) void gemm16_kernel(
    const __half* __restrict__ gBbase, int mode,
    const float* __restrict__ bout, float* __restrict__ outp) {
    extern __shared__ char smdyn[];
    unsigned sbase = smem_u32(smdyn);
    int tid = threadIdx.x, lane = tid & 31, wid = tid >> 5;
    int wm = wid & 3, wn = wid >> 2;
    int mBase = blockIdx.y * 128, nBase = blockIdx.x * 128;
    int lr = lane & 15, lh = lane >> 4;

    const __half* gA = g_A16 + (size_t)mBase * 512;
    const __half* gB = gBbase + (size_t)nBase * 512;

    float acc[2][8][4];
#pragma unroll
    for (int i = 0; i < 2; i++)
#pragma unroll
        for (int j = 0; j < 8; j++)
#pragma unroll
            for (int c = 0; c < 4; c++) acc[i][j][c] = 0.f;

    int r_ld = tid >> 1;
    int q2 = (tid & 1) * 4;

    auto load_stage = [&](int ch, unsigned st) {
#pragma unroll
        for (int u = 0; u < 4; u++) {
            unsigned soff = (unsigned)r_ld * 144u + (q2 + u) * 16u;
            size_t goff = (size_t)r_ld * 512 + ch * 64 + (q2 + u) * 8;
            cpasync16(sbase + st + soff, gA + goff);
            cpasync16(sbase + st + 18432u + soff, gB + goff);
        }
        CP_COMMIT();
    };

    load_stage(0, 0u);

    for (int ch = 0; ch < 8; ch++) {
        unsigned st = (unsigned)(ch & 1) * 36864u;
        if (ch + 1 < 8) {
            load_stage(ch + 1, (unsigned)((ch + 1) & 1) * 36864u);
            asm volatile("cp.async.wait_group 1;" ::: "memory");
        } else {
            asm volatile("cp.async.wait_group 0;" ::: "memory");
        }
        __syncthreads();

        unsigned aA = sbase + st;
        unsigned aB = aA + 18432u;
#pragma unroll
        for (int ks = 0; ks < 4; ks++) {
            unsigned kc2 = (unsigned)(ks * 16 + lh * 8) * 2u;
            unsigned ah[2][4];
#pragma unroll
            for (int mi = 0; mi < 2; mi++) {
                unsigned rowA = (unsigned)(wm * 32 + mi * 16 + lr) * 144u;
                ldm4(ah[mi], aA + rowA + kc2);
            }
#pragma unroll
            for (int nt = 0; nt < 4; nt++) {
                unsigned rowB = (unsigned)(wn * 64 + nt * 16 + lr) * 144u;
                unsigned bf[4];
                ldm4(bf, aB + rowB + kc2);
#pragma unroll
                for (int mi = 0; mi < 2; mi++) {
#pragma unroll
                    for (int ns = 0; ns < 2; ns++)
                        mmaf16(acc[mi][nt * 2 + ns], ah[mi], bf[ns], bf[ns + 2]);
                }
            }
        }
        __syncthreads();
    }

    int r0 = mBase + wm * 32 + (lane >> 2);
    if (mode == 0) {
        int sec = nBase >> 9;
        float sc = (sec == 0) ? SCALE : 1.f;
        __half* hdst = (sec == 0) ? g_qh : ((sec == 1) ? g_kh : g_vh);
        int h = ((nBase + wn * 64) >> 6) & 7;
#pragma unroll
        for (int mi = 0; mi < 2; mi++) {
#pragma unroll
            for (int jn = 0; jn < 8; jn++) {
                int d = jn * 8 + (lane & 3) * 2;
#pragma unroll
                for (int half = 0; half < 2; half++) {
                    int gr = r0 + mi * 16 + half * 8;
                    int bb = gr >> 13, n = gr & 8191;
                    size_t off = ((size_t)(bb * 8 + h) * NSEQ + n) * 64 + d;
                    *(__half2*)&hdst[off] = __floats2half2_rn(acc[mi][jn][half * 2] * sc,
                                                              acc[mi][jn][half * 2 + 1] * sc);
                }
            }
        }
    } else {
#pragma unroll
        for (int mi = 0; mi < 2; mi++) {
#pragma unroll
            for (int jn = 0; jn < 8; jn++) {
                int gc = nBase + wn * 64 + jn * 8 + (lane & 3) * 2;
#pragma unroll
                for (int half = 0; half < 2; half++) {
                    int gr = r0 + mi * 16 + half * 8;
                    float2 bo = *(const float2*)&bout[gc];
                    float2 xv = *(const float2*)&g_xn[(size_t)gr * 512 + gc];
                    float2 o = make_float2(acc[mi][jn][half * 2] + bo.x + xv.x,
                                           acc[mi][jn][half * 2 + 1] + bo.y + xv.y);
                    *(float2*)&outp[(size_t)gr * 512 + gc] = o;
                }
            }
        }
    }
}

// ================= bf16 split landmark GEMM (M=512, N=1024) =================
__global__ __launch_bounds__(256) void gemm_lm_kernel(
    const __nv_bfloat16* __restrict__ BThi, const __nv_bfloat16* __restrict__ BTlo) {
    extern __shared__ char smdyn[];
    unsigned sbase = smem_u32(smdyn);
    int tid = threadIdx.x, lane = tid & 31, wid = tid >> 5;
    int wm = wid & 3, wn = wid >> 2;
    int mBase = blockIdx.y * 128, nBase = blockIdx.x * 128;
    int lr = lane & 15, lh = lane >> 4;

    const __nv_bfloat16* gsrc[4];
    gsrc[0] = g_Ahi + (size_t)mBase * 512;
    gsrc[1] = g_Alo + (size_t)mBase * 512;
    gsrc[2] = BThi + (size_t)nBase * 512;
    gsrc[3] = BTlo + (size_t)nBase * 512;

    float acc[2][8][4];
#pragma unroll
    for (int i = 0; i < 2; i++)
#pragma unroll
        for (int j = 0; j < 8; j++)
#pragma unroll
            for (int c = 0; c < 4; c++) acc[i][j][c] = 0.f;

    int r_ld0 = tid >> 2, q_ld = tid & 3;
    unsigned so0 = (unsigned)r_ld0 * 80u + q_ld * 16u;
    unsigned so1 = (unsigned)(r_ld0 + 64) * 80u + q_ld * 16u;

    {
        size_t go0 = (size_t)r_ld0 * 512 + q_ld * 8;
        size_t go1 = (size_t)(r_ld0 + 64) * 512 + q_ld * 8;
#pragma unroll
        for (int a = 0; a < 4; a++) {
            cpasync16(sbase + a * 10240u + so0, gsrc[a] + go0);
            cpasync16(sbase + a * 10240u + so1, gsrc[a] + go1);
        }
        CP_COMMIT();
    }

    for (int ch = 0; ch < 16; ch++) {
        unsigned st = (unsigned)(ch & 1) * 40960u;
        if (ch + 1 < 16) {
            unsigned stn = (unsigned)((ch + 1) & 1) * 40960u;
            size_t go0 = (size_t)r_ld0 * 512 + (ch + 1) * 32 + q_ld * 8;
            size_t go1 = (size_t)(r_ld0 + 64) * 512 + (ch + 1) * 32 + q_ld * 8;
#pragma unroll
            for (int a = 0; a < 4; a++) {
                cpasync16(sbase + stn + a * 10240u + so0, gsrc[a] + go0);
                cpasync16(sbase + stn + a * 10240u + so1, gsrc[a] + go1);
            }
            CP_COMMIT();
            asm volatile("cp.async.wait_group 1;" ::: "memory");
        } else {
            asm volatile("cp.async.wait_group 0;" ::: "memory");
        }
        __syncthreads();

        unsigned aAh = sbase + st;
        unsigned aAl = aAh + 10240u;
        unsigned aBh = aAh + 20480u;
        unsigned aBl = aAh + 30720u;
#pragma unroll
        for (int ks = 0; ks < 2; ks++) {
            unsigned kc2 = (unsigned)(ks * 16 + lh * 8) * 2u;
            unsigned ah[2][4], al[2][4];
#pragma unroll
            for (int mi = 0; mi < 2; mi++) {
                unsigned rowA = (unsigned)(wm * 32 + mi * 16 + lr) * 80u;
                ldm4(ah[mi], aAh + rowA + kc2);
                ldm4(al[mi], aAl + rowA + kc2);
            }
#pragma unroll
            for (int nt = 0; nt < 4; nt++) {
                unsigned rowB = (unsigned)(wn * 64 + nt * 16 + lr) * 80u;
                unsigned bh[4], bl[4];
                ldm4(bh, aBh + rowB + kc2);
                ldm4(bl, aBl + rowB + kc2);
#pragma unroll
                for (int mi = 0; mi < 2; mi++) {
#pragma unroll
                    for (int ns = 0; ns < 2; ns++) {
                        float* cc = acc[mi][nt * 2 + ns];
                        mma16816(cc, ah[mi], bh[ns], bh[ns + 2]);
                        mma16816(cc, ah[mi], bl[ns], bl[ns + 2]);
                        mma16816(cc, al[mi], bh[ns], bh[ns + 2]);
                    }
                }
            }
        }
        __syncthreads();
    }

    int r0 = mBase + wm * 32 + (lane >> 2);
    int sec = nBase >> 9;
    float sc = (sec == 0) ? SCALE : 1.f;
    float* dst = (sec == 0) ? g_ql : g_kl;
    __half* hdst = (sec == 0) ? g_qlh : g_klh;
    int h = ((nBase + wn * 64) >> 6) & 7;
#pragma unroll
    for (int mi = 0; mi < 2; mi++) {
#pragma unroll
        for (int jn = 0; jn < 8; jn++) {
            int d = jn * 8 + (lane & 3) * 2;
#pragma unroll
            for (int half = 0; half < 2; half++) {
                int gr = r0 + mi * 16 + half * 8;
                int bb = gr >> 8, m = gr & 255;
                float2 o = make_float2(acc[mi][jn][half * 2] * sc,
                                       acc[mi][jn][half * 2 + 1] * sc);
                size_t off = ((size_t)(bb * 8 + h) * MLM + m) * 64 + d;
                *(float2*)&dst[off] = o;
                *(__half2*)&hdst[off] = __floats2half2_rn(o.x, o.y);
            }
        }
    }
}

// ================= attn2 = softmax(q_l k_l^T) =================
__global__ __launch_bounds__(256) void attn2_kernel() {
    int bh = blockIdx.x;
    int m = threadIdx.x;
    __shared__ float4 kls[1024];
    float4 q[16];
    const float4* qp = (const float4*)g_ql + (size_t)(bh * MLM + m) * 16;
#pragma unroll
    for (int i = 0; i < 16; i++) q[i] = qp[i];
    float sum = 0.f;
    float* arow = g_attn2 + (size_t)bh * 65536 + (size_t)m * 256;
    for (int tile = 0; tile < 4; tile++) {
        __syncthreads();
        const float4* src = (const float4*)g_kl + (size_t)(bh * MLM + tile * 64) * 16;
#pragma unroll
        for (int i = 0; i < 4; i++) kls[threadIdx.x + i * 256] = src[threadIdx.x + i * 256];
        __syncthreads();
        for (int j = 0; j < 64; j++) {
            const float4* kr = &kls[j * 16];
            float s = 0.f;
#pragma unroll
            for (int d = 0; d < 16; d++) {
                float4 a = q[d], b = kr[d];
                s += a.x * b.x + a.y * b.y + a.z * b.z + a.w * b.w;
            }
            float p = __expf(s);
            sum += p;
            arow[tile * 64 + j] = p;
        }
    }
    float inv = 1.f / sum;
    for (int j = 0; j < 256; j++) arow[j] *= inv;
}

// ================= max column-sum of attn2 =================
__global__ __launch_bounds__(256) void colmax_kernel() {
    int bh = blockIdx.x;
    int j = threadIdx.x;
    const float* a = g_attn2 + (size_t)bh * 65536;
    float s = 0.f;
    for (int m2 = 0; m2 < 256; m2++) s += a[m2 * 256 + j];
    __shared__ float red[256];
    red[j] = s;
    __syncthreads();
    for (int o = 128; o; o >>= 1) {
        if (j < o) red[j] = fmaxf(red[j], red[j + o]);
        __syncthreads();
    }
    if (j == 0) atomicMax(&g_maxc_bits, __float_as_int(red[0]));
}

__global__ void z0_kernel() {
    int idx = blockIdx.x * 256 + threadIdx.x;
    int bh = idx >> 16;
    int i = (idx >> 8) & 255;
    int j = idx & 255;
    float scale = 1.f / __int_as_float(g_maxc_bits);
    g_Za[idx] = g_attn2[(bh << 16) + (j << 8) + i] * scale;
}

// ================= buffer selector =================
__device__ __forceinline__ float* pickBuf(int id) {
    switch (id) {
        case 0: return g_attn2;
        case 1: return g_Y;
        case 2: return g_P;
        case 3: return g_Qm;
        case 4: return g_Za;
        case 5: return g_Zb;
        case 6: return g_W2;
        default: return g_W3;
    }
}

// ================= pinv batched GEMM on tensor cores (1 or 3 passes) =================
__global__ __launch_bounds__(256) void gemm_pinv_mma(int cId, int aId, int bId,
                                                     float beta, float sgn, float alpha,
                                                     int passes) {
    __shared__ __align__(16) __nv_bfloat16 sAh[128][40];
    __shared__ __align__(16) __nv_bfloat16 sAl[128][40];
    __shared__ __align__(16) __nv_bfloat16 sBh[64][40];
    __shared__ __align__(16) __nv_bfloat16 sBl[64][40];

    int bh = blockIdx.z;
    int mBase = blockIdx.y * 128, nBase = blockIdx.x * 64;
    const float* A = pickBuf(aId) + (size_t)bh * 65536;
    const float* B = pickBuf(bId) + (size_t)bh * 65536;
    float*       C = pickBuf(cId) + (size_t)bh * 65536;

    int tid = threadIdx.x, lane = tid & 31, w = tid >> 5;
    int wm = w & 3, wn = w >> 2;
    int lr = lane & 15, lh = lane >> 4;
    bool full = (passes == 3);

    float acc[2][4][4];
#pragma unroll
    for (int i = 0; i < 2; i++)
#pragma unroll
        for (int j = 0; j < 4; j++)
#pragma unroll
            for (int c = 0; c < 4; c++) acc[i][j][c] = 0.f;

    for (int ch = 0; ch < 8; ch++) {
        if (ch) __syncthreads();
#pragma unroll
        for (int i = 0; i < 4; i++) {
            int idx = tid + i * 256;
            int r = idx >> 3, c4 = (idx & 7) * 4;
            float4 v = *(const float4*)&A[(size_t)(mBase + r) * 256 + ch * 32 + c4];
            __nv_bfloat16 h0 = __float2bfloat16(v.x), h1 = __float2bfloat16(v.y);
            __nv_bfloat16 h2 = __float2bfloat16(v.z), h3 = __float2bfloat16(v.w);
            sAh[r][c4 + 0] = h0; sAh[r][c4 + 1] = h1;
            sAh[r][c4 + 2] = h2; sAh[r][c4 + 3] = h3;
            if (full) {
                sAl[r][c4 + 0] = __float2bfloat16(v.x - __bfloat162float(h0));
                sAl[r][c4 + 1] = __float2bfloat16(v.y - __bfloat162float(h1));
                sAl[r][c4 + 2] = __float2bfloat16(v.z - __bfloat162float(h2));
                sAl[r][c4 + 3] = __float2bfloat16(v.w - __bfloat162float(h3));
            }
        }
#pragma unroll
        for (int kl = 0; kl < 4; kl++) {
            int gk = ch * 32 + w * 4 + kl;
#pragma unroll
            for (int nh = 0; nh < 2; nh++) {
                int n = nh * 32 + lane;
                float v = B[(size_t)gk * 256 + nBase + n];
                v = sgn * v + ((gk == nBase + n) ? beta : 0.f);
                __nv_bfloat16 h = __float2bfloat16(v);
                sBh[n][w * 4 + kl] = h;
                if (full) sBl[n][w * 4 + kl] = __float2bfloat16(v - __bfloat162float(h));
            }
        }
        __syncthreads();
#pragma unroll
        for (int ks = 0; ks < 2; ks++) {
            int kc = ks * 16 + lh * 8;
            unsigned ah[2][4], al[2][4];
#pragma unroll
            for (int mi = 0; mi < 2; mi++) {
                int rowA = wm * 32 + mi * 16 + lr;
                ldm4(ah[mi], smem_u32(&sAh[rowA][kc]));
                if (full) ldm4(al[mi], smem_u32(&sAl[rowA][kc]));
            }
#pragma unroll
            for (int nt = 0; nt < 2; nt++) {
                int rowB = wn * 32 + nt * 16 + lr;
                unsigned bhf[4], blf[4];
                ldm4(bhf, smem_u32(&sBh[rowB][kc]));
                if (full) ldm4(blf, smem_u32(&sBl[rowB][kc]));
#pragma unroll
                for (int mi = 0; mi < 2; mi++) {
#pragma unroll
                    for (int ns = 0; ns < 2; ns++) {
                        float* cc = acc[mi][nt * 2 + ns];
                        mma16816(cc, ah[mi], bhf[ns], bhf[ns + 2]);
                        if (full) {
                            mma16816(cc, ah[mi], blf[ns], blf[ns + 2]);
                            mma16816(cc, al[mi], bhf[ns], bhf[ns + 2]);
                        }
                    }
                }
            }
        }
    }
#pragma unroll
    for (int mi = 0; mi < 2; mi++) {
#pragma unroll
        for (int jn = 0; jn < 4; jn++) {
            int gc = nBase + wn * 32 + jn * 8 + (lane & 3) * 2;
#pragma unroll
            for (int half = 0; half < 2; half++) {
                int gr = mBase + wm * 32 + mi * 16 + (lane >> 2) + half * 8;
                float2 o = make_float2(acc[mi][jn][half * 2] * alpha,
                                       acc[mi][jn][half * 2 + 1] * alpha);
                *(float2*)&C[(size_t)gr * 256 + gc] = o;
            }
        }
    }
}

// ================= batched per-bh GEMM (scalar, kept for W3) =================
__global__ __launch_bounds__(256) void gemm_bh_kernel(int cId, int aId, int bId, int Nn,
                                                      float beta, float sgn, float alpha) {
    int bh = blockIdx.z, mt = blockIdx.y, nt = blockIdx.x;
    const float* A  = pickBuf(aId) + (size_t)bh * 65536;
    const float* Bp = pickBuf(bId) + (size_t)bh * 256 * Nn;
    float*       C  = pickBuf(cId) + (size_t)bh * 256 * Nn;
    __shared__ float As[16][64];
    __shared__ float Bs[16][64];
    int tid = threadIdx.x;
    int ar = tid >> 2, ac = (tid & 3) * 4;
    int br = tid >> 4, bc = (tid & 15) * 4;
    int ty = tid >> 4, tx = tid & 15;
    float acc[4][4];
#pragma unroll
    for (int i = 0; i < 4; i++)
#pragma unroll
        for (int j = 0; j < 4; j++) acc[i][j] = 0.f;

    for (int k0 = 0; k0 < 256; k0 += 16) {
        float4 av = *(const float4*)&A[(size_t)(mt * 64 + ar) * 256 + k0 + ac];
        As[ac + 0][ar] = av.x; As[ac + 1][ar] = av.y;
        As[ac + 2][ar] = av.z; As[ac + 3][ar] = av.w;
        int gk = k0 + br;
        int gc = nt * 64 + bc;
        float4 bv = *(const float4*)&Bp[(size_t)gk * Nn + gc];
        bv.x = sgn * bv.x + (gk == gc + 0 ? beta : 0.f);
        bv.y = sgn * bv.y + (gk == gc + 1 ? beta : 0.f);
        bv.z = sgn * bv.z + (gk == gc + 2 ? beta : 0.f);
        bv.w = sgn * bv.w + (gk == gc + 3 ? beta : 0.f);
        *(float4*)&Bs[br][bc] = bv;
        __syncthreads();
#pragma unroll
        for (int kk = 0; kk < 16; kk++) {
            float4 a4 = *(const float4*)&As[kk][ty * 4];
            float4 b4 = *(const float4*)&Bs[kk][tx * 4];
            acc[0][0] += a4.x * b4.x; acc[0][1] += a4.x * b4.y; acc[0][2] += a4.x * b4.z; acc[0][3] += a4.x * b4.w;
            acc[1][0] += a4.y * b4.x; acc[1][1] += a4.y * b4.y; acc[1][2] += a4.y * b4.z; acc[1][3] += a4.y * b4.w;
            acc[2][0] += a4.z * b4.x; acc[2][1] += a4.z * b4.y; acc[2][2] += a4.z * b4.z; acc[2][3] += a4.z * b4.w;
            acc[3][0] += a4.w * b4.x; acc[3][1] += a4.w * b4.y; acc[3][2] += a4.w * b4.z; acc[3][3] += a4.w * b4.w;
        }
        __syncthreads();
    }
#pragma unroll
    for (int i = 0; i < 4; i++) {
        float4 o = make_float4(acc[i][0] * alpha, acc[i][1] * alpha,
                               acc[i][2] * alpha, acc[i][3] * alpha);
        *(float4*)&C[(size_t)(mt * 64 + ty * 4 + i) * Nn + nt * 64 + tx * 4] = o;
    }
}

// ================= flash W2 on tensor cores =================
__global__ __launch_bounds__(256) void flash_w2_mma() {
    __shared__ __align__(16) __half sql[128][72];
    __shared__ __align__(16) __half sk[64][72];
    __shared__ __align__(16) __half svT[64][72];

    int tid = threadIdx.x, lane = tid & 31, w = tid >> 5;
    int chunk = blockIdx.x, mblk = blockIdx.y, bh = blockIdx.z;
    int lr = lane & 15, lh = lane >> 4;

    const __half* qlh = g_qlh + (size_t)(bh * MLM + mblk * 128) * 64;
#pragma unroll
    for (int i = 0; i < 4; i++) {
        int idx = tid + i * 256;
        int r = idx >> 3, c = (idx & 7) * 8;
        *(uint4*)&sql[r][c] = *(const uint4*)&qlh[(size_t)r * 64 + c];
    }
    __syncthreads();
    unsigned qa[4][4];
#pragma unroll
    for (int ks = 0; ks < 4; ks++)
        ldm4(qa[ks], smem_u32(&sql[w * 16 + lr][ks * 16 + lh * 8]));

    float outacc[8][4];
#pragma unroll
    for (int i = 0; i < 8; i++)
#pragma unroll
        for (int c = 0; c < 4; c++) outacc[i][c] = 0.f;
    float rsA = 0.f, rsB = 0.f;

    const __half* kb = g_kh + (size_t)bh * NSEQ * 64;
    const __half* vb = g_vh + (size_t)bh * NSEQ * 64;

    for (int it = 0; it < 32; it++) {
        int s0 = chunk * 2048 + it * 64;
        __syncthreads();
#pragma unroll
        for (int i = 0; i < 2; i++) {
            int idx = tid + i * 256;
            int r = idx >> 3, c = (idx & 7) * 8;
            *(uint4*)&sk[r][c] = *(const uint4*)&kb[(size_t)(s0 + r) * 64 + c];
            uint4 vv = *(const uint4*)&vb[(size_t)(s0 + r) * 64 + c];
            __half vh[8];
            *(uint4*)vh = vv;
#pragma unroll
            for (int j = 0; j < 8; j++) svT[c + j][r] = vh[j];
        }
        __syncthreads();
        float sf[8][4];
#pragma unroll
        for (int i = 0; i < 8; i++)
#pragma unroll
            for (int c = 0; c < 4; c++) sf[i][c] = 0.f;
#pragma unroll
        for (int ks = 0; ks < 4; ks++) {
#pragma unroll
            for (int nf4 = 0; nf4 < 4; nf4++) {
                unsigned bbf[4];
                ldm4(bbf, smem_u32(&sk[nf4 * 16 + lr][ks * 16 + lh * 8]));
                mmaf16(sf[nf4 * 2], qa[ks], bbf[0], bbf[2]);
                mmaf16(sf[nf4 * 2 + 1], qa[ks], bbf[1], bbf[3]);
            }
        }
#pragma unroll
        for (int nf = 0; nf < 8; nf++) {
            sf[nf][0] = fexp(sf[nf][0]); sf[nf][1] = fexp(sf[nf][1]);
            sf[nf][2] = fexp(sf[nf][2]); sf[nf][3] = fexp(sf[nf][3]);
            rsA += sf[nf][0] + sf[nf][1];
            rsB += sf[nf][2] + sf[nf][3];
        }
#pragma unroll
        for (int kk = 0; kk < 4; kk++) {
            unsigned pa[4];
            pa[0] = packh2(sf[2 * kk][0], sf[2 * kk][1]);
            pa[1] = packh2(sf[2 * kk][2], sf[2 * kk][3]);
            pa[2] = packh2(sf[2 * kk + 1][0], sf[2 * kk + 1][1]);
            pa[3] = packh2(sf[2 * kk + 1][2], sf[2 * kk + 1][3]);
#pragma unroll
            for (int nf4 = 0; nf4 < 4; nf4++) {
                unsigned bbf[4];
                ldm4(bbf, smem_u32(&svT[nf4 * 16 + lr][kk * 16 + lh * 8]));
                mmaf16(outacc[nf4 * 2], pa, bbf[0], bbf[2]);
                mmaf16(outacc[nf4 * 2 + 1], pa, bbf[1], bbf[3]);
            }
        }
    }
    rsA += __shfl_xor_sync(0xffffffffu, rsA, 1);
    rsA += __shfl_xor_sync(0xffffffffu, rsA, 2);
    rsB += __shfl_xor_sync(0xffffffffu, rsB, 1);
    rsB += __shfl_xor_sync(0xffffffffu, rsB, 2);

    int rA = mblk * 128 + w * 16 + (lane >> 2);
    int rB = rA + 8;
    float* wpA = g_Wpart + (size_t)((bh * 4 + chunk) * MLM + rA) * 64;
    float* wpB = g_Wpart + (size_t)((bh * 4 + chunk) * MLM + rB) * 64;
#pragma unroll
    for (int nf = 0; nf < 8; nf++) {
        int d = nf * 8 + (lane & 3) * 2;
        *(float2*)&wpA[d] = make_float2(outacc[nf][0], outacc[nf][1]);
        *(float2*)&wpB[d] = make_float2(outacc[nf][2], outacc[nf][3]);
    }
    if ((lane & 3) == 0) {
        g_Spart[(bh * 4 + chunk) * MLM + rA] = rsA;
        g_Spart[(bh * 4 + chunk) * MLM + rB] = rsB;
    }
}

__global__ void combine_w2_kernel() {
    int idx = blockIdx.x * 256 + threadIdx.x;
    int bh = idx >> 14;
    int m = (idx >> 6) & 255;
    int d = idx & 63;
    float num = 0.f, den = 0.f;
#pragma unroll
    for (int c = 0; c < 4; c++) {
        num += g_Wpart[(size_t)((bh * 4 + c) * MLM + m) * 64 + d];
        den += g_Spart[(bh * 4 + c) * MLM + m];
    }
    g_W2[(bh * MLM + m) * 64 + d] = num / den;
}

// ================= attn1 + conv on tensor cores =================
__global__ __launch_bounds__(256) void attn1_mma(const float* __restrict__ convw) {
    extern __shared__ char smx[];
    __half (*sq)[72]  = (__half(*)[72])(smx);
    __half (*skl)[72] = (__half(*)[72])(smx + 18432);
    __half (*swT)[72] = (__half(*)[72])(smx + 27648);
    __half (*sv)[72]  = (__half(*)[72])(smx + 36864);
    float* cw = (float*)(smx + 59904);

    int tid = threadIdx.x, lane = tid & 31, w = tid >> 5;
    int ntile = blockIdx.x, bh = blockIdx.y;
    int h = bh & 7, bb2 = bh >> 3;
    int n0 = ntile * 128;
    int lr = lane & 15, lh = lane >> 4;

    if (tid < KSZ) cw[tid] = convw[h * KSZ + tid];

    const __half* qb = g_qh + ((size_t)bh * NSEQ + n0) * 64;
#pragma unroll
    for (int i = 0; i < 4; i++) {
        int idx = tid + i * 256;
        int r = idx >> 3, c = (idx & 7) * 8;
        *(uint4*)&sq[r][c] = *(const uint4*)&qb[(size_t)r * 64 + c];
    }
    const __half* vb2 = g_vh + (size_t)bh * NSEQ * 64;
#pragma unroll
    for (int i = 0; i < 5; i++) {
        int idx = tid + i * 256;
        int r = idx >> 3, c = (idx & 7) * 8;
        int gr = n0 - 16 + r;
        uint4 z = make_uint4(0u, 0u, 0u, 0u);
        if (gr >= 0 && gr < NSEQ) z = *(const uint4*)&vb2[(size_t)gr * 64 + c];
        *(uint4*)&sv[r][c] = z;
    }
    __syncthreads();

    unsigned qa[4][4];
#pragma unroll
    for (int ks = 0; ks < 4; ks++)
        ldm4(qa[ks], smem_u32(&sq[w * 16 + lr][ks * 16 + lh * 8]));

    float outacc[8][4];
#pragma unroll
    for (int i = 0; i < 8; i++)
#pragma unroll
        for (int c = 0; c < 4; c++) outacc[i][c] = 0.f;
    float rsA = 0.f, rsB = 0.f;

    const __half* klb = g_klh + (size_t)bh * MLM * 64;
    const __half* w3tb = g_W3T + (size_t)bh * 64 * 256;

    for (int lc = 0; lc < 4; lc++) {
        __syncthreads();
#pragma unroll
        for (int i = 0; i < 2; i++) {
            int idx = tid + i * 256;
            int r = idx >> 3, c = (idx & 7) * 8;
            *(uint4*)&skl[r][c] = *(const uint4*)&klb[(size_t)(lc * 64 + r) * 64 + c];
            *(uint4*)&swT[r][c] = *(const uint4*)&w3tb[(size_t)r * 256 + lc * 64 + c];
        }
        __syncthreads();
        float sf[8][4];
#pragma unroll
        for (int i = 0; i < 8; i++)
#pragma unroll
            for (int c = 0; c < 4; c++) sf[i][c] = 0.f;
#pragma unroll
        for (int ks = 0; ks < 4; ks++) {
#pragma unroll
            for (int nf4 = 0; nf4 < 4; nf4++) {
                unsigned bbf[4];
                ldm4(bbf, smem_u32(&skl[nf4 * 16 + lr][ks * 16 + lh * 8]));
                mmaf16(sf[nf4 * 2], qa[ks], bbf[0], bbf[2]);
                mmaf16(sf[nf4 * 2 + 1], qa[ks], bbf[1], bbf[3]);
            }
        }
#pragma unroll
        for (int nf = 0; nf < 8; nf++) {
            sf[nf][0] = fexp(sf[nf][0]); sf[nf][1] = fexp(sf[nf][1]);
            sf[nf][2] = fexp(sf[nf][2]); sf[nf][3] = fexp(sf[nf][3]);
            rsA += sf[nf][0] + sf[nf][1];
            rsB += sf[nf][2] + sf[nf][3];
        }
#pragma unroll
        for (int kk = 0; kk < 4; kk++) {
            unsigned pa[4];
            pa[0] = packh2(sf[2 * kk][0], sf[2 * kk][1]);
            pa[1] = packh2(sf[2 * kk][2], sf[2 * kk][3]);
            pa[2] = packh2(sf[2 * kk + 1][0], sf[2 * kk + 1][1]);
            pa[3] = packh2(sf[2 * kk + 1][2], sf[2 * kk + 1][3]);
#pragma unroll
            for (int nf4 = 0; nf4 < 4; nf4++) {
                unsigned bbf[4];
                ldm4(bbf, smem_u32(&swT[nf4 * 16 + lr][kk * 16 + lh * 8]));
                mmaf16(outacc[nf4 * 2], pa, bbf[0], bbf[2]);
                mmaf16(outacc[nf4 * 2 + 1], pa, bbf[1], bbf[3]);
            }
        }
    }
    rsA += __shfl_xor_sync(0xffffffffu, rsA, 1);
    rsA += __shfl_xor_sync(0xffffffffu, rsA, 2);
    rsB += __shfl_xor_sync(0xffffffffu, rsB, 1);
    rsB += __shfl_xor_sync(0xffffffffu, rsB, 2);
    float invA = 1.f / rsA, invB = 1.f / rsB;

    int lrA = w * 16 + (lane >> 2);
#pragma unroll
    for (int nf = 0; nf < 8; nf++) {
        int d = nf * 8 + (lane & 3) * 2;
        float a0 = 0.f, a1 = 0.f, b0 = 0.f, b1 = 0.f;
#pragma unroll
        for (int t = 0; t < KSZ; t++) {
            float wv = cw[t];
            float2 fA = __half22float2(*(__half2*)&sv[lrA + t][d]);
            float2 fB = __half22float2(*(__half2*)&sv[lrA + 8 + t][d]);
            a0 = fmaf(wv, fA.x, a0); a1 = fmaf(wv, fA.y, a1);
            b0 = fmaf(wv, fB.x, b0); b1 = fmaf(wv, fB.y, b1);
        }
        outacc[nf][0] = outacc[nf][0] * invA + a0;
        outacc[nf][1] = outacc[nf][1] * invA + a1;
        outacc[nf][2] = outacc[nf][2] * invB + b0;
        outacc[nf][3] = outacc[nf][3] * invB + b1;
    }

    int nA = n0 + lrA, nB = nA + 8;
    float* oA = g_outpre + (size_t)(bb2 * NSEQ + nA) * 512 + h * 64;
    float* oB = g_outpre + (size_t)(bb2 * NSEQ + nB) * 512 + h * 64;
#pragma unroll
    for (int nf = 0; nf < 8; nf++) {
        int d = nf * 8 + (lane & 3) * 2;
        *(float2*)&oA[d] = make_float2(outacc[nf][0], outacc[nf][1]);
        *(float2*)&oB[d] = make_float2(outacc[nf][2], outacc[nf][3]);
    }
}

// ================= host launcher =================
extern "C" void kernel_launch(void* const* d_in, const int* in_sizes, int n_in,
                              void* d_out, int out_size) {
    const float* x     = (const float*)d_in[0];
    const float* ln_g  = (const float*)d_in[1];
    const float* ln_b  = (const float*)d_in[2];
    const float* W_qkv = (const float*)d_in[3];
    const float* W_out = (const float*)d_in[4];
    const float* b_out = (const float*)d_in[5];
    const float* convw = (const float*)d_in[6];
    float* out = (float*)d_out;

    cudaFuncSetAttribute(attn1_mma, cudaFuncAttributeMaxDynamicSharedMemorySize, 60416);
    cudaFuncSetAttribute(gemm_lm_kernel, cudaFuncAttributeMaxDynamicSharedMemorySize, 81920);
    cudaFuncSetAttribute(gemm16_kernel, cudaFuncAttributeMaxDynamicSharedMemorySize, 73728);

    __nv_bfloat16 *bqh, *bql;
    cudaGetSymbolAddress((void**)&bqh, g_Bqh);
    cudaGetSymbolAddress((void**)&bql, g_Bql);
    __half *b16q, *b16o;
    cudaGetSymbolAddress((void**)&b16q, g_B16q);
    cudaGetSymbolAddress((void**)&b16o, g_B16o);
    float *xnp, *xnlmp, *opp;
    cudaGetSymbolAddress((void**)&xnp, g_xn);
    cudaGetSymbolAddress((void**)&xnlmp, g_xnlm);
    cudaGetSymbolAddress((void**)&opp, g_outpre);

    reset_kernel<<<1, 1>>>();
    ln_kernel<<<Bb * NSEQ, 128>>>(x, ln_g, ln_b);

    // fp16 conversions
    convA16_kernel<<<8192, 256>>>(xnp);
    convW16_kernel<<<dim3(48, 16), 1024>>>(W_qkv, 1536, b16q);
    convW16_kernel<<<dim3(16, 16), 1024>>>(W_out, 512, b16o);

    // qkv GEMM: single-pass fp16
    gemm16_kernel<<<dim3(12, 128), 256, 73728>>>(b16q, 0, nullptr, nullptr);

    // landmark path: xn group means -> bf16 hi/lo -> accurate small GEMM
    xnlm_kernel<<<1024, 256>>>();
    convA_kernel<<<256, 256>>>(xnlmp);
    convW_kernel<<<dim3(48, 16), 1024>>>(W_qkv, 1536, bqh, bql);
    gemm_lm_kernel<<<dim3(8, 4), 256, 81920>>>(bqh, bql);

    attn2_kernel<<<16, 256>>>();
    colmax_kernel<<<16, 256>>>();
    z0_kernel<<<4096, 256>>>();

    int zc = 4, zn = 5;  // Za, Zb
    for (int it = 0; it < 6; it++) {
        int np = (it == 5) ? 3 : 1;  // NS self-corrects: only final iteration needs full split
        gemm_pinv_mma<<<dim3(4, 2, 16), 256>>>(1, 0, zc, 0.f, 1.f, 1.f, np);
        gemm_pinv_mma<<<dim3(4, 2, 16), 256>>>(2, 1, 1, 7.f, -1.f, 1.f, np);
        gemm_pinv_mma<<<dim3(4, 2, 16), 256>>>(3, 1, 2, 15.f, -1.f, 1.f, np);
        gemm_pinv_mma<<<dim3(4, 2, 16), 256>>>(zn, zc, 3, 13.f, -1.f, 0.25f, np);
        int t = zc; zc = zn; zn = t;
    }

    flash_w2_mma<<<dim3(4, 2, 16), 256>>>();
    combine_w2_kernel<<<1024, 256>>>();
    gemm_bh_kernel<<<dim3(1, 4, 16), 256>>>(7, zc, 6, 64, 0.f, 1.f, 1.f);  // W3 = Z @ W2
    w3t_kernel<<<1024, 256>>>();
    attn1_mma<<<dim3(64, 16), 256, 60416>>>(convw);

    // out GEMM: single-pass fp16
    convA16_kernel<<<8192, 256>>>(opp);
    gemm16_kernel<<<dim3(4, 128), 256, 73728>>>(b16o, 1, b_out, out);
}